// round 6
// baseline (speedup 1.0000x reference)
#include <cuda_runtime.h>
#include <cuda_bf16.h>
#include <math.h>
#include <stdint.h>

// Shapes (fixed)
#define Bc   2
#define Lc   4096
#define Dc   1024
#define Hc   16
#define DHc  64
#define Mc   256
#define BHc  32
#define ROWS 8192   // B*L

typedef __nv_bfloat16 bf16;

// -------- scratch (device globals; no allocations allowed) --------
__device__ float g_v    [(size_t)ROWS * Dc];
__device__ float g_kf   [(size_t)BHc * Lc * Mc];
__device__ bf16  g_qfhi [(size_t)BHc * Lc * Mc];
__device__ bf16  g_qflo [(size_t)BHc * Lc * Mc];
__device__ float g_kv   [(size_t)BHc * Mc * DHc];
__device__ bf16  g_kvthi[(size_t)BHc * DHc * Mc];
__device__ bf16  g_kvtlo[(size_t)BHc * DHc * Mc];
__device__ float g_ksum [(size_t)BHc * Mc];
__device__ float g_z    [(size_t)BHc * Lc];
__device__ float g_attn [(size_t)ROWS * Dc];
__device__ float g_y    [(size_t)ROWS * Dc];
__device__ bf16  g_ahi  [(size_t)ROWS * Dc];
__device__ bf16  g_alo  [(size_t)ROWS * Dc];
__device__ bf16  g_bthi [(size_t)3 * Dc * Dc];
__device__ bf16  g_btlo [(size_t)3 * Dc * Dc];
__device__ bf16  g_qhi  [(size_t)ROWS * Dc];
__device__ bf16  g_qlo  [(size_t)ROWS * Dc];
__device__ bf16  g_khi  [(size_t)ROWS * Dc];
__device__ bf16  g_klo  [(size_t)ROWS * Dc];
__device__ bf16  g_phi  [(size_t)Hc * Mc * DHc];
__device__ bf16  g_plo  [(size_t)Hc * Mc * DHc];

// ================= baseline-PTX tensor-core helpers (sm_80+) ==========
__device__ __forceinline__ uint32_t smem_u32(const void* p) {
    uint32_t a;
    asm("{ .reg .u64 t; cvta.to.shared.u64 t, %1; cvt.u32.u64 %0, t; }"
        : "=r"(a) : "l"(p));
    return a;
}
__device__ __forceinline__ void cp_async16(uint32_t saddr, const void* g) {
    asm volatile("cp.async.cg.shared.global [%0], [%1], 16;"
                 :: "r"(saddr), "l"(g) : "memory");
}
#define CP_COMMIT() asm volatile("cp.async.commit_group;" ::: "memory")
#define CP_WAIT(n)  asm volatile("cp.async.wait_group %0;" :: "n"(n) : "memory")

__device__ __forceinline__ void ldsm_x4(uint32_t r[4], uint32_t addr) {
    asm volatile("ldmatrix.sync.aligned.m8n8.x4.shared.b16 {%0,%1,%2,%3}, [%4];"
                 : "=r"(r[0]), "=r"(r[1]), "=r"(r[2]), "=r"(r[3]) : "r"(addr));
}
__device__ __forceinline__ void mma16816(float c[4], const uint32_t a[4],
                                         uint32_t b0, uint32_t b1) {
    asm volatile(
        "mma.sync.aligned.m16n8k16.row.col.f32.bf16.bf16.f32 "
        "{%0,%1,%2,%3}, {%4,%5,%6,%7}, {%8,%9}, {%0,%1,%2,%3};"
        : "+f"(c[0]), "+f"(c[1]), "+f"(c[2]), "+f"(c[3])
        : "r"(a[0]), "r"(a[1]), "r"(a[2]), "r"(a[3]), "r"(b0), "r"(b1));
}
__device__ __forceinline__ void split2(float v, bf16& h, bf16& l) {
    h = __float2bfloat16_rn(v);
    l = __float2bfloat16_rn(v - __bfloat162float(h));
}

// ============================================================
// fp32 -> (hi, lo) bf16 split
// ============================================================
__global__ __launch_bounds__(256) void split_kernel(
    const float* __restrict__ in, bf16* __restrict__ hi,
    bf16* __restrict__ lo, int n4)
{
    int i = blockIdx.x * 256 + threadIdx.x;
    if (i >= n4) return;
    float4 v = ((const float4*)in)[i];
    bf16 h0, h1, h2, h3, l0, l1, l2, l3;
    split2(v.x, h0, l0); split2(v.y, h1, l1);
    split2(v.z, h2, l2); split2(v.w, h3, l3);
    ((__nv_bfloat162*)hi)[2*i]   = __halves2bfloat162(h0, h1);
    ((__nv_bfloat162*)hi)[2*i+1] = __halves2bfloat162(h2, h3);
    ((__nv_bfloat162*)lo)[2*i]   = __halves2bfloat162(l0, l1);
    ((__nv_bfloat162*)lo)[2*i+1] = __halves2bfloat162(l2, l3);
}

// ============================================================
// W [K=1024, N=1024] -> W^T [N,K] with bf16 hi/lo split
// ============================================================
__global__ void tsplit_kernel(const float* __restrict__ W,
    bf16* __restrict__ Thi, bf16* __restrict__ Tlo)
{
    __shared__ float t[32][33];
    int bx = blockIdx.x * 32, by = blockIdx.y * 32;
    int tx = threadIdx.x, ty = threadIdx.y;   // 32 x 8
#pragma unroll
    for (int i = 0; i < 32; i += 8)
        t[ty + i][tx] = W[(size_t)(by + ty + i) * Dc + bx + tx];
    __syncthreads();
#pragma unroll
    for (int i = 0; i < 32; i += 8) {
        float v = t[tx][ty + i];
        int orow = bx + ty + i, ocol = by + tx;
        bf16 h, l; split2(v, h, l);
        Thi[(size_t)orow * Dc + ocol] = h;
        Tlo[(size_t)orow * Dc + ocol] = l;
    }
}

// ============================================================
// bf16x3 tensor-core GEMM, 3-stage cp.async pipeline, 1 sync/iter.
// mode 0 (fused QKV): B rows 0..3071; which = bn>>10 selects output:
//   0 -> Qhi/Qlo (alpha=qscale), 1 -> Khi/Klo (alpha=qscale), 2 -> V fp32
// mode 1 (single):   C fp32 with exact GELU, alpha=1
// CTA tile 128x128, BK=32, 8 warps x (64x32 warp tile)
// ============================================================
#define LDT 40
#define GNIT 96
#define GEMM_STG (128 * LDT * 2)          // bytes per matrix stage
#define GEMM_SMEM3 (3 * 2 * GEMM_STG)     // 61440 B

__global__ __launch_bounds__(256) void mma_gemm_kernel(
    const bf16* __restrict__ Ahi, const bf16* __restrict__ Alo,
    const bf16* __restrict__ Bhi, const bf16* __restrict__ Blo,
    float* __restrict__ Cv,
    bf16* __restrict__ Qhi, bf16* __restrict__ Qlo,
    bf16* __restrict__ Khi, bf16* __restrict__ Klo,
    float qalpha, int mode)
{
    extern __shared__ char gsm[];
    const int tid  = threadIdx.x;
    const int lane = tid & 31, wid = tid >> 5;
    const int bm = blockIdx.y * 128;
    const int bn = blockIdx.x * 128;
    const int wm = (wid >> 2) * 64;
    const int wn = (wid & 3) * 32;

    uint32_t as_b[3], bs_b[3];
#pragma unroll
    for (int s = 0; s < 3; s++) {
        as_b[s] = smem_u32(gsm + s * 2 * GEMM_STG);
        bs_b[s] = as_b[s] + GEMM_STG;
    }

    const int a_row = wm + (lane & 15);
    const int a_col = (lane >> 4) << 3;
    const int b_row = wn + (lane & 7) + ((lane >> 4) << 3);
    const int b_col = ((lane >> 3) & 1) << 3;

    const int g_row0 = tid >> 2;
    const int g_c8   = (tid & 3) << 3;

    auto stage = [&](int kt) {
        const int s  = kt % 3;
        const int p  = kt >> 5;
        const int kk = (kt & 31) << 5;
        const bf16* Ag = (p < 2) ? Ahi : Alo;
        const bf16* Bg = (p == 1) ? Blo : Bhi;
#pragma unroll
        for (int i = 0; i < 2; i++) {
            int row = g_row0 + i * 64;
            uint32_t soff = (uint32_t)(row * LDT + g_c8) * 2;
            cp_async16(as_b[s] + soff, Ag + (size_t)(bm + row) * Dc + kk + g_c8);
            cp_async16(bs_b[s] + soff, Bg + (size_t)(bn + row) * Dc + kk + g_c8);
        }
        CP_COMMIT();
    };

    float acc[4][4][4];
#pragma unroll
    for (int mi = 0; mi < 4; mi++)
#pragma unroll
        for (int ni = 0; ni < 4; ni++)
#pragma unroll
            for (int e = 0; e < 4; e++) acc[mi][ni][e] = 0.f;

    stage(0); stage(1);

    for (int kt = 0; kt < GNIT; kt++) {
        const int s = kt % 3;
        if (kt + 1 < GNIT) CP_WAIT(1); else CP_WAIT(0);
        __syncthreads();
        if (kt + 2 < GNIT) stage(kt + 2);

#pragma unroll
        for (int k0 = 0; k0 < 32; k0 += 16) {
            uint32_t a[4][4];
#pragma unroll
            for (int mi = 0; mi < 4; mi++)
                ldsm_x4(a[mi], as_b[s] +
                        (uint32_t)((a_row + mi * 16) * LDT + k0 + a_col) * 2);
            uint32_t b[2][4];
#pragma unroll
            for (int pr = 0; pr < 2; pr++)
                ldsm_x4(b[pr], bs_b[s] +
                        (uint32_t)((b_row + pr * 16) * LDT + k0 + b_col) * 2);
#pragma unroll
            for (int mi = 0; mi < 4; mi++) {
                mma16816(acc[mi][0], a[mi], b[0][0], b[0][1]);
                mma16816(acc[mi][1], a[mi], b[0][2], b[0][3]);
                mma16816(acc[mi][2], a[mi], b[1][0], b[1][1]);
                mma16816(acc[mi][3], a[mi], b[1][2], b[1][3]);
            }
        }
    }

    // epilogue: 64x32 warp tile
    const int orow = bm + wm + (lane >> 2);
    const int occ0 = wn + ((lane & 3) << 1);

    if (mode == 0) {
        const int which = bn >> 10;        // 0 q, 1 k, 2 v
        const int bnl = bn & 1023;
        if (which < 2) {
            bf16* Oh = which ? Khi : Qhi;
            bf16* Ol = which ? Klo : Qlo;
#pragma unroll
            for (int mi = 0; mi < 4; mi++)
#pragma unroll
                for (int ni = 0; ni < 4; ni++) {
                    const size_t i0 = (size_t)(orow + mi * 16) * Dc + bnl + occ0 + ni * 8;
                    const size_t i1 = (size_t)(orow + mi * 16 + 8) * Dc + bnl + occ0 + ni * 8;
                    bf16 h0,l0,h1,l1,h2,l2,h3,l3;
                    split2(acc[mi][ni][0] * qalpha, h0, l0);
                    split2(acc[mi][ni][1] * qalpha, h1, l1);
                    split2(acc[mi][ni][2] * qalpha, h2, l2);
                    split2(acc[mi][ni][3] * qalpha, h3, l3);
                    *(__nv_bfloat162*)&Oh[i0] = __halves2bfloat162(h0, h1);
                    *(__nv_bfloat162*)&Oh[i1] = __halves2bfloat162(h2, h3);
                    *(__nv_bfloat162*)&Ol[i0] = __halves2bfloat162(l0, l1);
                    *(__nv_bfloat162*)&Ol[i1] = __halves2bfloat162(l2, l3);
                }
        } else {
#pragma unroll
            for (int mi = 0; mi < 4; mi++)
#pragma unroll
                for (int ni = 0; ni < 4; ni++) {
                    const size_t i0 = (size_t)(orow + mi * 16) * Dc + bnl + occ0 + ni * 8;
                    const size_t i1 = (size_t)(orow + mi * 16 + 8) * Dc + bnl + occ0 + ni * 8;
                    *(float2*)&Cv[i0] = make_float2(acc[mi][ni][0], acc[mi][ni][1]);
                    *(float2*)&Cv[i1] = make_float2(acc[mi][ni][2], acc[mi][ni][3]);
                }
        }
    } else {
#pragma unroll
        for (int mi = 0; mi < 4; mi++)
#pragma unroll
            for (int ni = 0; ni < 4; ni++) {
                float v0 = acc[mi][ni][0], v1 = acc[mi][ni][1];
                float v2 = acc[mi][ni][2], v3 = acc[mi][ni][3];
                v0 = 0.5f * v0 * (1.f + erff(v0 * 0.70710678118654752f));
                v1 = 0.5f * v1 * (1.f + erff(v1 * 0.70710678118654752f));
                v2 = 0.5f * v2 * (1.f + erff(v2 * 0.70710678118654752f));
                v3 = 0.5f * v3 * (1.f + erff(v3 * 0.70710678118654752f));
                const size_t i0 = (size_t)(orow + mi * 16) * Dc + bn + occ0 + ni * 8;
                const size_t i1 = (size_t)(orow + mi * 16 + 8) * Dc + bn + occ0 + ni * 8;
                *(float2*)&Cv[i0] = make_float2(v0, v1);
                *(float2*)&Cv[i1] = make_float2(v2, v3);
            }
    }
}

// ============================================================
// FAVOR+ feature via mma.sync bf16x3 (as R5), output mode:
//   omode 0: fp32 F    omode 1: bf16 hi/lo (Fhi, Flo)
// ============================================================
#define FLDK 72
#define FEAT2_SMEM ((128 + 128 + 256 + 256) * FLDK * 2 + 128 * 4 + 4 * 128 * 4)

__global__ __launch_bounds__(256) void feature_mma_kernel(
    const bf16* __restrict__ Uhi, const bf16* __restrict__ Ulo,
    const bf16* __restrict__ Phi, const bf16* __restrict__ Plo,
    float* __restrict__ F, bf16* __restrict__ Fhi, bf16* __restrict__ Flo,
    int omode)
{
    extern __shared__ char fsm[];
    bf16* us_h = (bf16*)fsm;                    // [128][FLDK]
    bf16* us_l = us_h + 128 * FLDK;
    bf16* ps_h = us_l + 128 * FLDK;             // [256][FLDK]
    bf16* ps_l = ps_h + 256 * FLDK;
    float* diag  = (float*)(ps_l + 256 * FLDK); // [128]
    float* rmaxp = diag + 128;                  // [4][128]

    const int bh = blockIdx.y;
    const int b = bh >> 4, h = bh & 15;
    const int l0 = blockIdx.x * 128;
    const int tid = threadIdx.x;
    const int lane = tid & 31, wid = tid >> 5;

#pragma unroll
    for (int i = 0; i < 4; i++) {
        int s = tid + i * 256;
        int r = s >> 3, c8 = (s & 7) << 3;
        size_t gi = (size_t)(b * Lc + l0 + r) * Dc + h * DHc + c8;
        *(uint4*)&us_h[r * FLDK + c8] = *(const uint4*)&Uhi[gi];
        *(uint4*)&us_l[r * FLDK + c8] = *(const uint4*)&Ulo[gi];
    }
#pragma unroll
    for (int i = 0; i < 8; i++) {
        int s = tid + i * 256;
        int r = s >> 3, c8 = (s & 7) << 3;
        size_t gi = (size_t)(h * Mc + r) * DHc + c8;
        *(uint4*)&ps_h[r * FLDK + c8] = *(const uint4*)&Phi[gi];
        *(uint4*)&ps_l[r * FLDK + c8] = *(const uint4*)&Plo[gi];
    }
    __syncthreads();

    if (tid < 128) {
        float s = 0.f;
#pragma unroll
        for (int d2 = 0; d2 < 32; d2++) {
            __nv_bfloat162 hh = *(__nv_bfloat162*)&us_h[tid * FLDK + d2 * 2];
            __nv_bfloat162 ll = *(__nv_bfloat162*)&us_l[tid * FLDK + d2 * 2];
            float u0 = __bfloat162float(hh.x) + __bfloat162float(ll.x);
            float u1 = __bfloat162float(hh.y) + __bfloat162float(ll.y);
            s += u0 * u0 + u1 * u1;
        }
        diag[tid] = 0.5f * s;
    }

    const int wm = (wid >> 2) * 64;
    const int wn = (wid & 3) * 64;
    const int a_row = wm + (lane & 15);
    const int a_col = (lane >> 4) << 3;
    const int b_row = wn + (lane & 7) + ((lane >> 4) << 3);
    const int b_col = ((lane >> 3) & 1) << 3;

    float acc[4][8][4];
#pragma unroll
    for (int mi = 0; mi < 4; mi++)
#pragma unroll
        for (int ni = 0; ni < 8; ni++)
#pragma unroll
            for (int e = 0; e < 4; e++) acc[mi][ni][e] = 0.f;

    const uint32_t ush = smem_u32(us_h), usl = smem_u32(us_l);
    const uint32_t psh = smem_u32(ps_h), psl = smem_u32(ps_l);
    __syncthreads();

#pragma unroll
    for (int p = 0; p < 3; p++) {
        const uint32_t ab = (p < 2) ? ush : usl;
        const uint32_t bb = (p == 1) ? psl : psh;
#pragma unroll
        for (int k0 = 0; k0 < 64; k0 += 16) {
            uint32_t a[4][4], bfr[4][4];
#pragma unroll
            for (int mi = 0; mi < 4; mi++)
                ldsm_x4(a[mi], ab + (uint32_t)((a_row + mi * 16) * FLDK + k0 + a_col) * 2);
#pragma unroll
            for (int pr = 0; pr < 4; pr++)
                ldsm_x4(bfr[pr], bb + (uint32_t)((b_row + pr * 16) * FLDK + k0 + b_col) * 2);
#pragma unroll
            for (int mi = 0; mi < 4; mi++)
#pragma unroll
                for (int pr = 0; pr < 4; pr++) {
                    mma16816(acc[mi][2 * pr],     a[mi], bfr[pr][0], bfr[pr][1]);
                    mma16816(acc[mi][2 * pr + 1], a[mi], bfr[pr][2], bfr[pr][3]);
                }
        }
    }

    float tmax[4][2];
#pragma unroll
    for (int mi = 0; mi < 4; mi++) {
        float m0 = -1e30f, m1 = -1e30f;
#pragma unroll
        for (int ni = 0; ni < 8; ni++) {
            m0 = fmaxf(m0, fmaxf(acc[mi][ni][0], acc[mi][ni][1]));
            m1 = fmaxf(m1, fmaxf(acc[mi][ni][2], acc[mi][ni][3]));
        }
#pragma unroll
        for (int off = 1; off <= 2; off <<= 1) {
            m0 = fmaxf(m0, __shfl_xor_sync(0xffffffffu, m0, off));
            m1 = fmaxf(m1, __shfl_xor_sync(0xffffffffu, m1, off));
        }
        tmax[mi][0] = m0; tmax[mi][1] = m1;
    }
    if ((lane & 3) == 0) {
        const int slab = wid & 3;
#pragma unroll
        for (int mi = 0; mi < 4; mi++) {
            int r = wm + mi * 16 + (lane >> 2);
            rmaxp[slab * 128 + r]     = tmax[mi][0];
            rmaxp[slab * 128 + r + 8] = tmax[mi][1];
        }
    }
    __syncthreads();

#pragma unroll
    for (int mi = 0; mi < 4; mi++) {
        const int r0 = wm + mi * 16 + (lane >> 2);
        const int r1 = r0 + 8;
        float rm0 = fmaxf(fmaxf(rmaxp[r0], rmaxp[128 + r0]),
                          fmaxf(rmaxp[256 + r0], rmaxp[384 + r0]));
        float rm1 = fmaxf(fmaxf(rmaxp[r1], rmaxp[128 + r1]),
                          fmaxf(rmaxp[256 + r1], rmaxp[384 + r1]));
        const float base0 = -diag[r0] - rm0;
        const float base1 = -diag[r1] - rm1;
        const size_t o0 = ((size_t)bh * Lc + l0 + r0) * Mc;
        const size_t o1 = ((size_t)bh * Lc + l0 + r1) * Mc;
        const int c0 = wn + ((lane & 3) << 1);
#pragma unroll
        for (int ni = 0; ni < 8; ni++) {
            int c = c0 + ni * 8;
            float f0 = __expf(acc[mi][ni][0] + base0) * 0.0625f;
            float f1 = __expf(acc[mi][ni][1] + base0) * 0.0625f;
            float f2 = __expf(acc[mi][ni][2] + base1) * 0.0625f;
            float f3 = __expf(acc[mi][ni][3] + base1) * 0.0625f;
            if (omode == 0) {
                *(float2*)&F[o0 + c] = make_float2(f0, f1);
                *(float2*)&F[o1 + c] = make_float2(f2, f3);
            } else {
                bf16 h0,l0b,h1,l1b,h2,l2b,h3,l3b;
                split2(f0, h0, l0b); split2(f1, h1, l1b);
                split2(f2, h2, l2b); split2(f3, h3, l3b);
                *(__nv_bfloat162*)&Fhi[o0 + c] = __halves2bfloat162(h0, h1);
                *(__nv_bfloat162*)&Fhi[o1 + c] = __halves2bfloat162(h2, h3);
                *(__nv_bfloat162*)&Flo[o0 + c] = __halves2bfloat162(l0b, l1b);
                *(__nv_bfloat162*)&Flo[o1 + c] = __halves2bfloat162(l2b, l3b);
            }
        }
    }
}

// ============================================================
// kv[m,d] = sum_l kf[l,m]*v[l,d];  ksum[m] = sum_l kf[l,m]  (unchanged)
// ============================================================
__global__ __launch_bounds__(256) void kv_kernel(
    const float* __restrict__ kf, const float* __restrict__ v,
    float* __restrict__ kv, float* __restrict__ ksum)
{
    __shared__ float vs[16][64];
    const int bh = blockIdx.x;
    const int b = bh >> 4, h = bh & 15;
    const int l0 = blockIdx.y * 256;
    const int t = threadIdx.x;

    float acc[64];
#pragma unroll
    for (int d = 0; d < 64; d++) acc[d] = 0.f;
    float s = 0.f;

    for (int l = l0; l < l0 + 256; l += 16) {
        {
            int r = t >> 4, c4 = (t & 15) << 2;
            *(float4*)&vs[r][c4] =
                *(const float4*)&v[(size_t)(b * Lc + l + r) * Dc + h * DHc + c4];
        }
        __syncthreads();
#pragma unroll
        for (int r = 0; r < 16; r++) {
            float a = kf[((size_t)bh * Lc + l + r) * Mc + t];
            s += a;
#pragma unroll
            for (int d4 = 0; d4 < 16; d4++) {
                float4 vv = *(const float4*)&vs[r][d4 * 4];
                acc[d4 * 4 + 0] += a * vv.x;
                acc[d4 * 4 + 1] += a * vv.y;
                acc[d4 * 4 + 2] += a * vv.z;
                acc[d4 * 4 + 3] += a * vv.w;
            }
        }
        __syncthreads();
    }
    float* kvp = kv + ((size_t)bh * Mc + t) * DHc;
#pragma unroll
    for (int d = 0; d < 64; d++) atomicAdd(&kvp[d], acc[d]);
    atomicAdd(&ksum[bh * Mc + t], s);
}

// ============================================================
// kv [bh][256][64] fp32 -> kvt [bh][64][256] bf16 hi/lo (transpose + split)
// ============================================================
__global__ __launch_bounds__(256) void kvt_kernel(
    const float* __restrict__ kv, bf16* __restrict__ Thi, bf16* __restrict__ Tlo)
{
    const int bh = blockIdx.x;
    const float* src = kv + (size_t)bh * Mc * DHc;
    bf16* dh = Thi + (size_t)bh * DHc * Mc;
    bf16* dl = Tlo + (size_t)bh * DHc * Mc;
    for (int o = threadIdx.x; o < DHc * Mc; o += 256) {
        int n = o >> 8, m = o & 255;
        float v = src[m * DHc + n];
        bf16 h, l; split2(v, h, l);
        dh[o] = h; dl[o] = l;
    }
}

// ============================================================
// z[bh,l] = 1 / (dot(qf_hi+qf_lo, ksum) + 1e-6)
// ============================================================
__global__ __launch_bounds__(256) void z_kernel(
    const bf16* __restrict__ qfhi, const bf16* __restrict__ qflo,
    const float* __restrict__ ksum, float* __restrict__ z)
{
    __shared__ float ks[256];
    const int bh = blockIdx.y;
    ks[threadIdx.x] = ksum[bh * Mc + threadIdx.x];
    __syncthreads();
    const int w = threadIdx.x >> 5, lane = threadIdx.x & 31;
    const int l = blockIdx.x * 8 + w;
    const size_t base = ((size_t)bh * Lc + l) * Mc;
    float s = 0.f;
#pragma unroll
    for (int q8 = 0; q8 < 8; q8++) {
        int c = lane + q8 * 32;
        s += (__bfloat162float(qfhi[base + c]) + __bfloat162float(qflo[base + c])) * ks[c];
    }
#pragma unroll
    for (int off = 16; off; off >>= 1) s += __shfl_xor_sync(0xffffffffu, s, off);
    if (lane == 0) z[bh * Lc + l] = 1.0f / (s + 1e-6f);
}

// ============================================================
// attn via mma bf16x3: per bh, attn[l,d] = z[l] * sum_m qf[l,m]*kvt[d,m]
// CTA 256 rows x 64 cols, BK=32, 3-stage pipeline, 8 warps x (64x32)
// ============================================================
#define ANIT 24                           // 3 passes * (256/32)
#define ATT_ASTG (256 * LDT * 2)          // 20480 B
#define ATT_BSTG (64 * LDT * 2)           // 5120 B
#define ATT_SMEM (3 * (ATT_ASTG + ATT_BSTG))   // 76800 B

__global__ __launch_bounds__(256) void attn_mma_kernel(
    const bf16* __restrict__ qfhi, const bf16* __restrict__ qflo,
    const bf16* __restrict__ kvthi, const bf16* __restrict__ kvtlo,
    const float* __restrict__ z, float* __restrict__ attn)
{
    extern __shared__ char asm_[];
    const int bh = blockIdx.y;
    const int b = bh >> 4, h = bh & 15;
    const int l0 = blockIdx.x * 256;
    const int tid = threadIdx.x;
    const int lane = tid & 31, wid = tid >> 5;
    const int wm = (wid >> 1) * 64;     // 4 m-warps
    const int wn = (wid & 1) * 32;      // 2 n-warps

    uint32_t as_b[3], bs_b[3];
#pragma unroll
    for (int s = 0; s < 3; s++) {
        as_b[s] = smem_u32(asm_ + s * (ATT_ASTG + ATT_BSTG));
        bs_b[s] = as_b[s] + ATT_ASTG;
    }

    const int a_row = wm + (lane & 15);
    const int a_col = (lane >> 4) << 3;
    const int b_row = wn + (lane & 7) + ((lane >> 4) << 3);
    const int b_col = ((lane >> 3) & 1) << 3;

    const size_t qbase = ((size_t)bh * Lc + l0) * Mc;
    const size_t kbase = (size_t)bh * DHc * Mc;

    // A: 256x32 = 1024 x 16B (4/thread); B: 64x32 = 256 x 16B (1/thread)
    const int ga_row0 = tid >> 2, ga_c8 = (tid & 3) << 3;
    const int gb_row = tid >> 2, gb_c8 = (tid & 3) << 3;

    auto stage = [&](int kt) {
        const int s  = kt % 3;
        const int p  = kt >> 3;
        const int kk = (kt & 7) << 5;
        const bf16* Ag = ((p < 2) ? qfhi : qflo) + qbase;
        const bf16* Bg = ((p == 1) ? kvtlo : kvthi) + kbase;
#pragma unroll
        for (int i = 0; i < 4; i++) {
            int row = ga_row0 + i * 64;
            cp_async16(as_b[s] + (uint32_t)(row * LDT + ga_c8) * 2,
                       Ag + (size_t)row * Mc + kk + ga_c8);
        }
        cp_async16(bs_b[s] + (uint32_t)(gb_row * LDT + gb_c8) * 2,
                   Bg + (size_t)gb_row * Mc + kk + gb_c8);
        CP_COMMIT();
    };

    float acc[4][4][4];
#pragma unroll
    for (int mi = 0; mi < 4; mi++)
#pragma unroll
        for (int ni = 0; ni < 4; ni++)
#pragma unroll
            for (int e = 0; e < 4; e++) acc[mi][ni][e] = 0.f;

    stage(0); stage(1);

    for (int kt = 0; kt < ANIT; kt++) {
        const int s = kt % 3;
        if (kt + 1 < ANIT) CP_WAIT(1); else CP_WAIT(0);
        __syncthreads();
        if (kt + 2 < ANIT) stage(kt + 2);

#pragma unroll
        for (int k0 = 0; k0 < 32; k0 += 16) {
            uint32_t a[4][4];
#pragma unroll
            for (int mi = 0; mi < 4; mi++)
                ldsm_x4(a[mi], as_b[s] +
                        (uint32_t)((a_row + mi * 16) * LDT + k0 + a_col) * 2);
            uint32_t bf_[2][4];
#pragma unroll
            for (int pr = 0; pr < 2; pr++)
                ldsm_x4(bf_[pr], bs_b[s] +
                        (uint32_t)((b_row + pr * 16) * LDT + k0 + b_col) * 2);
#pragma unroll
            for (int mi = 0; mi < 4; mi++) {
                mma16816(acc[mi][0], a[mi], bf_[0][0], bf_[0][1]);
                mma16816(acc[mi][1], a[mi], bf_[0][2], bf_[0][3]);
                mma16816(acc[mi][2], a[mi], bf_[1][0], bf_[1][1]);
                mma16816(acc[mi][3], a[mi], bf_[1][2], bf_[1][3]);
            }
        }
    }

    // epilogue: multiply by z, write fp32
    const int lr = lane >> 2;
    const int occ0 = wn + ((lane & 3) << 1);
#pragma unroll
    for (int mi = 0; mi < 4; mi++) {
        const int r0 = wm + mi * 16 + lr;
        const int r1 = r0 + 8;
        const float z0 = z[(size_t)bh * Lc + l0 + r0];
        const float z1 = z[(size_t)bh * Lc + l0 + r1];
        float* p0 = &attn[(size_t)(b * Lc + l0 + r0) * Dc + h * DHc];
        float* p1 = &attn[(size_t)(b * Lc + l0 + r1) * Dc + h * DHc];
#pragma unroll
        for (int ni = 0; ni < 4; ni++) {
            int c = occ0 + ni * 8;
            *(float2*)&p0[c] = make_float2(acc[mi][ni][0] * z0, acc[mi][ni][1] * z0);
            *(float2*)&p1[c] = make_float2(acc[mi][ni][2] * z1, acc[mi][ni][3] * z1);
        }
    }
}

// ============================================================
// LayerNorm + duplicate rows (unchanged)
// ============================================================
__global__ __launch_bounds__(256) void ln_dup_kernel(
    const float* __restrict__ y, const float* __restrict__ g,
    const float* __restrict__ beta, float* __restrict__ out)
{
    __shared__ float red[18];
    const int row = blockIdx.x;
    const int b = row >> 12, l = row & 4095;
    const int tid = threadIdx.x;
    const float* yr = y + (size_t)row * Dc;

    float v[4];
    float s = 0.f, ss = 0.f;
#pragma unroll
    for (int i = 0; i < 4; i++) {
        float t = yr[tid + i * 256];
        v[i] = t; s += t; ss += t * t;
    }
#pragma unroll
    for (int off = 16; off; off >>= 1) {
        s  += __shfl_xor_sync(0xffffffffu, s, off);
        ss += __shfl_xor_sync(0xffffffffu, ss, off);
    }
    const int w = tid >> 5, lane = tid & 31;
    if (lane == 0) { red[w] = s; red[8 + w] = ss; }
    __syncthreads();
    if (tid == 0) {
        float ts = 0.f, tss = 0.f;
#pragma unroll
        for (int i = 0; i < 8; i++) { ts += red[i]; tss += red[8 + i]; }
        float mean = ts * (1.0f / 1024.0f);
        float var = tss * (1.0f / 1024.0f) - mean * mean;
        red[16] = mean;
        red[17] = rsqrtf(var + 1e-5f);
    }
    __syncthreads();
    const float mean = red[16], rstd = red[17];
    float* o0 = out + ((size_t)b * 8192 + 2 * (size_t)l) * Dc;
#pragma unroll
    for (int i = 0; i < 4; i++) {
        int c = tid + i * 256;
        float o = (v[i] - mean) * rstd * g[c] + beta[c];
        o0[c] = o;
        o0[Dc + c] = o;
    }
}

// ============================================================
// host launch
// ============================================================
extern "C" void kernel_launch(void* const* d_in, const int* in_sizes, int n_in,
                              void* d_out, int out_size)
{
    const float* x    = (const float*)d_in[0];
    const float* Wq   = (const float*)d_in[1];
    const float* Wk   = (const float*)d_in[2];
    const float* Wv   = (const float*)d_in[3];
    const float* Wo   = (const float*)d_in[4];
    const float* proj = (const float*)d_in[5];
    const float* ln_g = (const float*)d_in[6];
    const float* ln_b = (const float*)d_in[7];
    float* out = (float*)d_out;

    float *v, *kf, *kv, *ksum, *z, *attn, *y;
    bf16 *qfhi, *qflo, *kvthi, *kvtlo;
    bf16 *ahi, *alo, *bthi, *btlo, *qhi, *qlo, *khi, *klo, *phi, *plo;
    cudaGetSymbolAddress((void**)&v,     g_v);
    cudaGetSymbolAddress((void**)&kf,    g_kf);
    cudaGetSymbolAddress((void**)&qfhi,  g_qfhi);
    cudaGetSymbolAddress((void**)&qflo,  g_qflo);
    cudaGetSymbolAddress((void**)&kv,    g_kv);
    cudaGetSymbolAddress((void**)&kvthi, g_kvthi);
    cudaGetSymbolAddress((void**)&kvtlo, g_kvtlo);
    cudaGetSymbolAddress((void**)&ksum,  g_ksum);
    cudaGetSymbolAddress((void**)&z,     g_z);
    cudaGetSymbolAddress((void**)&attn,  g_attn);
    cudaGetSymbolAddress((void**)&y,     g_y);
    cudaGetSymbolAddress((void**)&ahi,   g_ahi);
    cudaGetSymbolAddress((void**)&alo,   g_alo);
    cudaGetSymbolAddress((void**)&bthi,  g_bthi);
    cudaGetSymbolAddress((void**)&btlo,  g_btlo);
    cudaGetSymbolAddress((void**)&qhi,   g_qhi);
    cudaGetSymbolAddress((void**)&qlo,   g_qlo);
    cudaGetSymbolAddress((void**)&khi,   g_khi);
    cudaGetSymbolAddress((void**)&klo,   g_klo);
    cudaGetSymbolAddress((void**)&phi,   g_phi);
    cudaGetSymbolAddress((void**)&plo,   g_plo);

    const float qscale = 0.35355339059327379f;  // 64^-0.25

    cudaFuncSetAttribute(mma_gemm_kernel,
                         cudaFuncAttributeMaxDynamicSharedMemorySize, GEMM_SMEM3);
    cudaFuncSetAttribute(feature_mma_kernel,
                         cudaFuncAttributeMaxDynamicSharedMemorySize, FEAT2_SMEM);
    cudaFuncSetAttribute(attn_mma_kernel,
                         cudaFuncAttributeMaxDynamicSharedMemorySize, ATT_SMEM);

    const int n4 = ROWS * Dc / 4;
    dim3 tgrid(32, 32), tblk(32, 8);

    // splits
    split_kernel<<<n4 / 256, 256>>>(x, ahi, alo, n4);
    split_kernel<<<(Hc * Mc * DHc / 4) / 256, 256>>>(proj, phi, plo, Hc * Mc * DHc / 4);
    tsplit_kernel<<<tgrid, tblk>>>(Wq, bthi,                  btlo);
    tsplit_kernel<<<tgrid, tblk>>>(Wk, bthi + (size_t)Dc*Dc,  btlo + (size_t)Dc*Dc);
    tsplit_kernel<<<tgrid, tblk>>>(Wv, bthi + (size_t)2*Dc*Dc, btlo + (size_t)2*Dc*Dc);

    // fused QKV GEMM (grid 24 x 64)
    mma_gemm_kernel<<<dim3(24, 64), 256, GEMM_SMEM3>>>(
        ahi, alo, bthi, btlo, v, qhi, qlo, khi, klo, qscale, 0);

    // features: Q -> bf16 hi/lo, K -> fp32
    feature_mma_kernel<<<dim3(Lc / 128, BHc), 256, FEAT2_SMEM>>>(
        qhi, qlo, phi, plo, nullptr, qfhi, qflo, 1);
    feature_mma_kernel<<<dim3(Lc / 128, BHc), 256, FEAT2_SMEM>>>(
        khi, klo, phi, plo, kf, nullptr, nullptr, 0);

    cudaMemsetAsync(kv,   0, (size_t)BHc * Mc * DHc * sizeof(float), 0);
    cudaMemsetAsync(ksum, 0, (size_t)BHc * Mc * sizeof(float), 0);
    kv_kernel<<<dim3(BHc, 16), 256>>>(kf, v, kv, ksum);
    kvt_kernel<<<BHc, 256>>>(kv, kvthi, kvtlo);

    z_kernel<<<dim3(Lc / 8, BHc), 256>>>(qfhi, qflo, ksum, z);
    attn_mma_kernel<<<dim3(Lc / 256, BHc), 256, ATT_SMEM>>>(
        qfhi, qflo, kvthi, kvtlo, z, attn);

    // O projection + exact GELU
    split_kernel<<<n4 / 256, 256>>>(attn, ahi, alo, n4);
    tsplit_kernel<<<tgrid, tblk>>>(Wo, bthi, btlo);
    mma_gemm_kernel<<<dim3(8, 64), 256, GEMM_SMEM3>>>(
        ahi, alo, bthi, btlo, y, nullptr, nullptr, nullptr, nullptr, 1.0f, 1);

    ln_dup_kernel<<<ROWS, 256>>>(y, ln_g, ln_b, out);
}

// round 7
// speedup vs baseline: 1.0662x; 1.0662x over previous
#include <cuda_runtime.h>
#include <cuda_bf16.h>
#include <math.h>
#include <stdint.h>

// Shapes (fixed)
#define Bc   2
#define Lc   4096
#define Dc   1024
#define Hc   16
#define DHc  64
#define Mc   256
#define BHc  32
#define ROWS 8192   // B*L

typedef __nv_bfloat16 bf16;

// -------- scratch (device globals; no allocations allowed) --------
__device__ float g_v    [(size_t)ROWS * Dc];
__device__ float g_kf   [(size_t)BHc * Lc * Mc];
__device__ bf16  g_qfhi [(size_t)BHc * Lc * Mc];
__device__ bf16  g_qflo [(size_t)BHc * Lc * Mc];
__device__ float g_kv   [(size_t)BHc * Mc * DHc];
__device__ bf16  g_kvthi[(size_t)BHc * DHc * Mc];
__device__ bf16  g_kvtlo[(size_t)BHc * DHc * Mc];
__device__ float g_ksum [(size_t)BHc * Mc];
__device__ float g_z    [(size_t)BHc * Lc];
__device__ float g_attn [(size_t)ROWS * Dc];
__device__ float g_y    [(size_t)ROWS * Dc];
__device__ bf16  g_ahi  [(size_t)ROWS * Dc];
__device__ bf16  g_alo  [(size_t)ROWS * Dc];
__device__ bf16  g_bthi [(size_t)3 * Dc * Dc];
__device__ bf16  g_btlo [(size_t)3 * Dc * Dc];
__device__ bf16  g_qhi  [(size_t)ROWS * Dc];
__device__ bf16  g_qlo  [(size_t)ROWS * Dc];
__device__ bf16  g_khi  [(size_t)ROWS * Dc];
__device__ bf16  g_klo  [(size_t)ROWS * Dc];
__device__ bf16  g_phi  [(size_t)Hc * Mc * DHc];
__device__ bf16  g_plo  [(size_t)Hc * Mc * DHc];

// ================= baseline-PTX tensor-core helpers (sm_80+) ==========
__device__ __forceinline__ uint32_t smem_u32(const void* p) {
    uint32_t a;
    asm("{ .reg .u64 t; cvta.to.shared.u64 t, %1; cvt.u32.u64 %0, t; }"
        : "=r"(a) : "l"(p));
    return a;
}
__device__ __forceinline__ void cp_async16(uint32_t saddr, const void* g) {
    asm volatile("cp.async.cg.shared.global [%0], [%1], 16;"
                 :: "r"(saddr), "l"(g) : "memory");
}
#define CP_COMMIT() asm volatile("cp.async.commit_group;" ::: "memory")
#define CP_WAIT(n)  asm volatile("cp.async.wait_group %0;" :: "n"(n) : "memory")

__device__ __forceinline__ void ldsm_x4(uint32_t r[4], uint32_t addr) {
    asm volatile("ldmatrix.sync.aligned.m8n8.x4.shared.b16 {%0,%1,%2,%3}, [%4];"
                 : "=r"(r[0]), "=r"(r[1]), "=r"(r[2]), "=r"(r[3]) : "r"(addr));
}
__device__ __forceinline__ void mma16816(float c[4], const uint32_t a[4],
                                         uint32_t b0, uint32_t b1) {
    asm volatile(
        "mma.sync.aligned.m16n8k16.row.col.f32.bf16.bf16.f32 "
        "{%0,%1,%2,%3}, {%4,%5,%6,%7}, {%8,%9}, {%0,%1,%2,%3};"
        : "+f"(c[0]), "+f"(c[1]), "+f"(c[2]), "+f"(c[3])
        : "r"(a[0]), "r"(a[1]), "r"(a[2]), "r"(a[3]), "r"(b0), "r"(b1));
}
__device__ __forceinline__ void split2(float v, bf16& h, bf16& l) {
    h = __float2bfloat16_rn(v);
    l = __float2bfloat16_rn(v - __bfloat162float(h));
}

// ============================================================
// fp32 -> (hi, lo) bf16 split
// ============================================================
__global__ __launch_bounds__(256) void split_kernel(
    const float* __restrict__ in, bf16* __restrict__ hi,
    bf16* __restrict__ lo, int n4)
{
    int i = blockIdx.x * 256 + threadIdx.x;
    if (i >= n4) return;
    float4 v = ((const float4*)in)[i];
    bf16 h0, h1, h2, h3, l0, l1, l2, l3;
    split2(v.x, h0, l0); split2(v.y, h1, l1);
    split2(v.z, h2, l2); split2(v.w, h3, l3);
    ((__nv_bfloat162*)hi)[2*i]   = __halves2bfloat162(h0, h1);
    ((__nv_bfloat162*)hi)[2*i+1] = __halves2bfloat162(h2, h3);
    ((__nv_bfloat162*)lo)[2*i]   = __halves2bfloat162(l0, l1);
    ((__nv_bfloat162*)lo)[2*i+1] = __halves2bfloat162(l2, l3);
}

// ============================================================
// W [K=1024, N=1024] -> W^T [N,K] with bf16 hi/lo split
// ============================================================
__global__ void tsplit_kernel(const float* __restrict__ W,
    bf16* __restrict__ Thi, bf16* __restrict__ Tlo)
{
    __shared__ float t[32][33];
    int bx = blockIdx.x * 32, by = blockIdx.y * 32;
    int tx = threadIdx.x, ty = threadIdx.y;   // 32 x 8
#pragma unroll
    for (int i = 0; i < 32; i += 8)
        t[ty + i][tx] = W[(size_t)(by + ty + i) * Dc + bx + tx];
    __syncthreads();
#pragma unroll
    for (int i = 0; i < 32; i += 8) {
        float v = t[tx][ty + i];
        int orow = bx + ty + i, ocol = by + tx;
        bf16 h, l; split2(v, h, l);
        Thi[(size_t)orow * Dc + ocol] = h;
        Tlo[(size_t)orow * Dc + ocol] = l;
    }
}

// ============================================================
// bf16x3 tensor-core GEMM, 3-stage cp.async pipeline, 1 sync/iter.
// MODE 0 (fused QKV): which = bn>>10: 0 -> Qhi/Qlo, 1 -> Khi/Klo (x qalpha),
//                     2 -> V fp32
// MODE 1 (single):    C fp32 with exact GELU
// CTA tile 128x128, BK=32, 8 warps x (64x32 warp tile), 2 CTAs/SM forced.
// ============================================================
#define LDT 40
#define GNIT 96
#define GEMM_STG (128 * LDT * 2)          // bytes per matrix stage
#define GEMM_SMEM3 (3 * 2 * GEMM_STG)     // 61440 B

template<int MODE>
__global__ __launch_bounds__(256, 2) void mma_gemm_kernel(
    const bf16* __restrict__ Ahi, const bf16* __restrict__ Alo,
    const bf16* __restrict__ Bhi, const bf16* __restrict__ Blo,
    float* __restrict__ Cv,
    bf16* __restrict__ Qhi, bf16* __restrict__ Qlo,
    bf16* __restrict__ Khi, bf16* __restrict__ Klo,
    float qalpha)
{
    extern __shared__ char gsm[];
    const int tid  = threadIdx.x;
    const int lane = tid & 31, wid = tid >> 5;
    const int bm = blockIdx.y * 128;
    const int bn = blockIdx.x * 128;
    const int wm = (wid >> 2) * 64;
    const int wn = (wid & 3) * 32;

    uint32_t as_b[3], bs_b[3];
#pragma unroll
    for (int s = 0; s < 3; s++) {
        as_b[s] = smem_u32(gsm + s * 2 * GEMM_STG);
        bs_b[s] = as_b[s] + GEMM_STG;
    }

    const int a_row = wm + (lane & 15);
    const int a_col = (lane >> 4) << 3;
    const int b_row = wn + (lane & 7) + ((lane >> 4) << 3);
    const int b_col = ((lane >> 3) & 1) << 3;

    const int g_row0 = tid >> 2;
    const int g_c8   = (tid & 3) << 3;

    auto stage = [&](int kt) {
        const int s  = kt % 3;
        const int p  = kt >> 5;
        const int kk = (kt & 31) << 5;
        const bf16* Ag = (p < 2) ? Ahi : Alo;
        const bf16* Bg = (p == 1) ? Blo : Bhi;
#pragma unroll
        for (int i = 0; i < 2; i++) {
            int row = g_row0 + i * 64;
            uint32_t soff = (uint32_t)(row * LDT + g_c8) * 2;
            cp_async16(as_b[s] + soff, Ag + (size_t)(bm + row) * Dc + kk + g_c8);
            cp_async16(bs_b[s] + soff, Bg + (size_t)(bn + row) * Dc + kk + g_c8);
        }
        CP_COMMIT();
    };

    float acc[4][4][4];
#pragma unroll
    for (int mi = 0; mi < 4; mi++)
#pragma unroll
        for (int ni = 0; ni < 4; ni++)
#pragma unroll
            for (int e = 0; e < 4; e++) acc[mi][ni][e] = 0.f;

    stage(0); stage(1);

    for (int kt = 0; kt < GNIT; kt++) {
        const int s = kt % 3;
        if (kt + 1 < GNIT) CP_WAIT(1); else CP_WAIT(0);
        __syncthreads();
        if (kt + 2 < GNIT) stage(kt + 2);

#pragma unroll
        for (int k0 = 0; k0 < 32; k0 += 16) {
            uint32_t a[4][4];
#pragma unroll
            for (int mi = 0; mi < 4; mi++)
                ldsm_x4(a[mi], as_b[s] +
                        (uint32_t)((a_row + mi * 16) * LDT + k0 + a_col) * 2);
            uint32_t b[2][4];
#pragma unroll
            for (int pr = 0; pr < 2; pr++)
                ldsm_x4(b[pr], bs_b[s] +
                        (uint32_t)((b_row + pr * 16) * LDT + k0 + b_col) * 2);
#pragma unroll
            for (int mi = 0; mi < 4; mi++) {
                mma16816(acc[mi][0], a[mi], b[0][0], b[0][1]);
                mma16816(acc[mi][1], a[mi], b[0][2], b[0][3]);
                mma16816(acc[mi][2], a[mi], b[1][0], b[1][1]);
                mma16816(acc[mi][3], a[mi], b[1][2], b[1][3]);
            }
        }
    }

    // epilogue: 64x32 warp tile
    const int orow = bm + wm + (lane >> 2);
    const int occ0 = wn + ((lane & 3) << 1);

    if (MODE == 0) {
        const int which = bn >> 10;        // 0 q, 1 k, 2 v
        const int bnl = bn & 1023;
        if (which < 2) {
            bf16* Oh = which ? Khi : Qhi;
            bf16* Ol = which ? Klo : Qlo;
#pragma unroll
            for (int mi = 0; mi < 4; mi++)
#pragma unroll
                for (int ni = 0; ni < 4; ni++) {
                    const size_t i0 = (size_t)(orow + mi * 16) * Dc + bnl + occ0 + ni * 8;
                    const size_t i1 = (size_t)(orow + mi * 16 + 8) * Dc + bnl + occ0 + ni * 8;
                    bf16 h0,l0,h1,l1,h2,l2,h3,l3;
                    split2(acc[mi][ni][0] * qalpha, h0, l0);
                    split2(acc[mi][ni][1] * qalpha, h1, l1);
                    split2(acc[mi][ni][2] * qalpha, h2, l2);
                    split2(acc[mi][ni][3] * qalpha, h3, l3);
                    *(__nv_bfloat162*)&Oh[i0] = __halves2bfloat162(h0, h1);
                    *(__nv_bfloat162*)&Oh[i1] = __halves2bfloat162(h2, h3);
                    *(__nv_bfloat162*)&Ol[i0] = __halves2bfloat162(l0, l1);
                    *(__nv_bfloat162*)&Ol[i1] = __halves2bfloat162(l2, l3);
                }
        } else {
#pragma unroll
            for (int mi = 0; mi < 4; mi++)
#pragma unroll
                for (int ni = 0; ni < 4; ni++) {
                    const size_t i0 = (size_t)(orow + mi * 16) * Dc + bnl + occ0 + ni * 8;
                    const size_t i1 = (size_t)(orow + mi * 16 + 8) * Dc + bnl + occ0 + ni * 8;
                    *(float2*)&Cv[i0] = make_float2(acc[mi][ni][0], acc[mi][ni][1]);
                    *(float2*)&Cv[i1] = make_float2(acc[mi][ni][2], acc[mi][ni][3]);
                }
        }
    } else {
#pragma unroll
        for (int mi = 0; mi < 4; mi++)
#pragma unroll
            for (int ni = 0; ni < 4; ni++) {
                float v0 = acc[mi][ni][0], v1 = acc[mi][ni][1];
                float v2 = acc[mi][ni][2], v3 = acc[mi][ni][3];
                v0 = 0.5f * v0 * (1.f + erff(v0 * 0.70710678118654752f));
                v1 = 0.5f * v1 * (1.f + erff(v1 * 0.70710678118654752f));
                v2 = 0.5f * v2 * (1.f + erff(v2 * 0.70710678118654752f));
                v3 = 0.5f * v3 * (1.f + erff(v3 * 0.70710678118654752f));
                const size_t i0 = (size_t)(orow + mi * 16) * Dc + bn + occ0 + ni * 8;
                const size_t i1 = (size_t)(orow + mi * 16 + 8) * Dc + bn + occ0 + ni * 8;
                *(float2*)&Cv[i0] = make_float2(v0, v1);
                *(float2*)&Cv[i1] = make_float2(v2, v3);
            }
    }
}

// ============================================================
// FAVOR+ feature via mma.sync bf16x3 (as R5), output mode:
//   omode 0: fp32 F    omode 1: bf16 hi/lo (Fhi, Flo)
// ============================================================
#define FLDK 72
#define FEAT2_SMEM ((128 + 128 + 256 + 256) * FLDK * 2 + 128 * 4 + 4 * 128 * 4)

__global__ __launch_bounds__(256) void feature_mma_kernel(
    const bf16* __restrict__ Uhi, const bf16* __restrict__ Ulo,
    const bf16* __restrict__ Phi, const bf16* __restrict__ Plo,
    float* __restrict__ F, bf16* __restrict__ Fhi, bf16* __restrict__ Flo,
    int omode)
{
    extern __shared__ char fsm[];
    bf16* us_h = (bf16*)fsm;                    // [128][FLDK]
    bf16* us_l = us_h + 128 * FLDK;
    bf16* ps_h = us_l + 128 * FLDK;             // [256][FLDK]
    bf16* ps_l = ps_h + 256 * FLDK;
    float* diag  = (float*)(ps_l + 256 * FLDK); // [128]
    float* rmaxp = diag + 128;                  // [4][128]

    const int bh = blockIdx.y;
    const int b = bh >> 4, h = bh & 15;
    const int l0 = blockIdx.x * 128;
    const int tid = threadIdx.x;
    const int lane = tid & 31, wid = tid >> 5;

#pragma unroll
    for (int i = 0; i < 4; i++) {
        int s = tid + i * 256;
        int r = s >> 3, c8 = (s & 7) << 3;
        size_t gi = (size_t)(b * Lc + l0 + r) * Dc + h * DHc + c8;
        *(uint4*)&us_h[r * FLDK + c8] = *(const uint4*)&Uhi[gi];
        *(uint4*)&us_l[r * FLDK + c8] = *(const uint4*)&Ulo[gi];
    }
#pragma unroll
    for (int i = 0; i < 8; i++) {
        int s = tid + i * 256;
        int r = s >> 3, c8 = (s & 7) << 3;
        size_t gi = (size_t)(h * Mc + r) * DHc + c8;
        *(uint4*)&ps_h[r * FLDK + c8] = *(const uint4*)&Phi[gi];
        *(uint4*)&ps_l[r * FLDK + c8] = *(const uint4*)&Plo[gi];
    }
    __syncthreads();

    if (tid < 128) {
        float s = 0.f;
#pragma unroll
        for (int d2 = 0; d2 < 32; d2++) {
            __nv_bfloat162 hh = *(__nv_bfloat162*)&us_h[tid * FLDK + d2 * 2];
            __nv_bfloat162 ll = *(__nv_bfloat162*)&us_l[tid * FLDK + d2 * 2];
            float u0 = __bfloat162float(hh.x) + __bfloat162float(ll.x);
            float u1 = __bfloat162float(hh.y) + __bfloat162float(ll.y);
            s += u0 * u0 + u1 * u1;
        }
        diag[tid] = 0.5f * s;
    }

    const int wm = (wid >> 2) * 64;
    const int wn = (wid & 3) * 64;
    const int a_row = wm + (lane & 15);
    const int a_col = (lane >> 4) << 3;
    const int b_row = wn + (lane & 7) + ((lane >> 4) << 3);
    const int b_col = ((lane >> 3) & 1) << 3;

    float acc[4][8][4];
#pragma unroll
    for (int mi = 0; mi < 4; mi++)
#pragma unroll
        for (int ni = 0; ni < 8; ni++)
#pragma unroll
            for (int e = 0; e < 4; e++) acc[mi][ni][e] = 0.f;

    const uint32_t ush = smem_u32(us_h), usl = smem_u32(us_l);
    const uint32_t psh = smem_u32(ps_h), psl = smem_u32(ps_l);
    __syncthreads();

#pragma unroll
    for (int p = 0; p < 3; p++) {
        const uint32_t ab = (p < 2) ? ush : usl;
        const uint32_t bb = (p == 1) ? psl : psh;
#pragma unroll
        for (int k0 = 0; k0 < 64; k0 += 16) {
            uint32_t a[4][4], bfr[4][4];
#pragma unroll
            for (int mi = 0; mi < 4; mi++)
                ldsm_x4(a[mi], ab + (uint32_t)((a_row + mi * 16) * FLDK + k0 + a_col) * 2);
#pragma unroll
            for (int pr = 0; pr < 4; pr++)
                ldsm_x4(bfr[pr], bb + (uint32_t)((b_row + pr * 16) * FLDK + k0 + b_col) * 2);
#pragma unroll
            for (int mi = 0; mi < 4; mi++)
#pragma unroll
                for (int pr = 0; pr < 4; pr++) {
                    mma16816(acc[mi][2 * pr],     a[mi], bfr[pr][0], bfr[pr][1]);
                    mma16816(acc[mi][2 * pr + 1], a[mi], bfr[pr][2], bfr[pr][3]);
                }
        }
    }

    float tmax[4][2];
#pragma unroll
    for (int mi = 0; mi < 4; mi++) {
        float m0 = -1e30f, m1 = -1e30f;
#pragma unroll
        for (int ni = 0; ni < 8; ni++) {
            m0 = fmaxf(m0, fmaxf(acc[mi][ni][0], acc[mi][ni][1]));
            m1 = fmaxf(m1, fmaxf(acc[mi][ni][2], acc[mi][ni][3]));
        }
#pragma unroll
        for (int off = 1; off <= 2; off <<= 1) {
            m0 = fmaxf(m0, __shfl_xor_sync(0xffffffffu, m0, off));
            m1 = fmaxf(m1, __shfl_xor_sync(0xffffffffu, m1, off));
        }
        tmax[mi][0] = m0; tmax[mi][1] = m1;
    }
    if ((lane & 3) == 0) {
        const int slab = wid & 3;
#pragma unroll
        for (int mi = 0; mi < 4; mi++) {
            int r = wm + mi * 16 + (lane >> 2);
            rmaxp[slab * 128 + r]     = tmax[mi][0];
            rmaxp[slab * 128 + r + 8] = tmax[mi][1];
        }
    }
    __syncthreads();

#pragma unroll
    for (int mi = 0; mi < 4; mi++) {
        const int r0 = wm + mi * 16 + (lane >> 2);
        const int r1 = r0 + 8;
        float rm0 = fmaxf(fmaxf(rmaxp[r0], rmaxp[128 + r0]),
                          fmaxf(rmaxp[256 + r0], rmaxp[384 + r0]));
        float rm1 = fmaxf(fmaxf(rmaxp[r1], rmaxp[128 + r1]),
                          fmaxf(rmaxp[256 + r1], rmaxp[384 + r1]));
        const float base0 = -diag[r0] - rm0;
        const float base1 = -diag[r1] - rm1;
        const size_t o0 = ((size_t)bh * Lc + l0 + r0) * Mc;
        const size_t o1 = ((size_t)bh * Lc + l0 + r1) * Mc;
        const int c0 = wn + ((lane & 3) << 1);
#pragma unroll
        for (int ni = 0; ni < 8; ni++) {
            int c = c0 + ni * 8;
            float f0 = __expf(acc[mi][ni][0] + base0) * 0.0625f;
            float f1 = __expf(acc[mi][ni][1] + base0) * 0.0625f;
            float f2 = __expf(acc[mi][ni][2] + base1) * 0.0625f;
            float f3 = __expf(acc[mi][ni][3] + base1) * 0.0625f;
            if (omode == 0) {
                *(float2*)&F[o0 + c] = make_float2(f0, f1);
                *(float2*)&F[o1 + c] = make_float2(f2, f3);
            } else {
                bf16 h0,l0b,h1,l1b,h2,l2b,h3,l3b;
                split2(f0, h0, l0b); split2(f1, h1, l1b);
                split2(f2, h2, l2b); split2(f3, h3, l3b);
                *(__nv_bfloat162*)&Fhi[o0 + c] = __halves2bfloat162(h0, h1);
                *(__nv_bfloat162*)&Fhi[o1 + c] = __halves2bfloat162(h2, h3);
                *(__nv_bfloat162*)&Flo[o0 + c] = __halves2bfloat162(l0b, l1b);
                *(__nv_bfloat162*)&Flo[o1 + c] = __halves2bfloat162(l2b, l3b);
            }
        }
    }
}

// ============================================================
// kv[m,d] = sum_l kf[l,m]*v[l,d];  ksum[m] = sum_l kf[l,m]
// ============================================================
__global__ __launch_bounds__(256) void kv_kernel(
    const float* __restrict__ kf, const float* __restrict__ v,
    float* __restrict__ kv, float* __restrict__ ksum)
{
    __shared__ float vs[16][64];
    const int bh = blockIdx.x;
    const int b = bh >> 4, h = bh & 15;
    const int l0 = blockIdx.y * 256;
    const int t = threadIdx.x;

    float acc[64];
#pragma unroll
    for (int d = 0; d < 64; d++) acc[d] = 0.f;
    float s = 0.f;

    for (int l = l0; l < l0 + 256; l += 16) {
        {
            int r = t >> 4, c4 = (t & 15) << 2;
            *(float4*)&vs[r][c4] =
                *(const float4*)&v[(size_t)(b * Lc + l + r) * Dc + h * DHc + c4];
        }
        __syncthreads();
#pragma unroll
        for (int r = 0; r < 16; r++) {
            float a = kf[((size_t)bh * Lc + l + r) * Mc + t];
            s += a;
#pragma unroll
            for (int d4 = 0; d4 < 16; d4++) {
                float4 vv = *(const float4*)&vs[r][d4 * 4];
                acc[d4 * 4 + 0] += a * vv.x;
                acc[d4 * 4 + 1] += a * vv.y;
                acc[d4 * 4 + 2] += a * vv.z;
                acc[d4 * 4 + 3] += a * vv.w;
            }
        }
        __syncthreads();
    }
    float* kvp = kv + ((size_t)bh * Mc + t) * DHc;
#pragma unroll
    for (int d = 0; d < 64; d++) atomicAdd(&kvp[d], acc[d]);
    atomicAdd(&ksum[bh * Mc + t], s);
}

// ============================================================
// kv [bh][256][64] fp32 -> kvt [bh][64][256] bf16 hi/lo
// ============================================================
__global__ __launch_bounds__(256) void kvt_kernel(
    const float* __restrict__ kv, bf16* __restrict__ Thi, bf16* __restrict__ Tlo)
{
    const int bh = blockIdx.x;
    const float* src = kv + (size_t)bh * Mc * DHc;
    bf16* dh = Thi + (size_t)bh * DHc * Mc;
    bf16* dl = Tlo + (size_t)bh * DHc * Mc;
    for (int o = threadIdx.x; o < DHc * Mc; o += 256) {
        int n = o >> 8, m = o & 255;
        float v = src[m * DHc + n];
        bf16 h, l; split2(v, h, l);
        dh[o] = h; dl[o] = l;
    }
}

// ============================================================
// z[bh,l] = 1 / (dot(qf_hi+qf_lo, ksum) + 1e-6)
// ============================================================
__global__ __launch_bounds__(256) void z_kernel(
    const bf16* __restrict__ qfhi, const bf16* __restrict__ qflo,
    const float* __restrict__ ksum, float* __restrict__ z)
{
    __shared__ float ks[256];
    const int bh = blockIdx.y;
    ks[threadIdx.x] = ksum[bh * Mc + threadIdx.x];
    __syncthreads();
    const int w = threadIdx.x >> 5, lane = threadIdx.x & 31;
    const int l = blockIdx.x * 8 + w;
    const size_t base = ((size_t)bh * Lc + l) * Mc;
    float s = 0.f;
#pragma unroll
    for (int q8 = 0; q8 < 8; q8++) {
        int c = lane + q8 * 32;
        s += (__bfloat162float(qfhi[base + c]) + __bfloat162float(qflo[base + c])) * ks[c];
    }
#pragma unroll
    for (int off = 16; off; off >>= 1) s += __shfl_xor_sync(0xffffffffu, s, off);
    if (lane == 0) z[bh * Lc + l] = 1.0f / (s + 1e-6f);
}

// ============================================================
// attn via mma bf16x3, 2 CTAs/SM forced
// ============================================================
#define ANIT 24                           // 3 passes * (256/32)
#define ATT_ASTG (256 * LDT * 2)          // 20480 B
#define ATT_BSTG (64 * LDT * 2)           // 5120 B
#define ATT_SMEM (3 * (ATT_ASTG + ATT_BSTG))   // 76800 B

__global__ __launch_bounds__(256, 2) void attn_mma_kernel(
    const bf16* __restrict__ qfhi, const bf16* __restrict__ qflo,
    const bf16* __restrict__ kvthi, const bf16* __restrict__ kvtlo,
    const float* __restrict__ z, float* __restrict__ attn)
{
    extern __shared__ char asm_[];
    const int bh = blockIdx.y;
    const int b = bh >> 4, h = bh & 15;
    const int l0 = blockIdx.x * 256;
    const int tid = threadIdx.x;
    const int lane = tid & 31, wid = tid >> 5;
    const int wm = (wid >> 1) * 64;
    const int wn = (wid & 1) * 32;

    uint32_t as_b[3], bs_b[3];
#pragma unroll
    for (int s = 0; s < 3; s++) {
        as_b[s] = smem_u32(asm_ + s * (ATT_ASTG + ATT_BSTG));
        bs_b[s] = as_b[s] + ATT_ASTG;
    }

    const int a_row = wm + (lane & 15);
    const int a_col = (lane >> 4) << 3;
    const int b_row = wn + (lane & 7) + ((lane >> 4) << 3);
    const int b_col = ((lane >> 3) & 1) << 3;

    const size_t qbase = ((size_t)bh * Lc + l0) * Mc;
    const size_t kbase = (size_t)bh * DHc * Mc;

    const int ga_row0 = tid >> 2, ga_c8 = (tid & 3) << 3;
    const int gb_row = tid >> 2, gb_c8 = (tid & 3) << 3;

    auto stage = [&](int kt) {
        const int s  = kt % 3;
        const int p  = kt >> 3;
        const int kk = (kt & 7) << 5;
        const bf16* Ag = ((p < 2) ? qfhi : qflo) + qbase;
        const bf16* Bg = ((p == 1) ? kvtlo : kvthi) + kbase;
#pragma unroll
        for (int i = 0; i < 4; i++) {
            int row = ga_row0 + i * 64;
            cp_async16(as_b[s] + (uint32_t)(row * LDT + ga_c8) * 2,
                       Ag + (size_t)row * Mc + kk + ga_c8);
        }
        cp_async16(bs_b[s] + (uint32_t)(gb_row * LDT + gb_c8) * 2,
                   Bg + (size_t)gb_row * Mc + kk + gb_c8);
        CP_COMMIT();
    };

    float acc[4][4][4];
#pragma unroll
    for (int mi = 0; mi < 4; mi++)
#pragma unroll
        for (int ni = 0; ni < 4; ni++)
#pragma unroll
            for (int e = 0; e < 4; e++) acc[mi][ni][e] = 0.f;

    stage(0); stage(1);

    for (int kt = 0; kt < ANIT; kt++) {
        const int s = kt % 3;
        if (kt + 1 < ANIT) CP_WAIT(1); else CP_WAIT(0);
        __syncthreads();
        if (kt + 2 < ANIT) stage(kt + 2);

#pragma unroll
        for (int k0 = 0; k0 < 32; k0 += 16) {
            uint32_t a[4][4];
#pragma unroll
            for (int mi = 0; mi < 4; mi++)
                ldsm_x4(a[mi], as_b[s] +
                        (uint32_t)((a_row + mi * 16) * LDT + k0 + a_col) * 2);
            uint32_t bf_[2][4];
#pragma unroll
            for (int pr = 0; pr < 2; pr++)
                ldsm_x4(bf_[pr], bs_b[s] +
                        (uint32_t)((b_row + pr * 16) * LDT + k0 + b_col) * 2);
#pragma unroll
            for (int mi = 0; mi < 4; mi++) {
                mma16816(acc[mi][0], a[mi], bf_[0][0], bf_[0][1]);
                mma16816(acc[mi][1], a[mi], bf_[0][2], bf_[0][3]);
                mma16816(acc[mi][2], a[mi], bf_[1][0], bf_[1][1]);
                mma16816(acc[mi][3], a[mi], bf_[1][2], bf_[1][3]);
            }
        }
    }

    const int lr = lane >> 2;
    const int occ0 = wn + ((lane & 3) << 1);
#pragma unroll
    for (int mi = 0; mi < 4; mi++) {
        const int r0 = wm + mi * 16 + lr;
        const int r1 = r0 + 8;
        const float z0 = z[(size_t)bh * Lc + l0 + r0];
        const float z1 = z[(size_t)bh * Lc + l0 + r1];
        float* p0 = &attn[(size_t)(b * Lc + l0 + r0) * Dc + h * DHc];
        float* p1 = &attn[(size_t)(b * Lc + l0 + r1) * Dc + h * DHc];
#pragma unroll
        for (int ni = 0; ni < 4; ni++) {
            int c = occ0 + ni * 8;
            *(float2*)&p0[c] = make_float2(acc[mi][ni][0] * z0, acc[mi][ni][1] * z0);
            *(float2*)&p1[c] = make_float2(acc[mi][ni][2] * z1, acc[mi][ni][3] * z1);
        }
    }
}

// ============================================================
// LayerNorm + duplicate rows
// ============================================================
__global__ __launch_bounds__(256) void ln_dup_kernel(
    const float* __restrict__ y, const float* __restrict__ g,
    const float* __restrict__ beta, float* __restrict__ out)
{
    __shared__ float red[18];
    const int row = blockIdx.x;
    const int b = row >> 12, l = row & 4095;
    const int tid = threadIdx.x;
    const float* yr = y + (size_t)row * Dc;

    float v[4];
    float s = 0.f, ss = 0.f;
#pragma unroll
    for (int i = 0; i < 4; i++) {
        float t = yr[tid + i * 256];
        v[i] = t; s += t; ss += t * t;
    }
#pragma unroll
    for (int off = 16; off; off >>= 1) {
        s  += __shfl_xor_sync(0xffffffffu, s, off);
        ss += __shfl_xor_sync(0xffffffffu, ss, off);
    }
    const int w = tid >> 5, lane = tid & 31;
    if (lane == 0) { red[w] = s; red[8 + w] = ss; }
    __syncthreads();
    if (tid == 0) {
        float ts = 0.f, tss = 0.f;
#pragma unroll
        for (int i = 0; i < 8; i++) { ts += red[i]; tss += red[8 + i]; }
        float mean = ts * (1.0f / 1024.0f);
        float var = tss * (1.0f / 1024.0f) - mean * mean;
        red[16] = mean;
        red[17] = rsqrtf(var + 1e-5f);
    }
    __syncthreads();
    const float mean = red[16], rstd = red[17];
    float* o0 = out + ((size_t)b * 8192 + 2 * (size_t)l) * Dc;
#pragma unroll
    for (int i = 0; i < 4; i++) {
        int c = tid + i * 256;
        float o = (v[i] - mean) * rstd * g[c] + beta[c];
        o0[c] = o;
        o0[Dc + c] = o;
    }
}

// ============================================================
// host launch
// ============================================================
extern "C" void kernel_launch(void* const* d_in, const int* in_sizes, int n_in,
                              void* d_out, int out_size)
{
    const float* x    = (const float*)d_in[0];
    const float* Wq   = (const float*)d_in[1];
    const float* Wk   = (const float*)d_in[2];
    const float* Wv   = (const float*)d_in[3];
    const float* Wo   = (const float*)d_in[4];
    const float* proj = (const float*)d_in[5];
    const float* ln_g = (const float*)d_in[6];
    const float* ln_b = (const float*)d_in[7];
    float* out = (float*)d_out;

    float *v, *kf, *kv, *ksum, *z, *attn, *y;
    bf16 *qfhi, *qflo, *kvthi, *kvtlo;
    bf16 *ahi, *alo, *bthi, *btlo, *qhi, *qlo, *khi, *klo, *phi, *plo;
    cudaGetSymbolAddress((void**)&v,     g_v);
    cudaGetSymbolAddress((void**)&kf,    g_kf);
    cudaGetSymbolAddress((void**)&qfhi,  g_qfhi);
    cudaGetSymbolAddress((void**)&qflo,  g_qflo);
    cudaGetSymbolAddress((void**)&kv,    g_kv);
    cudaGetSymbolAddress((void**)&kvthi, g_kvthi);
    cudaGetSymbolAddress((void**)&kvtlo, g_kvtlo);
    cudaGetSymbolAddress((void**)&ksum,  g_ksum);
    cudaGetSymbolAddress((void**)&z,     g_z);
    cudaGetSymbolAddress((void**)&attn,  g_attn);
    cudaGetSymbolAddress((void**)&y,     g_y);
    cudaGetSymbolAddress((void**)&ahi,   g_ahi);
    cudaGetSymbolAddress((void**)&alo,   g_alo);
    cudaGetSymbolAddress((void**)&bthi,  g_bthi);
    cudaGetSymbolAddress((void**)&btlo,  g_btlo);
    cudaGetSymbolAddress((void**)&qhi,   g_qhi);
    cudaGetSymbolAddress((void**)&qlo,   g_qlo);
    cudaGetSymbolAddress((void**)&khi,   g_khi);
    cudaGetSymbolAddress((void**)&klo,   g_klo);
    cudaGetSymbolAddress((void**)&phi,   g_phi);
    cudaGetSymbolAddress((void**)&plo,   g_plo);

    const float qscale = 0.35355339059327379f;  // 64^-0.25

    cudaFuncSetAttribute(mma_gemm_kernel<0>,
                         cudaFuncAttributeMaxDynamicSharedMemorySize, GEMM_SMEM3);
    cudaFuncSetAttribute(mma_gemm_kernel<1>,
                         cudaFuncAttributeMaxDynamicSharedMemorySize, GEMM_SMEM3);
    cudaFuncSetAttribute(feature_mma_kernel,
                         cudaFuncAttributeMaxDynamicSharedMemorySize, FEAT2_SMEM);
    cudaFuncSetAttribute(attn_mma_kernel,
                         cudaFuncAttributeMaxDynamicSharedMemorySize, ATT_SMEM);

    const int n4 = ROWS * Dc / 4;
    dim3 tgrid(32, 32), tblk(32, 8);

    // splits
    split_kernel<<<n4 / 256, 256>>>(x, ahi, alo, n4);
    split_kernel<<<(Hc * Mc * DHc / 4) / 256, 256>>>(proj, phi, plo, Hc * Mc * DHc / 4);
    tsplit_kernel<<<tgrid, tblk>>>(Wq, bthi,                  btlo);
    tsplit_kernel<<<tgrid, tblk>>>(Wk, bthi + (size_t)Dc*Dc,  btlo + (size_t)Dc*Dc);
    tsplit_kernel<<<tgrid, tblk>>>(Wv, bthi + (size_t)2*Dc*Dc, btlo + (size_t)2*Dc*Dc);

    // fused QKV GEMM (grid 24 x 64)
    mma_gemm_kernel<0><<<dim3(24, 64), 256, GEMM_SMEM3>>>(
        ahi, alo, bthi, btlo, v, qhi, qlo, khi, klo, qscale);

    // features: Q -> bf16 hi/lo, K -> fp32
    feature_mma_kernel<<<dim3(Lc / 128, BHc), 256, FEAT2_SMEM>>>(
        qhi, qlo, phi, plo, nullptr, qfhi, qflo, 1);
    feature_mma_kernel<<<dim3(Lc / 128, BHc), 256, FEAT2_SMEM>>>(
        khi, klo, phi, plo, kf, nullptr, nullptr, 0);

    cudaMemsetAsync(kv,   0, (size_t)BHc * Mc * DHc * sizeof(float), 0);
    cudaMemsetAsync(ksum, 0, (size_t)BHc * Mc * sizeof(float), 0);
    kv_kernel<<<dim3(BHc, 16), 256>>>(kf, v, kv, ksum);
    kvt_kernel<<<BHc, 256>>>(kv, kvthi, kvtlo);

    z_kernel<<<dim3(Lc / 8, BHc), 256>>>(qfhi, qflo, ksum, z);
    attn_mma_kernel<<<dim3(Lc / 256, BHc), 256, ATT_SMEM>>>(
        qfhi, qflo, kvthi, kvtlo, z, attn);

    // O projection + exact GELU
    split_kernel<<<n4 / 256, 256>>>(attn, ahi, alo, n4);
    tsplit_kernel<<<tgrid, tblk>>>(Wo, bthi, btlo);
    mma_gemm_kernel<1><<<dim3(8, 64), 256, GEMM_SMEM3>>>(
        ahi, alo, bthi, btlo, y, nullptr, nullptr, nullptr, nullptr, 1.0f);

    ln_dup_kernel<<<ROWS, 256>>>(y, ln_g, ln_b, out);
}

// round 8
// speedup vs baseline: 1.1202x; 1.0506x over previous
#include <cuda_runtime.h>
#include <cuda_bf16.h>
#include <math.h>
#include <stdint.h>

// Shapes (fixed)
#define Bc   2
#define Lc   4096
#define Dc   1024
#define Hc   16
#define DHc  64
#define Mc   256
#define BHc  32
#define ROWS 8192   // B*L

typedef __nv_bfloat16 bf16;

// -------- scratch (device globals; no allocations allowed) --------
__device__ float g_v    [(size_t)ROWS * Dc];
__device__ bf16  g_qfhi [(size_t)BHc * Lc * Mc];
__device__ bf16  g_qflo [(size_t)BHc * Lc * Mc];
__device__ bf16  g_kfthi[(size_t)BHc * Mc * Lc];
__device__ bf16  g_kftlo[(size_t)BHc * Mc * Lc];
__device__ bf16  g_vthi [(size_t)BHc * DHc * Lc];
__device__ bf16  g_vtlo [(size_t)BHc * DHc * Lc];
__device__ float g_kvtf [(size_t)BHc * DHc * Mc];
__device__ bf16  g_kvthi[(size_t)BHc * DHc * Mc];
__device__ bf16  g_kvtlo[(size_t)BHc * DHc * Mc];
__device__ float g_ksum [(size_t)BHc * Mc];
__device__ float g_z    [(size_t)BHc * Lc];
__device__ float g_y    [(size_t)ROWS * Dc];
__device__ bf16  g_ahi  [(size_t)ROWS * Dc];
__device__ bf16  g_alo  [(size_t)ROWS * Dc];
__device__ bf16  g_bthi [(size_t)3 * Dc * Dc];
__device__ bf16  g_btlo [(size_t)3 * Dc * Dc];
__device__ bf16  g_qhi  [(size_t)ROWS * Dc];
__device__ bf16  g_qlo  [(size_t)ROWS * Dc];
__device__ bf16  g_khi  [(size_t)ROWS * Dc];
__device__ bf16  g_klo  [(size_t)ROWS * Dc];
__device__ bf16  g_phi  [(size_t)Hc * Mc * DHc];
__device__ bf16  g_plo  [(size_t)Hc * Mc * DHc];

// ================= baseline-PTX tensor-core helpers (sm_80+) ==========
__device__ __forceinline__ uint32_t smem_u32(const void* p) {
    uint32_t a;
    asm("{ .reg .u64 t; cvta.to.shared.u64 t, %1; cvt.u32.u64 %0, t; }"
        : "=r"(a) : "l"(p));
    return a;
}
__device__ __forceinline__ void cp_async16(uint32_t saddr, const void* g) {
    asm volatile("cp.async.cg.shared.global [%0], [%1], 16;"
                 :: "r"(saddr), "l"(g) : "memory");
}
#define CP_COMMIT() asm volatile("cp.async.commit_group;" ::: "memory")
#define CP_WAIT(n)  asm volatile("cp.async.wait_group %0;" :: "n"(n) : "memory")

__device__ __forceinline__ void ldsm_x4(uint32_t r[4], uint32_t addr) {
    asm volatile("ldmatrix.sync.aligned.m8n8.x4.shared.b16 {%0,%1,%2,%3}, [%4];"
                 : "=r"(r[0]), "=r"(r[1]), "=r"(r[2]), "=r"(r[3]) : "r"(addr));
}
__device__ __forceinline__ void mma16816(float c[4], const uint32_t a[4],
                                         uint32_t b0, uint32_t b1) {
    asm volatile(
        "mma.sync.aligned.m16n8k16.row.col.f32.bf16.bf16.f32 "
        "{%0,%1,%2,%3}, {%4,%5,%6,%7}, {%8,%9}, {%0,%1,%2,%3};"
        : "+f"(c[0]), "+f"(c[1]), "+f"(c[2]), "+f"(c[3])
        : "r"(a[0]), "r"(a[1]), "r"(a[2]), "r"(a[3]), "r"(b0), "r"(b1));
}
__device__ __forceinline__ void split2(float v, bf16& h, bf16& l) {
    h = __float2bfloat16_rn(v);
    l = __float2bfloat16_rn(v - __bfloat162float(h));
}

// ============================================================
// fp32 -> (hi, lo) bf16 split
// ============================================================
__global__ __launch_bounds__(256) void split_kernel(
    const float* __restrict__ in, bf16* __restrict__ hi,
    bf16* __restrict__ lo, int n4)
{
    int i = blockIdx.x * 256 + threadIdx.x;
    if (i >= n4) return;
    float4 v = ((const float4*)in)[i];
    bf16 h0, h1, h2, h3, l0, l1, l2, l3;
    split2(v.x, h0, l0); split2(v.y, h1, l1);
    split2(v.z, h2, l2); split2(v.w, h3, l3);
    ((__nv_bfloat162*)hi)[2*i]   = __halves2bfloat162(h0, h1);
    ((__nv_bfloat162*)hi)[2*i+1] = __halves2bfloat162(h2, h3);
    ((__nv_bfloat162*)lo)[2*i]   = __halves2bfloat162(l0, l1);
    ((__nv_bfloat162*)lo)[2*i+1] = __halves2bfloat162(l2, l3);
}

// ============================================================
// W [K=1024, N=1024] -> W^T [N,K] with bf16 hi/lo split
// ============================================================
__global__ void tsplit_kernel(const float* __restrict__ W,
    bf16* __restrict__ Thi, bf16* __restrict__ Tlo)
{
    __shared__ float t[32][33];
    int bx = blockIdx.x * 32, by = blockIdx.y * 32;
    int tx = threadIdx.x, ty = threadIdx.y;   // 32 x 8
#pragma unroll
    for (int i = 0; i < 32; i += 8)
        t[ty + i][tx] = W[(size_t)(by + ty + i) * Dc + bx + tx];
    __syncthreads();
#pragma unroll
    for (int i = 0; i < 32; i += 8) {
        float v = t[tx][ty + i];
        int orow = bx + ty + i, ocol = by + tx;
        bf16 h, l; split2(v, h, l);
        Thi[(size_t)orow * Dc + ocol] = h;
        Tlo[(size_t)orow * Dc + ocol] = l;
    }
}

// ============================================================
// v [b*L][D] fp32 -> v_t [bh][d][l] bf16 hi/lo (per-head transpose + split)
// ============================================================
__global__ __launch_bounds__(256) void vt_kernel(
    const float* __restrict__ v, bf16* __restrict__ Thi, bf16* __restrict__ Tlo)
{
    __shared__ float t[64][33];
    const int bh = blockIdx.y;
    const int b = bh >> 4, h = bh & 15;
    const int l0 = blockIdx.x * 32;
    const int tid = threadIdx.x;
#pragma unroll
    for (int i = 0; i < 8; i++) {
        int s = tid + i * 256;
        int r = s >> 6, c = s & 63;    // r = l, c = d
        t[c][r & 31] = v[(size_t)(b * Lc + l0 + r) * Dc + h * DHc + c];
    }
    __syncthreads();
#pragma unroll
    for (int i = 0; i < 8; i++) {
        int s = tid + i * 256;
        int d = s >> 5, c = s & 31;    // d row, c = l
        float val = t[d][c];
        bf16 hh, ll; split2(val, hh, ll);
        size_t o = ((size_t)bh * DHc + d) * Lc + l0 + c;
        Thi[o] = hh; Tlo[o] = ll;
    }
}

// ============================================================
// bf16x3 tensor-core GEMM, 3-stage cp.async pipeline, 1 sync/iter.
// MODE 0 (fused QKV), MODE 1 (single + exact GELU). 2 CTAs/SM forced.
// ============================================================
#define LDT 40
#define GNIT 96
#define GEMM_STG (128 * LDT * 2)
#define GEMM_SMEM3 (3 * 2 * GEMM_STG)     // 61440 B

template<int MODE>
__global__ __launch_bounds__(256, 2) void mma_gemm_kernel(
    const bf16* __restrict__ Ahi, const bf16* __restrict__ Alo,
    const bf16* __restrict__ Bhi, const bf16* __restrict__ Blo,
    float* __restrict__ Cv,
    bf16* __restrict__ Qhi, bf16* __restrict__ Qlo,
    bf16* __restrict__ Khi, bf16* __restrict__ Klo,
    float qalpha)
{
    extern __shared__ char gsm[];
    const int tid  = threadIdx.x;
    const int lane = tid & 31, wid = tid >> 5;
    const int bm = blockIdx.y * 128;
    const int bn = blockIdx.x * 128;
    const int wm = (wid >> 2) * 64;
    const int wn = (wid & 3) * 32;

    uint32_t as_b[3], bs_b[3];
#pragma unroll
    for (int s = 0; s < 3; s++) {
        as_b[s] = smem_u32(gsm + s * 2 * GEMM_STG);
        bs_b[s] = as_b[s] + GEMM_STG;
    }

    const int a_row = wm + (lane & 15);
    const int a_col = (lane >> 4) << 3;
    const int b_row = wn + (lane & 7) + ((lane >> 4) << 3);
    const int b_col = ((lane >> 3) & 1) << 3;

    const int g_row0 = tid >> 2;
    const int g_c8   = (tid & 3) << 3;

    auto stage = [&](int kt) {
        const int s  = kt % 3;
        const int p  = kt >> 5;
        const int kk = (kt & 31) << 5;
        const bf16* Ag = (p < 2) ? Ahi : Alo;
        const bf16* Bg = (p == 1) ? Blo : Bhi;
#pragma unroll
        for (int i = 0; i < 2; i++) {
            int row = g_row0 + i * 64;
            uint32_t soff = (uint32_t)(row * LDT + g_c8) * 2;
            cp_async16(as_b[s] + soff, Ag + (size_t)(bm + row) * Dc + kk + g_c8);
            cp_async16(bs_b[s] + soff, Bg + (size_t)(bn + row) * Dc + kk + g_c8);
        }
        CP_COMMIT();
    };

    float acc[4][4][4];
#pragma unroll
    for (int mi = 0; mi < 4; mi++)
#pragma unroll
        for (int ni = 0; ni < 4; ni++)
#pragma unroll
            for (int e = 0; e < 4; e++) acc[mi][ni][e] = 0.f;

    stage(0); stage(1);

    for (int kt = 0; kt < GNIT; kt++) {
        const int s = kt % 3;
        if (kt + 1 < GNIT) CP_WAIT(1); else CP_WAIT(0);
        __syncthreads();
        if (kt + 2 < GNIT) stage(kt + 2);

#pragma unroll
        for (int k0 = 0; k0 < 32; k0 += 16) {
            uint32_t a[4][4];
#pragma unroll
            for (int mi = 0; mi < 4; mi++)
                ldsm_x4(a[mi], as_b[s] +
                        (uint32_t)((a_row + mi * 16) * LDT + k0 + a_col) * 2);
            uint32_t b[2][4];
#pragma unroll
            for (int pr = 0; pr < 2; pr++)
                ldsm_x4(b[pr], bs_b[s] +
                        (uint32_t)((b_row + pr * 16) * LDT + k0 + b_col) * 2);
#pragma unroll
            for (int mi = 0; mi < 4; mi++) {
                mma16816(acc[mi][0], a[mi], b[0][0], b[0][1]);
                mma16816(acc[mi][1], a[mi], b[0][2], b[0][3]);
                mma16816(acc[mi][2], a[mi], b[1][0], b[1][1]);
                mma16816(acc[mi][3], a[mi], b[1][2], b[1][3]);
            }
        }
    }

    const int orow = bm + wm + (lane >> 2);
    const int occ0 = wn + ((lane & 3) << 1);

    if (MODE == 0) {
        const int which = bn >> 10;        // 0 q, 1 k, 2 v
        const int bnl = bn & 1023;
        if (which < 2) {
            bf16* Oh = which ? Khi : Qhi;
            bf16* Ol = which ? Klo : Qlo;
#pragma unroll
            for (int mi = 0; mi < 4; mi++)
#pragma unroll
                for (int ni = 0; ni < 4; ni++) {
                    const size_t i0 = (size_t)(orow + mi * 16) * Dc + bnl + occ0 + ni * 8;
                    const size_t i1 = (size_t)(orow + mi * 16 + 8) * Dc + bnl + occ0 + ni * 8;
                    bf16 h0,l0,h1,l1,h2,l2,h3,l3;
                    split2(acc[mi][ni][0] * qalpha, h0, l0);
                    split2(acc[mi][ni][1] * qalpha, h1, l1);
                    split2(acc[mi][ni][2] * qalpha, h2, l2);
                    split2(acc[mi][ni][3] * qalpha, h3, l3);
                    *(__nv_bfloat162*)&Oh[i0] = __halves2bfloat162(h0, h1);
                    *(__nv_bfloat162*)&Oh[i1] = __halves2bfloat162(h2, h3);
                    *(__nv_bfloat162*)&Ol[i0] = __halves2bfloat162(l0, l1);
                    *(__nv_bfloat162*)&Ol[i1] = __halves2bfloat162(l2, l3);
                }
        } else {
#pragma unroll
            for (int mi = 0; mi < 4; mi++)
#pragma unroll
                for (int ni = 0; ni < 4; ni++) {
                    const size_t i0 = (size_t)(orow + mi * 16) * Dc + bnl + occ0 + ni * 8;
                    const size_t i1 = (size_t)(orow + mi * 16 + 8) * Dc + bnl + occ0 + ni * 8;
                    *(float2*)&Cv[i0] = make_float2(acc[mi][ni][0], acc[mi][ni][1]);
                    *(float2*)&Cv[i1] = make_float2(acc[mi][ni][2], acc[mi][ni][3]);
                }
        }
    } else {
#pragma unroll
        for (int mi = 0; mi < 4; mi++)
#pragma unroll
            for (int ni = 0; ni < 4; ni++) {
                float v0 = acc[mi][ni][0], v1 = acc[mi][ni][1];
                float v2 = acc[mi][ni][2], v3 = acc[mi][ni][3];
                v0 = 0.5f * v0 * (1.f + erff(v0 * 0.70710678118654752f));
                v1 = 0.5f * v1 * (1.f + erff(v1 * 0.70710678118654752f));
                v2 = 0.5f * v2 * (1.f + erff(v2 * 0.70710678118654752f));
                v3 = 0.5f * v3 * (1.f + erff(v3 * 0.70710678118654752f));
                const size_t i0 = (size_t)(orow + mi * 16) * Dc + bn + occ0 + ni * 8;
                const size_t i1 = (size_t)(orow + mi * 16 + 8) * Dc + bn + occ0 + ni * 8;
                *(float2*)&Cv[i0] = make_float2(v0, v1);
                *(float2*)&Cv[i1] = make_float2(v2, v3);
            }
    }
}

// ============================================================
// FAVOR+ feature via mma.sync bf16x3.
// OMODE 1: F bf16 hi/lo, standard layout [bh][l][m]  (Q path)
// OMODE 2: F bf16 hi/lo, TRANSPOSED [bh][m][l] + ksum atomics (K path)
// ============================================================
#define FLDK 72
#define FEAT2_SMEM ((128 + 128 + 256 + 256) * FLDK * 2 + 128 * 4 + 4 * 128 * 4 + 256 * 4)

template<int OMODE>
__global__ __launch_bounds__(256) void feature_mma_kernel(
    const bf16* __restrict__ Uhi, const bf16* __restrict__ Ulo,
    const bf16* __restrict__ Phi, const bf16* __restrict__ Plo,
    bf16* __restrict__ Fhi, bf16* __restrict__ Flo,
    float* __restrict__ ksum)
{
    extern __shared__ char fsm[];
    bf16* us_h = (bf16*)fsm;                    // [128][FLDK]
    bf16* us_l = us_h + 128 * FLDK;
    bf16* ps_h = us_l + 128 * FLDK;             // [256][FLDK]
    bf16* ps_l = ps_h + 256 * FLDK;
    float* diag   = (float*)(ps_l + 256 * FLDK); // [128]
    float* rmaxp  = diag + 128;                  // [4][128]
    float* colsum = rmaxp + 4 * 128;             // [256]

    const int bh = blockIdx.y;
    const int b = bh >> 4, h = bh & 15;
    const int l0 = blockIdx.x * 128;
    const int tid = threadIdx.x;
    const int lane = tid & 31, wid = tid >> 5;

#pragma unroll
    for (int i = 0; i < 4; i++) {
        int s = tid + i * 256;
        int r = s >> 3, c8 = (s & 7) << 3;
        size_t gi = (size_t)(b * Lc + l0 + r) * Dc + h * DHc + c8;
        *(uint4*)&us_h[r * FLDK + c8] = *(const uint4*)&Uhi[gi];
        *(uint4*)&us_l[r * FLDK + c8] = *(const uint4*)&Ulo[gi];
    }
#pragma unroll
    for (int i = 0; i < 8; i++) {
        int s = tid + i * 256;
        int r = s >> 3, c8 = (s & 7) << 3;
        size_t gi = (size_t)(h * Mc + r) * DHc + c8;
        *(uint4*)&ps_h[r * FLDK + c8] = *(const uint4*)&Phi[gi];
        *(uint4*)&ps_l[r * FLDK + c8] = *(const uint4*)&Plo[gi];
    }
    __syncthreads();

    if (tid < 128) {
        float s = 0.f;
#pragma unroll
        for (int d2 = 0; d2 < 32; d2++) {
            __nv_bfloat162 hh = *(__nv_bfloat162*)&us_h[tid * FLDK + d2 * 2];
            __nv_bfloat162 ll = *(__nv_bfloat162*)&us_l[tid * FLDK + d2 * 2];
            float u0 = __bfloat162float(hh.x) + __bfloat162float(ll.x);
            float u1 = __bfloat162float(hh.y) + __bfloat162float(ll.y);
            s += u0 * u0 + u1 * u1;
        }
        diag[tid] = 0.5f * s;
    }

    const int wm = (wid >> 2) * 64;
    const int wn = (wid & 3) * 64;
    const int a_row = wm + (lane & 15);
    const int a_col = (lane >> 4) << 3;
    const int b_row = wn + (lane & 7) + ((lane >> 4) << 3);
    const int b_col = ((lane >> 3) & 1) << 3;

    float acc[4][8][4];
#pragma unroll
    for (int mi = 0; mi < 4; mi++)
#pragma unroll
        for (int ni = 0; ni < 8; ni++)
#pragma unroll
            for (int e = 0; e < 4; e++) acc[mi][ni][e] = 0.f;

    const uint32_t ush = smem_u32(us_h), usl = smem_u32(us_l);
    const uint32_t psh = smem_u32(ps_h), psl = smem_u32(ps_l);
    __syncthreads();

#pragma unroll
    for (int p = 0; p < 3; p++) {
        const uint32_t ab = (p < 2) ? ush : usl;
        const uint32_t bb = (p == 1) ? psl : psh;
#pragma unroll
        for (int k0 = 0; k0 < 64; k0 += 16) {
            uint32_t a[4][4], bfr[4][4];
#pragma unroll
            for (int mi = 0; mi < 4; mi++)
                ldsm_x4(a[mi], ab + (uint32_t)((a_row + mi * 16) * FLDK + k0 + a_col) * 2);
#pragma unroll
            for (int pr = 0; pr < 4; pr++)
                ldsm_x4(bfr[pr], bb + (uint32_t)((b_row + pr * 16) * FLDK + k0 + b_col) * 2);
#pragma unroll
            for (int mi = 0; mi < 4; mi++)
#pragma unroll
                for (int pr = 0; pr < 4; pr++) {
                    mma16816(acc[mi][2 * pr],     a[mi], bfr[pr][0], bfr[pr][1]);
                    mma16816(acc[mi][2 * pr + 1], a[mi], bfr[pr][2], bfr[pr][3]);
                }
        }
    }

    float tmax[4][2];
#pragma unroll
    for (int mi = 0; mi < 4; mi++) {
        float m0 = -1e30f, m1 = -1e30f;
#pragma unroll
        for (int ni = 0; ni < 8; ni++) {
            m0 = fmaxf(m0, fmaxf(acc[mi][ni][0], acc[mi][ni][1]));
            m1 = fmaxf(m1, fmaxf(acc[mi][ni][2], acc[mi][ni][3]));
        }
#pragma unroll
        for (int off = 1; off <= 2; off <<= 1) {
            m0 = fmaxf(m0, __shfl_xor_sync(0xffffffffu, m0, off));
            m1 = fmaxf(m1, __shfl_xor_sync(0xffffffffu, m1, off));
        }
        tmax[mi][0] = m0; tmax[mi][1] = m1;
    }
    if ((lane & 3) == 0) {
        const int slab = wid & 3;
#pragma unroll
        for (int mi = 0; mi < 4; mi++) {
            int r = wm + mi * 16 + (lane >> 2);
            rmaxp[slab * 128 + r]     = tmax[mi][0];
            rmaxp[slab * 128 + r + 8] = tmax[mi][1];
        }
    }
    if (OMODE == 2 && tid < 256) colsum[tid] = 0.f;
    __syncthreads();

    // per-row bases
    float base[4][2];
#pragma unroll
    for (int mi = 0; mi < 4; mi++) {
        const int r0 = wm + mi * 16 + (lane >> 2);
        const int r1 = r0 + 8;
        float rm0 = fmaxf(fmaxf(rmaxp[r0], rmaxp[128 + r0]),
                          fmaxf(rmaxp[256 + r0], rmaxp[384 + r0]));
        float rm1 = fmaxf(fmaxf(rmaxp[r1], rmaxp[128 + r1]),
                          fmaxf(rmaxp[256 + r1], rmaxp[384 + r1]));
        base[mi][0] = -diag[r0] - rm0;
        base[mi][1] = -diag[r1] - rm1;
    }

    if (OMODE == 1) {
#pragma unroll
        for (int mi = 0; mi < 4; mi++) {
            const int r0 = wm + mi * 16 + (lane >> 2);
            const size_t o0 = ((size_t)bh * Lc + l0 + r0) * Mc;
            const size_t o1 = ((size_t)bh * Lc + l0 + r0 + 8) * Mc;
            const int c0 = wn + ((lane & 3) << 1);
#pragma unroll
            for (int ni = 0; ni < 8; ni++) {
                int c = c0 + ni * 8;
                float f0 = __expf(acc[mi][ni][0] + base[mi][0]) * 0.0625f;
                float f1 = __expf(acc[mi][ni][1] + base[mi][0]) * 0.0625f;
                float f2 = __expf(acc[mi][ni][2] + base[mi][1]) * 0.0625f;
                float f3 = __expf(acc[mi][ni][3] + base[mi][1]) * 0.0625f;
                bf16 h0,l0b,h1,l1b,h2,l2b,h3,l3b;
                split2(f0, h0, l0b); split2(f1, h1, l1b);
                split2(f2, h2, l2b); split2(f3, h3, l3b);
                *(__nv_bfloat162*)&Fhi[o0 + c] = __halves2bfloat162(h0, h1);
                *(__nv_bfloat162*)&Fhi[o1 + c] = __halves2bfloat162(h2, h3);
                *(__nv_bfloat162*)&Flo[o0 + c] = __halves2bfloat162(l0b, l1b);
                *(__nv_bfloat162*)&Flo[o1 + c] = __halves2bfloat162(l2b, l3b);
            }
        }
    } else {
        // transposed store [bh][m][l] + column sums
        const int lr = lane >> 2;
#pragma unroll
        for (int ni = 0; ni < 8; ni++) {
            const int c = wn + ((lane & 3) << 1) + ni * 8;
            float s0 = 0.f, s1 = 0.f;
#pragma unroll
            for (int mi = 0; mi < 4; mi++) {
                const int r0 = wm + mi * 16 + lr;
                float f0 = __expf(acc[mi][ni][0] + base[mi][0]) * 0.0625f;
                float f1 = __expf(acc[mi][ni][1] + base[mi][0]) * 0.0625f;
                float f2 = __expf(acc[mi][ni][2] + base[mi][1]) * 0.0625f;
                float f3 = __expf(acc[mi][ni][3] + base[mi][1]) * 0.0625f;
                s0 += f0 + f2; s1 += f1 + f3;
                const size_t t0 = ((size_t)bh * Mc + c) * Lc + l0;
                const size_t t1 = t0 + Lc;
                bf16 hh, ll;
                split2(f0, hh, ll); Fhi[t0 + r0] = hh;     Flo[t0 + r0] = ll;
                split2(f2, hh, ll); Fhi[t0 + r0 + 8] = hh; Flo[t0 + r0 + 8] = ll;
                split2(f1, hh, ll); Fhi[t1 + r0] = hh;     Flo[t1 + r0] = ll;
                split2(f3, hh, ll); Fhi[t1 + r0 + 8] = hh; Flo[t1 + r0 + 8] = ll;
            }
            atomicAdd(&colsum[c], s0);
            atomicAdd(&colsum[c + 1], s1);
        }
        __syncthreads();
        if (tid < 256) atomicAdd(&ksum[bh * Mc + tid], colsum[tid]);
    }
}

// ============================================================
// kv via mma bf16x3: kvt[d][m] = sum_l v_t[d][l] * kf_t[m][l]
// grid (split=8, bh=32); CTA 64(d) x 256(m), K=512/CTA; fp32 atomic accum.
// ============================================================
#define KVNIT 48                             // 3 * (512/32)
#define KV_ASTG (64 * LDT * 2)               // 5120
#define KV_BSTG (256 * LDT * 2)              // 20480
#define KV_SMEM (3 * (KV_ASTG + KV_BSTG))    // 76800

__global__ __launch_bounds__(256, 2) void kv_mma_kernel(
    const bf16* __restrict__ vthi, const bf16* __restrict__ vtlo,
    const bf16* __restrict__ kfthi, const bf16* __restrict__ kftlo,
    float* __restrict__ kvtf)
{
    extern __shared__ char ksm[];
    const int bh = blockIdx.y;
    const int l0 = blockIdx.x * 512;
    const int tid = threadIdx.x;
    const int lane = tid & 31, wid = tid >> 5;
    const int wn = wid * 32;                 // m cols

    uint32_t as_b[3], bs_b[3];
#pragma unroll
    for (int s = 0; s < 3; s++) {
        as_b[s] = smem_u32(ksm + s * (KV_ASTG + KV_BSTG));
        bs_b[s] = as_b[s] + KV_ASTG;
    }

    const int a_row = (lane & 15);
    const int a_col = (lane >> 4) << 3;
    const int b_row = wn + (lane & 7) + ((lane >> 4) << 3);
    const int b_col = ((lane >> 3) & 1) << 3;

    const size_t abase = (size_t)bh * DHc * Lc + l0;   // v_t [64][Lc]
    const size_t bbase = (size_t)bh * Mc * Lc + l0;    // kf_t [256][Lc]

    const int ga_row = tid >> 2, ga_c8 = (tid & 3) << 3;

    auto stage = [&](int kt) {
        const int s  = kt % 3;
        const int p  = kt >> 4;
        const int kk = (kt & 15) << 5;
        const bf16* Ag = ((p < 2) ? vthi : vtlo) + abase;
        const bf16* Bg = ((p == 1) ? kftlo : kfthi) + bbase;
        // A: 64 rows x 32 cols = 256 x 16B (1/thread)
        cp_async16(as_b[s] + (uint32_t)(ga_row * LDT + ga_c8) * 2,
                   Ag + (size_t)ga_row * Lc + kk + ga_c8);
        // B: 256 rows x 32 cols = 1024 x 16B (4/thread)
#pragma unroll
        for (int i = 0; i < 4; i++) {
            int row = ga_row + i * 64;
            cp_async16(bs_b[s] + (uint32_t)(row * LDT + ga_c8) * 2,
                       Bg + (size_t)row * Lc + kk + ga_c8);
        }
        CP_COMMIT();
    };

    float acc[4][4][4];
#pragma unroll
    for (int mi = 0; mi < 4; mi++)
#pragma unroll
        for (int ni = 0; ni < 4; ni++)
#pragma unroll
            for (int e = 0; e < 4; e++) acc[mi][ni][e] = 0.f;

    stage(0); stage(1);

    for (int kt = 0; kt < KVNIT; kt++) {
        const int s = kt % 3;
        if (kt + 1 < KVNIT) CP_WAIT(1); else CP_WAIT(0);
        __syncthreads();
        if (kt + 2 < KVNIT) stage(kt + 2);

#pragma unroll
        for (int k0 = 0; k0 < 32; k0 += 16) {
            uint32_t a[4][4];
#pragma unroll
            for (int mi = 0; mi < 4; mi++)
                ldsm_x4(a[mi], as_b[s] +
                        (uint32_t)((a_row + mi * 16) * LDT + k0 + a_col) * 2);
            uint32_t bf_[2][4];
#pragma unroll
            for (int pr = 0; pr < 2; pr++)
                ldsm_x4(bf_[pr], bs_b[s] +
                        (uint32_t)((b_row + pr * 16) * LDT + k0 + b_col) * 2);
#pragma unroll
            for (int mi = 0; mi < 4; mi++) {
                mma16816(acc[mi][0], a[mi], bf_[0][0], bf_[0][1]);
                mma16816(acc[mi][1], a[mi], bf_[0][2], bf_[0][3]);
                mma16816(acc[mi][2], a[mi], bf_[1][0], bf_[1][1]);
                mma16816(acc[mi][3], a[mi], bf_[1][2], bf_[1][3]);
            }
        }
    }

    // epilogue: atomic accumulate into kvtf [bh][64 d][256 m]
    const int lr = lane >> 2;
    const int c0 = wn + ((lane & 3) << 1);
    float* dst = kvtf + (size_t)bh * DHc * Mc;
#pragma unroll
    for (int mi = 0; mi < 4; mi++) {
        const int d0 = mi * 16 + lr;
        const int d1 = d0 + 8;
#pragma unroll
        for (int ni = 0; ni < 4; ni++) {
            int c = c0 + ni * 8;
            atomicAdd(&dst[d0 * Mc + c],     acc[mi][ni][0]);
            atomicAdd(&dst[d0 * Mc + c + 1], acc[mi][ni][1]);
            atomicAdd(&dst[d1 * Mc + c],     acc[mi][ni][2]);
            atomicAdd(&dst[d1 * Mc + c + 1], acc[mi][ni][3]);
        }
    }
}

// ============================================================
// kvtf fp32 [bh][64][256] -> kvthi/kvtlo (plain split)
// ============================================================
__global__ __launch_bounds__(256) void kvsplit_kernel(
    const float* __restrict__ kvtf, bf16* __restrict__ Thi, bf16* __restrict__ Tlo)
{
    int i = blockIdx.x * 256 + threadIdx.x;
    float v = kvtf[i];
    bf16 h, l; split2(v, h, l);
    Thi[i] = h; Tlo[i] = l;
}

// ============================================================
// z[bh,l] = 1 / (dot(qf_hi+qf_lo, ksum) + 1e-6)
// ============================================================
__global__ __launch_bounds__(256) void z_kernel(
    const bf16* __restrict__ qfhi, const bf16* __restrict__ qflo,
    const float* __restrict__ ksum, float* __restrict__ z)
{
    __shared__ float ks[256];
    const int bh = blockIdx.y;
    ks[threadIdx.x] = ksum[bh * Mc + threadIdx.x];
    __syncthreads();
    const int w = threadIdx.x >> 5, lane = threadIdx.x & 31;
    const int l = blockIdx.x * 8 + w;
    const size_t base = ((size_t)bh * Lc + l) * Mc;
    float s = 0.f;
#pragma unroll
    for (int q8 = 0; q8 < 8; q8++) {
        int c = lane + q8 * 32;
        s += (__bfloat162float(qfhi[base + c]) + __bfloat162float(qflo[base + c])) * ks[c];
    }
#pragma unroll
    for (int off = 16; off; off >>= 1) s += __shfl_xor_sync(0xffffffffu, s, off);
    if (lane == 0) z[bh * Lc + l] = 1.0f / (s + 1e-6f);
}

// ============================================================
// attn via mma bf16x3, hi/lo z-scaled output (feeds O GEMM directly)
// ============================================================
#define ANIT 24                           // 3 passes * (256/32)
#define ATT_ASTG (256 * LDT * 2)          // 20480 B
#define ATT_BSTG (64 * LDT * 2)           // 5120 B
#define ATT_SMEM (3 * (ATT_ASTG + ATT_BSTG))   // 76800 B

__global__ __launch_bounds__(256, 2) void attn_mma_kernel(
    const bf16* __restrict__ qfhi, const bf16* __restrict__ qflo,
    const bf16* __restrict__ kvthi, const bf16* __restrict__ kvtlo,
    const float* __restrict__ z,
    bf16* __restrict__ Ohi, bf16* __restrict__ Olo)
{
    extern __shared__ char asm_[];
    const int bh = blockIdx.y;
    const int b = bh >> 4, h = bh & 15;
    const int l0 = blockIdx.x * 256;
    const int tid = threadIdx.x;
    const int lane = tid & 31, wid = tid >> 5;
    const int wm = (wid >> 1) * 64;
    const int wn = (wid & 1) * 32;

    uint32_t as_b[3], bs_b[3];
#pragma unroll
    for (int s = 0; s < 3; s++) {
        as_b[s] = smem_u32(asm_ + s * (ATT_ASTG + ATT_BSTG));
        bs_b[s] = as_b[s] + ATT_ASTG;
    }

    const int a_row = wm + (lane & 15);
    const int a_col = (lane >> 4) << 3;
    const int b_row = wn + (lane & 7) + ((lane >> 4) << 3);
    const int b_col = ((lane >> 3) & 1) << 3;

    const size_t qbase = ((size_t)bh * Lc + l0) * Mc;
    const size_t kbase = (size_t)bh * DHc * Mc;

    const int ga_row0 = tid >> 2, ga_c8 = (tid & 3) << 3;
    const int gb_row = tid >> 2, gb_c8 = (tid & 3) << 3;

    auto stage = [&](int kt) {
        const int s  = kt % 3;
        const int p  = kt >> 3;
        const int kk = (kt & 7) << 5;
        const bf16* Ag = ((p < 2) ? qfhi : qflo) + qbase;
        const bf16* Bg = ((p == 1) ? kvtlo : kvthi) + kbase;
#pragma unroll
        for (int i = 0; i < 4; i++) {
            int row = ga_row0 + i * 64;
            cp_async16(as_b[s] + (uint32_t)(row * LDT + ga_c8) * 2,
                       Ag + (size_t)row * Mc + kk + ga_c8);
        }
        cp_async16(bs_b[s] + (uint32_t)(gb_row * LDT + gb_c8) * 2,
                   Bg + (size_t)gb_row * Mc + kk + gb_c8);
        CP_COMMIT();
    };

    float acc[4][4][4];
#pragma unroll
    for (int mi = 0; mi < 4; mi++)
#pragma unroll
        for (int ni = 0; ni < 4; ni++)
#pragma unroll
            for (int e = 0; e < 4; e++) acc[mi][ni][e] = 0.f;

    stage(0); stage(1);

    for (int kt = 0; kt < ANIT; kt++) {
        const int s = kt % 3;
        if (kt + 1 < ANIT) CP_WAIT(1); else CP_WAIT(0);
        __syncthreads();
        if (kt + 2 < ANIT) stage(kt + 2);

#pragma unroll
        for (int k0 = 0; k0 < 32; k0 += 16) {
            uint32_t a[4][4];
#pragma unroll
            for (int mi = 0; mi < 4; mi++)
                ldsm_x4(a[mi], as_b[s] +
                        (uint32_t)((a_row + mi * 16) * LDT + k0 + a_col) * 2);
            uint32_t bf_[2][4];
#pragma unroll
            for (int pr = 0; pr < 2; pr++)
                ldsm_x4(bf_[pr], bs_b[s] +
                        (uint32_t)((b_row + pr * 16) * LDT + k0 + b_col) * 2);
#pragma unroll
            for (int mi = 0; mi < 4; mi++) {
                mma16816(acc[mi][0], a[mi], bf_[0][0], bf_[0][1]);
                mma16816(acc[mi][1], a[mi], bf_[0][2], bf_[0][3]);
                mma16816(acc[mi][2], a[mi], bf_[1][0], bf_[1][1]);
                mma16816(acc[mi][3], a[mi], bf_[1][2], bf_[1][3]);
            }
        }
    }

    const int lr = lane >> 2;
    const int occ0 = wn + ((lane & 3) << 1);
#pragma unroll
    for (int mi = 0; mi < 4; mi++) {
        const int r0 = wm + mi * 16 + lr;
        const int r1 = r0 + 8;
        const float z0 = z[(size_t)bh * Lc + l0 + r0];
        const float z1 = z[(size_t)bh * Lc + l0 + r1];
        const size_t i0 = (size_t)(b * Lc + l0 + r0) * Dc + h * DHc;
        const size_t i1 = (size_t)(b * Lc + l0 + r1) * Dc + h * DHc;
#pragma unroll
        for (int ni = 0; ni < 4; ni++) {
            int c = occ0 + ni * 8;
            bf16 h0,l0b,h1,l1b,h2,l2b,h3,l3b;
            split2(acc[mi][ni][0] * z0, h0, l0b);
            split2(acc[mi][ni][1] * z0, h1, l1b);
            split2(acc[mi][ni][2] * z1, h2, l2b);
            split2(acc[mi][ni][3] * z1, h3, l3b);
            *(__nv_bfloat162*)&Ohi[i0 + c] = __halves2bfloat162(h0, h1);
            *(__nv_bfloat162*)&Ohi[i1 + c] = __halves2bfloat162(h2, h3);
            *(__nv_bfloat162*)&Olo[i0 + c] = __halves2bfloat162(l0b, l1b);
            *(__nv_bfloat162*)&Olo[i1 + c] = __halves2bfloat162(l2b, l3b);
        }
    }
}

// ============================================================
// LayerNorm + duplicate rows
// ============================================================
__global__ __launch_bounds__(256) void ln_dup_kernel(
    const float* __restrict__ y, const float* __restrict__ g,
    const float* __restrict__ beta, float* __restrict__ out)
{
    __shared__ float red[18];
    const int row = blockIdx.x;
    const int b = row >> 12, l = row & 4095;
    const int tid = threadIdx.x;
    const float* yr = y + (size_t)row * Dc;

    float v[4];
    float s = 0.f, ss = 0.f;
#pragma unroll
    for (int i = 0; i < 4; i++) {
        float t = yr[tid + i * 256];
        v[i] = t; s += t; ss += t * t;
    }
#pragma unroll
    for (int off = 16; off; off >>= 1) {
        s  += __shfl_xor_sync(0xffffffffu, s, off);
        ss += __shfl_xor_sync(0xffffffffu, ss, off);
    }
    const int w = tid >> 5, lane = tid & 31;
    if (lane == 0) { red[w] = s; red[8 + w] = ss; }
    __syncthreads();
    if (tid == 0) {
        float ts = 0.f, tss = 0.f;
#pragma unroll
        for (int i = 0; i < 8; i++) { ts += red[i]; tss += red[8 + i]; }
        float mean = ts * (1.0f / 1024.0f);
        float var = tss * (1.0f / 1024.0f) - mean * mean;
        red[16] = mean;
        red[17] = rsqrtf(var + 1e-5f);
    }
    __syncthreads();
    const float mean = red[16], rstd = red[17];
    float* o0 = out + ((size_t)b * 8192 + 2 * (size_t)l) * Dc;
#pragma unroll
    for (int i = 0; i < 4; i++) {
        int c = tid + i * 256;
        float o = (v[i] - mean) * rstd * g[c] + beta[c];
        o0[c] = o;
        o0[Dc + c] = o;
    }
}

// ============================================================
// host launch
// ============================================================
extern "C" void kernel_launch(void* const* d_in, const int* in_sizes, int n_in,
                              void* d_out, int out_size)
{
    const float* x    = (const float*)d_in[0];
    const float* Wq   = (const float*)d_in[1];
    const float* Wk   = (const float*)d_in[2];
    const float* Wv   = (const float*)d_in[3];
    const float* Wo   = (const float*)d_in[4];
    const float* proj = (const float*)d_in[5];
    const float* ln_g = (const float*)d_in[6];
    const float* ln_b = (const float*)d_in[7];
    float* out = (float*)d_out;

    float *v, *kvtf, *ksum, *z, *y;
    bf16 *qfhi, *qflo, *kfthi, *kftlo, *vthi, *vtlo, *kvthi, *kvtlo;
    bf16 *ahi, *alo, *bthi, *btlo, *qhi, *qlo, *khi, *klo, *phi, *plo;
    cudaGetSymbolAddress((void**)&v,     g_v);
    cudaGetSymbolAddress((void**)&qfhi,  g_qfhi);
    cudaGetSymbolAddress((void**)&qflo,  g_qflo);
    cudaGetSymbolAddress((void**)&kfthi, g_kfthi);
    cudaGetSymbolAddress((void**)&kftlo, g_kftlo);
    cudaGetSymbolAddress((void**)&vthi,  g_vthi);
    cudaGetSymbolAddress((void**)&vtlo,  g_vtlo);
    cudaGetSymbolAddress((void**)&kvtf,  g_kvtf);
    cudaGetSymbolAddress((void**)&kvthi, g_kvthi);
    cudaGetSymbolAddress((void**)&kvtlo, g_kvtlo);
    cudaGetSymbolAddress((void**)&ksum,  g_ksum);
    cudaGetSymbolAddress((void**)&z,     g_z);
    cudaGetSymbolAddress((void**)&y,     g_y);
    cudaGetSymbolAddress((void**)&ahi,   g_ahi);
    cudaGetSymbolAddress((void**)&alo,   g_alo);
    cudaGetSymbolAddress((void**)&bthi,  g_bthi);
    cudaGetSymbolAddress((void**)&btlo,  g_btlo);
    cudaGetSymbolAddress((void**)&qhi,   g_qhi);
    cudaGetSymbolAddress((void**)&qlo,   g_qlo);
    cudaGetSymbolAddress((void**)&khi,   g_khi);
    cudaGetSymbolAddress((void**)&klo,   g_klo);
    cudaGetSymbolAddress((void**)&phi,   g_phi);
    cudaGetSymbolAddress((void**)&plo,   g_plo);

    const float qscale = 0.35355339059327379f;  // 64^-0.25

    cudaFuncSetAttribute(mma_gemm_kernel<0>,
                         cudaFuncAttributeMaxDynamicSharedMemorySize, GEMM_SMEM3);
    cudaFuncSetAttribute(mma_gemm_kernel<1>,
                         cudaFuncAttributeMaxDynamicSharedMemorySize, GEMM_SMEM3);
    cudaFuncSetAttribute(feature_mma_kernel<1>,
                         cudaFuncAttributeMaxDynamicSharedMemorySize, FEAT2_SMEM);
    cudaFuncSetAttribute(feature_mma_kernel<2>,
                         cudaFuncAttributeMaxDynamicSharedMemorySize, FEAT2_SMEM);
    cudaFuncSetAttribute(kv_mma_kernel,
                         cudaFuncAttributeMaxDynamicSharedMemorySize, KV_SMEM);
    cudaFuncSetAttribute(attn_mma_kernel,
                         cudaFuncAttributeMaxDynamicSharedMemorySize, ATT_SMEM);

    const int n4 = ROWS * Dc / 4;
    dim3 tgrid(32, 32), tblk(32, 8);

    // splits
    split_kernel<<<n4 / 256, 256>>>(x, ahi, alo, n4);
    split_kernel<<<(Hc * Mc * DHc / 4) / 256, 256>>>(proj, phi, plo, Hc * Mc * DHc / 4);
    tsplit_kernel<<<tgrid, tblk>>>(Wq, bthi,                   btlo);
    tsplit_kernel<<<tgrid, tblk>>>(Wk, bthi + (size_t)Dc*Dc,   btlo + (size_t)Dc*Dc);
    tsplit_kernel<<<tgrid, tblk>>>(Wv, bthi + (size_t)2*Dc*Dc, btlo + (size_t)2*Dc*Dc);

    // zero accumulators (consumed by feature<2> and kv_mma)
    cudaMemsetAsync(ksum, 0, (size_t)BHc * Mc * sizeof(float), 0);
    cudaMemsetAsync(kvtf, 0, (size_t)BHc * DHc * Mc * sizeof(float), 0);

    // fused QKV GEMM
    mma_gemm_kernel<0><<<dim3(24, 64), 256, GEMM_SMEM3>>>(
        ahi, alo, bthi, btlo, v, qhi, qlo, khi, klo, qscale);

    // features: Q -> qf hi/lo [l][m]; K -> kf_t hi/lo [m][l] + ksum
    feature_mma_kernel<1><<<dim3(Lc / 128, BHc), 256, FEAT2_SMEM>>>(
        qhi, qlo, phi, plo, qfhi, qflo, nullptr);
    feature_mma_kernel<2><<<dim3(Lc / 128, BHc), 256, FEAT2_SMEM>>>(
        khi, klo, phi, plo, kfthi, kftlo, ksum);

    // v transpose+split, then kv via tensor cores
    vt_kernel<<<dim3(Lc / 32, BHc), 256>>>(v, vthi, vtlo);
    kv_mma_kernel<<<dim3(8, BHc), 256, KV_SMEM>>>(vthi, vtlo, kfthi, kftlo, kvtf);
    kvsplit_kernel<<<(BHc * DHc * Mc) / 256, 256>>>(kvtf, kvthi, kvtlo);

    z_kernel<<<dim3(Lc / 8, BHc), 256>>>(qfhi, qflo, ksum, z);

    // attn -> hi/lo directly into O-GEMM A buffers
    attn_mma_kernel<<<dim3(Lc / 256, BHc), 256, ATT_SMEM>>>(
        qfhi, qflo, kvthi, kvtlo, z, ahi, alo);

    // O projection + exact GELU
    tsplit_kernel<<<tgrid, tblk>>>(Wo, bthi, btlo);
    mma_gemm_kernel<1><<<dim3(8, 64), 256, GEMM_SMEM3>>>(
        ahi, alo, bthi, btlo, y, nullptr, nullptr, nullptr, nullptr, 1.0f);

    ln_dup_kernel<<<ROWS, 256>>>(y, ln_g, ln_b, out);
}

// round 9
// speedup vs baseline: 1.2258x; 1.0943x over previous
#include <cuda_runtime.h>
#include <cuda_bf16.h>
#include <math.h>
#include <stdint.h>

// Shapes (fixed)
#define Bc   2
#define Lc   4096
#define Dc   1024
#define Hc   16
#define DHc  64
#define Mc   256
#define BHc  32
#define ROWS 8192   // B*L

typedef __nv_bfloat16 bf16;

// -------- scratch (device globals; no allocations allowed) --------
__device__ float g_v    [(size_t)ROWS * Dc];
__device__ bf16  g_qfhi [(size_t)BHc * Lc * Mc];
__device__ bf16  g_qflo [(size_t)BHc * Lc * Mc];
__device__ bf16  g_kfthi[(size_t)BHc * Mc * Lc];
__device__ bf16  g_kftlo[(size_t)BHc * Mc * Lc];
__device__ bf16  g_vthi [(size_t)BHc * DHc * Lc];
__device__ bf16  g_vtlo [(size_t)BHc * DHc * Lc];
__device__ float g_kvtf [(size_t)BHc * DHc * Mc];
__device__ bf16  g_kvthi[(size_t)BHc * DHc * Mc];
__device__ bf16  g_kvtlo[(size_t)BHc * DHc * Mc];
__device__ float g_ksum [(size_t)BHc * Mc];
__device__ float g_z    [(size_t)BHc * Lc];
__device__ float g_y    [(size_t)ROWS * Dc];
__device__ bf16  g_ahi  [(size_t)ROWS * Dc];
__device__ bf16  g_alo  [(size_t)ROWS * Dc];
__device__ bf16  g_bthi [(size_t)3 * Dc * Dc];
__device__ bf16  g_btlo [(size_t)3 * Dc * Dc];
__device__ bf16  g_qhi  [(size_t)ROWS * Dc];
__device__ bf16  g_qlo  [(size_t)ROWS * Dc];
__device__ bf16  g_khi  [(size_t)ROWS * Dc];
__device__ bf16  g_klo  [(size_t)ROWS * Dc];
__device__ bf16  g_phi  [(size_t)Hc * Mc * DHc];
__device__ bf16  g_plo  [(size_t)Hc * Mc * DHc];

// ================= baseline-PTX tensor-core helpers (sm_80+) ==========
__device__ __forceinline__ uint32_t smem_u32(const void* p) {
    uint32_t a;
    asm("{ .reg .u64 t; cvta.to.shared.u64 t, %1; cvt.u32.u64 %0, t; }"
        : "=r"(a) : "l"(p));
    return a;
}
__device__ __forceinline__ void cp_async16(uint32_t saddr, const void* g) {
    asm volatile("cp.async.cg.shared.global [%0], [%1], 16;"
                 :: "r"(saddr), "l"(g) : "memory");
}
#define CP_COMMIT() asm volatile("cp.async.commit_group;" ::: "memory")
#define CP_WAIT(n)  asm volatile("cp.async.wait_group %0;" :: "n"(n) : "memory")

__device__ __forceinline__ void ldsm_x4(uint32_t r[4], uint32_t addr) {
    asm volatile("ldmatrix.sync.aligned.m8n8.x4.shared.b16 {%0,%1,%2,%3}, [%4];"
                 : "=r"(r[0]), "=r"(r[1]), "=r"(r[2]), "=r"(r[3]) : "r"(addr));
}
__device__ __forceinline__ void mma16816(float c[4], const uint32_t a[4],
                                         uint32_t b0, uint32_t b1) {
    asm volatile(
        "mma.sync.aligned.m16n8k16.row.col.f32.bf16.bf16.f32 "
        "{%0,%1,%2,%3}, {%4,%5,%6,%7}, {%8,%9}, {%0,%1,%2,%3};"
        : "+f"(c[0]), "+f"(c[1]), "+f"(c[2]), "+f"(c[3])
        : "r"(a[0]), "r"(a[1]), "r"(a[2]), "r"(a[3]), "r"(b0), "r"(b1));
}
__device__ __forceinline__ void split2(float v, bf16& h, bf16& l) {
    h = __float2bfloat16_rn(v);
    l = __float2bfloat16_rn(v - __bfloat162float(h));
}

// ============================================================
// fp32 -> (hi, lo) bf16 split
// ============================================================
__global__ __launch_bounds__(256) void split_kernel(
    const float* __restrict__ in, bf16* __restrict__ hi,
    bf16* __restrict__ lo, int n4)
{
    int i = blockIdx.x * 256 + threadIdx.x;
    if (i >= n4) return;
    float4 v = ((const float4*)in)[i];
    bf16 h0, h1, h2, h3, l0, l1, l2, l3;
    split2(v.x, h0, l0); split2(v.y, h1, l1);
    split2(v.z, h2, l2); split2(v.w, h3, l3);
    ((__nv_bfloat162*)hi)[2*i]   = __halves2bfloat162(h0, h1);
    ((__nv_bfloat162*)hi)[2*i+1] = __halves2bfloat162(h2, h3);
    ((__nv_bfloat162*)lo)[2*i]   = __halves2bfloat162(l0, l1);
    ((__nv_bfloat162*)lo)[2*i+1] = __halves2bfloat162(l2, l3);
}

// ============================================================
// W [K=1024, N=1024] -> W^T [N,K] with bf16 hi/lo split
// ============================================================
__global__ void tsplit_kernel(const float* __restrict__ W,
    bf16* __restrict__ Thi, bf16* __restrict__ Tlo)
{
    __shared__ float t[32][33];
    int bx = blockIdx.x * 32, by = blockIdx.y * 32;
    int tx = threadIdx.x, ty = threadIdx.y;   // 32 x 8
#pragma unroll
    for (int i = 0; i < 32; i += 8)
        t[ty + i][tx] = W[(size_t)(by + ty + i) * Dc + bx + tx];
    __syncthreads();
#pragma unroll
    for (int i = 0; i < 32; i += 8) {
        float v = t[tx][ty + i];
        int orow = bx + ty + i, ocol = by + tx;
        bf16 h, l; split2(v, h, l);
        Thi[(size_t)orow * Dc + ocol] = h;
        Tlo[(size_t)orow * Dc + ocol] = l;
    }
}

// ============================================================
// v [b*L][D] fp32 -> v_t [bh][d][l] bf16 hi/lo
// ============================================================
__global__ __launch_bounds__(256) void vt_kernel(
    const float* __restrict__ v, bf16* __restrict__ Thi, bf16* __restrict__ Tlo)
{
    __shared__ float t[64][33];
    const int bh = blockIdx.y;
    const int b = bh >> 4, h = bh & 15;
    const int l0 = blockIdx.x * 32;
    const int tid = threadIdx.x;
#pragma unroll
    for (int i = 0; i < 8; i++) {
        int s = tid + i * 256;
        int r = s >> 6, c = s & 63;
        t[c][r & 31] = v[(size_t)(b * Lc + l0 + r) * Dc + h * DHc + c];
    }
    __syncthreads();
#pragma unroll
    for (int i = 0; i < 8; i++) {
        int s = tid + i * 256;
        int d = s >> 5, c = s & 31;
        float val = t[d][c];
        bf16 hh, ll; split2(val, hh, ll);
        size_t o = ((size_t)bh * DHc + d) * Lc + l0 + c;
        Thi[o] = hh; Tlo[o] = ll;
    }
}

// ============================================================
// bf16x3 tensor-core GEMM, BK=64, 3-stage cp.async, 1 sync per 64-K.
// MODE 0 (fused QKV), MODE 1 (single + exact GELU). 2 CTAs/SM forced.
// CTA tile 128x128, 8 warps x (64x32 warp tile).
// ============================================================
#define LDTG 72                            // smem stride for BK=64 (144 B)
#define GNIT64 48                          // 3 passes * (1024/64)
#define GEMM_STG64 (128 * LDTG * 2)        // 18432 B per matrix stage
#define GEMM_SMEM64 (3 * 2 * GEMM_STG64)   // 110592 B

template<int MODE>
__global__ __launch_bounds__(256, 2) void mma_gemm_kernel(
    const bf16* __restrict__ Ahi, const bf16* __restrict__ Alo,
    const bf16* __restrict__ Bhi, const bf16* __restrict__ Blo,
    float* __restrict__ Cv,
    bf16* __restrict__ Qhi, bf16* __restrict__ Qlo,
    bf16* __restrict__ Khi, bf16* __restrict__ Klo,
    float qalpha)
{
    extern __shared__ char gsm[];
    const int tid  = threadIdx.x;
    const int lane = tid & 31, wid = tid >> 5;
    const int bm = blockIdx.y * 128;
    const int bn = blockIdx.x * 128;
    const int wm = (wid >> 2) * 64;
    const int wn = (wid & 3) * 32;

    uint32_t as_b[3], bs_b[3];
#pragma unroll
    for (int s = 0; s < 3; s++) {
        as_b[s] = smem_u32(gsm + s * 2 * GEMM_STG64);
        bs_b[s] = as_b[s] + GEMM_STG64;
    }

    const int a_row = wm + (lane & 15);
    const int a_col = (lane >> 4) << 3;
    const int b_row = wn + (lane & 7) + ((lane >> 4) << 3);
    const int b_col = ((lane >> 3) & 1) << 3;

    // staging: 128 rows x 64 cols = 1024 x 16B per matrix; 4/thread each
    const int g_row0 = tid >> 1;             // wrong for 4 chunks; use s-loop
    (void)g_row0;

    auto stage = [&](int kt) {
        const int s  = kt % 3;
        const int p  = kt >> 4;               // pass 0,1,2
        const int kk = (kt & 15) << 6;        // k element offset (64/step)
        const bf16* Ag = (p < 2) ? Ahi : Alo;
        const bf16* Bg = (p == 1) ? Blo : Bhi;
#pragma unroll
        for (int i = 0; i < 4; i++) {
            int sidx = tid + i * 256;         // 0..1023
            int row  = sidx >> 3;             // 0..127
            int c8   = (sidx & 7) << 3;       // 0..56 elements
            uint32_t soff = (uint32_t)(row * LDTG + c8) * 2;
            cp_async16(as_b[s] + soff, Ag + (size_t)(bm + row) * Dc + kk + c8);
            cp_async16(bs_b[s] + soff, Bg + (size_t)(bn + row) * Dc + kk + c8);
        }
        CP_COMMIT();
    };

    float acc[4][4][4];
#pragma unroll
    for (int mi = 0; mi < 4; mi++)
#pragma unroll
        for (int ni = 0; ni < 4; ni++)
#pragma unroll
            for (int e = 0; e < 4; e++) acc[mi][ni][e] = 0.f;

    stage(0); stage(1);

    for (int kt = 0; kt < GNIT64; kt++) {
        const int s = kt % 3;
        if (kt + 1 < GNIT64) CP_WAIT(1); else CP_WAIT(0);
        __syncthreads();
        if (kt + 2 < GNIT64) stage(kt + 2);

#pragma unroll
        for (int k0 = 0; k0 < 64; k0 += 16) {
            uint32_t a[4][4];
#pragma unroll
            for (int mi = 0; mi < 4; mi++)
                ldsm_x4(a[mi], as_b[s] +
                        (uint32_t)((a_row + mi * 16) * LDTG + k0 + a_col) * 2);
            uint32_t b[2][4];
#pragma unroll
            for (int pr = 0; pr < 2; pr++)
                ldsm_x4(b[pr], bs_b[s] +
                        (uint32_t)((b_row + pr * 16) * LDTG + k0 + b_col) * 2);
#pragma unroll
            for (int mi = 0; mi < 4; mi++) {
                mma16816(acc[mi][0], a[mi], b[0][0], b[0][1]);
                mma16816(acc[mi][1], a[mi], b[0][2], b[0][3]);
                mma16816(acc[mi][2], a[mi], b[1][0], b[1][1]);
                mma16816(acc[mi][3], a[mi], b[1][2], b[1][3]);
            }
        }
    }

    const int orow = bm + wm + (lane >> 2);
    const int occ0 = wn + ((lane & 3) << 1);

    if (MODE == 0) {
        const int which = bn >> 10;        // 0 q, 1 k, 2 v
        const int bnl = bn & 1023;
        if (which < 2) {
            bf16* Oh = which ? Khi : Qhi;
            bf16* Ol = which ? Klo : Qlo;
#pragma unroll
            for (int mi = 0; mi < 4; mi++)
#pragma unroll
                for (int ni = 0; ni < 4; ni++) {
                    const size_t i0 = (size_t)(orow + mi * 16) * Dc + bnl + occ0 + ni * 8;
                    const size_t i1 = (size_t)(orow + mi * 16 + 8) * Dc + bnl + occ0 + ni * 8;
                    bf16 h0,l0,h1,l1,h2,l2,h3,l3;
                    split2(acc[mi][ni][0] * qalpha, h0, l0);
                    split2(acc[mi][ni][1] * qalpha, h1, l1);
                    split2(acc[mi][ni][2] * qalpha, h2, l2);
                    split2(acc[mi][ni][3] * qalpha, h3, l3);
                    *(__nv_bfloat162*)&Oh[i0] = __halves2bfloat162(h0, h1);
                    *(__nv_bfloat162*)&Oh[i1] = __halves2bfloat162(h2, h3);
                    *(__nv_bfloat162*)&Ol[i0] = __halves2bfloat162(l0, l1);
                    *(__nv_bfloat162*)&Ol[i1] = __halves2bfloat162(l2, l3);
                }
        } else {
#pragma unroll
            for (int mi = 0; mi < 4; mi++)
#pragma unroll
                for (int ni = 0; ni < 4; ni++) {
                    const size_t i0 = (size_t)(orow + mi * 16) * Dc + bnl + occ0 + ni * 8;
                    const size_t i1 = (size_t)(orow + mi * 16 + 8) * Dc + bnl + occ0 + ni * 8;
                    *(float2*)&Cv[i0] = make_float2(acc[mi][ni][0], acc[mi][ni][1]);
                    *(float2*)&Cv[i1] = make_float2(acc[mi][ni][2], acc[mi][ni][3]);
                }
        }
    } else {
#pragma unroll
        for (int mi = 0; mi < 4; mi++)
#pragma unroll
            for (int ni = 0; ni < 4; ni++) {
                float v0 = acc[mi][ni][0], v1 = acc[mi][ni][1];
                float v2 = acc[mi][ni][2], v3 = acc[mi][ni][3];
                v0 = 0.5f * v0 * (1.f + erff(v0 * 0.70710678118654752f));
                v1 = 0.5f * v1 * (1.f + erff(v1 * 0.70710678118654752f));
                v2 = 0.5f * v2 * (1.f + erff(v2 * 0.70710678118654752f));
                v3 = 0.5f * v3 * (1.f + erff(v3 * 0.70710678118654752f));
                const size_t i0 = (size_t)(orow + mi * 16) * Dc + bn + occ0 + ni * 8;
                const size_t i1 = (size_t)(orow + mi * 16 + 8) * Dc + bn + occ0 + ni * 8;
                *(float2*)&Cv[i0] = make_float2(v0, v1);
                *(float2*)&Cv[i1] = make_float2(v2, v3);
            }
    }
}

// ============================================================
// FAVOR+ feature via mma.sync bf16x3 (unchanged from R8)
// OMODE 1: [bh][l][m] hi/lo.  OMODE 2: transposed [bh][m][l] + ksum.
// ============================================================
#define LDT 40
#define FLDK 72
#define FEAT2_SMEM ((128 + 128 + 256 + 256) * FLDK * 2 + 128 * 4 + 4 * 128 * 4 + 256 * 4)

template<int OMODE>
__global__ __launch_bounds__(256) void feature_mma_kernel(
    const bf16* __restrict__ Uhi, const bf16* __restrict__ Ulo,
    const bf16* __restrict__ Phi, const bf16* __restrict__ Plo,
    bf16* __restrict__ Fhi, bf16* __restrict__ Flo,
    float* __restrict__ ksum)
{
    extern __shared__ char fsm[];
    bf16* us_h = (bf16*)fsm;
    bf16* us_l = us_h + 128 * FLDK;
    bf16* ps_h = us_l + 128 * FLDK;
    bf16* ps_l = ps_h + 256 * FLDK;
    float* diag   = (float*)(ps_l + 256 * FLDK);
    float* rmaxp  = diag + 128;
    float* colsum = rmaxp + 4 * 128;

    const int bh = blockIdx.y;
    const int b = bh >> 4, h = bh & 15;
    const int l0 = blockIdx.x * 128;
    const int tid = threadIdx.x;
    const int lane = tid & 31, wid = tid >> 5;

#pragma unroll
    for (int i = 0; i < 4; i++) {
        int s = tid + i * 256;
        int r = s >> 3, c8 = (s & 7) << 3;
        size_t gi = (size_t)(b * Lc + l0 + r) * Dc + h * DHc + c8;
        *(uint4*)&us_h[r * FLDK + c8] = *(const uint4*)&Uhi[gi];
        *(uint4*)&us_l[r * FLDK + c8] = *(const uint4*)&Ulo[gi];
    }
#pragma unroll
    for (int i = 0; i < 8; i++) {
        int s = tid + i * 256;
        int r = s >> 3, c8 = (s & 7) << 3;
        size_t gi = (size_t)(h * Mc + r) * DHc + c8;
        *(uint4*)&ps_h[r * FLDK + c8] = *(const uint4*)&Phi[gi];
        *(uint4*)&ps_l[r * FLDK + c8] = *(const uint4*)&Plo[gi];
    }
    __syncthreads();

    if (tid < 128) {
        float s = 0.f;
#pragma unroll
        for (int d2 = 0; d2 < 32; d2++) {
            __nv_bfloat162 hh = *(__nv_bfloat162*)&us_h[tid * FLDK + d2 * 2];
            __nv_bfloat162 ll = *(__nv_bfloat162*)&us_l[tid * FLDK + d2 * 2];
            float u0 = __bfloat162float(hh.x) + __bfloat162float(ll.x);
            float u1 = __bfloat162float(hh.y) + __bfloat162float(ll.y);
            s += u0 * u0 + u1 * u1;
        }
        diag[tid] = 0.5f * s;
    }

    const int wm = (wid >> 2) * 64;
    const int wn = (wid & 3) * 64;
    const int a_row = wm + (lane & 15);
    const int a_col = (lane >> 4) << 3;
    const int b_row = wn + (lane & 7) + ((lane >> 4) << 3);
    const int b_col = ((lane >> 3) & 1) << 3;

    float acc[4][8][4];
#pragma unroll
    for (int mi = 0; mi < 4; mi++)
#pragma unroll
        for (int ni = 0; ni < 8; ni++)
#pragma unroll
            for (int e = 0; e < 4; e++) acc[mi][ni][e] = 0.f;

    const uint32_t ush = smem_u32(us_h), usl = smem_u32(us_l);
    const uint32_t psh = smem_u32(ps_h), psl = smem_u32(ps_l);
    __syncthreads();

#pragma unroll
    for (int p = 0; p < 3; p++) {
        const uint32_t ab = (p < 2) ? ush : usl;
        const uint32_t bb = (p == 1) ? psl : psh;
#pragma unroll
        for (int k0 = 0; k0 < 64; k0 += 16) {
            uint32_t a[4][4], bfr[4][4];
#pragma unroll
            for (int mi = 0; mi < 4; mi++)
                ldsm_x4(a[mi], ab + (uint32_t)((a_row + mi * 16) * FLDK + k0 + a_col) * 2);
#pragma unroll
            for (int pr = 0; pr < 4; pr++)
                ldsm_x4(bfr[pr], bb + (uint32_t)((b_row + pr * 16) * FLDK + k0 + b_col) * 2);
#pragma unroll
            for (int mi = 0; mi < 4; mi++)
#pragma unroll
                for (int pr = 0; pr < 4; pr++) {
                    mma16816(acc[mi][2 * pr],     a[mi], bfr[pr][0], bfr[pr][1]);
                    mma16816(acc[mi][2 * pr + 1], a[mi], bfr[pr][2], bfr[pr][3]);
                }
        }
    }

    float tmax[4][2];
#pragma unroll
    for (int mi = 0; mi < 4; mi++) {
        float m0 = -1e30f, m1 = -1e30f;
#pragma unroll
        for (int ni = 0; ni < 8; ni++) {
            m0 = fmaxf(m0, fmaxf(acc[mi][ni][0], acc[mi][ni][1]));
            m1 = fmaxf(m1, fmaxf(acc[mi][ni][2], acc[mi][ni][3]));
        }
#pragma unroll
        for (int off = 1; off <= 2; off <<= 1) {
            m0 = fmaxf(m0, __shfl_xor_sync(0xffffffffu, m0, off));
            m1 = fmaxf(m1, __shfl_xor_sync(0xffffffffu, m1, off));
        }
        tmax[mi][0] = m0; tmax[mi][1] = m1;
    }
    if ((lane & 3) == 0) {
        const int slab = wid & 3;
#pragma unroll
        for (int mi = 0; mi < 4; mi++) {
            int r = wm + mi * 16 + (lane >> 2);
            rmaxp[slab * 128 + r]     = tmax[mi][0];
            rmaxp[slab * 128 + r + 8] = tmax[mi][1];
        }
    }
    if (OMODE == 2 && tid < 256) colsum[tid] = 0.f;
    __syncthreads();

    float base[4][2];
#pragma unroll
    for (int mi = 0; mi < 4; mi++) {
        const int r0 = wm + mi * 16 + (lane >> 2);
        const int r1 = r0 + 8;
        float rm0 = fmaxf(fmaxf(rmaxp[r0], rmaxp[128 + r0]),
                          fmaxf(rmaxp[256 + r0], rmaxp[384 + r0]));
        float rm1 = fmaxf(fmaxf(rmaxp[r1], rmaxp[128 + r1]),
                          fmaxf(rmaxp[256 + r1], rmaxp[384 + r1]));
        base[mi][0] = -diag[r0] - rm0;
        base[mi][1] = -diag[r1] - rm1;
    }

    if (OMODE == 1) {
#pragma unroll
        for (int mi = 0; mi < 4; mi++) {
            const int r0 = wm + mi * 16 + (lane >> 2);
            const size_t o0 = ((size_t)bh * Lc + l0 + r0) * Mc;
            const size_t o1 = ((size_t)bh * Lc + l0 + r0 + 8) * Mc;
            const int c0 = wn + ((lane & 3) << 1);
#pragma unroll
            for (int ni = 0; ni < 8; ni++) {
                int c = c0 + ni * 8;
                float f0 = __expf(acc[mi][ni][0] + base[mi][0]) * 0.0625f;
                float f1 = __expf(acc[mi][ni][1] + base[mi][0]) * 0.0625f;
                float f2 = __expf(acc[mi][ni][2] + base[mi][1]) * 0.0625f;
                float f3 = __expf(acc[mi][ni][3] + base[mi][1]) * 0.0625f;
                bf16 h0,l0b,h1,l1b,h2,l2b,h3,l3b;
                split2(f0, h0, l0b); split2(f1, h1, l1b);
                split2(f2, h2, l2b); split2(f3, h3, l3b);
                *(__nv_bfloat162*)&Fhi[o0 + c] = __halves2bfloat162(h0, h1);
                *(__nv_bfloat162*)&Fhi[o1 + c] = __halves2bfloat162(h2, h3);
                *(__nv_bfloat162*)&Flo[o0 + c] = __halves2bfloat162(l0b, l1b);
                *(__nv_bfloat162*)&Flo[o1 + c] = __halves2bfloat162(l2b, l3b);
            }
        }
    } else {
        const int lr = lane >> 2;
#pragma unroll
        for (int ni = 0; ni < 8; ni++) {
            const int c = wn + ((lane & 3) << 1) + ni * 8;
            float s0 = 0.f, s1 = 0.f;
#pragma unroll
            for (int mi = 0; mi < 4; mi++) {
                const int r0 = wm + mi * 16 + lr;
                float f0 = __expf(acc[mi][ni][0] + base[mi][0]) * 0.0625f;
                float f1 = __expf(acc[mi][ni][1] + base[mi][0]) * 0.0625f;
                float f2 = __expf(acc[mi][ni][2] + base[mi][1]) * 0.0625f;
                float f3 = __expf(acc[mi][ni][3] + base[mi][1]) * 0.0625f;
                s0 += f0 + f2; s1 += f1 + f3;
                const size_t t0 = ((size_t)bh * Mc + c) * Lc + l0;
                const size_t t1 = t0 + Lc;
                bf16 hh, ll;
                split2(f0, hh, ll); Fhi[t0 + r0] = hh;     Flo[t0 + r0] = ll;
                split2(f2, hh, ll); Fhi[t0 + r0 + 8] = hh; Flo[t0 + r0 + 8] = ll;
                split2(f1, hh, ll); Fhi[t1 + r0] = hh;     Flo[t1 + r0] = ll;
                split2(f3, hh, ll); Fhi[t1 + r0 + 8] = hh; Flo[t1 + r0 + 8] = ll;
            }
            atomicAdd(&colsum[c], s0);
            atomicAdd(&colsum[c + 1], s1);
        }
        __syncthreads();
        if (tid < 256) atomicAdd(&ksum[bh * Mc + tid], colsum[tid]);
    }
}

// ============================================================
// kv via mma bf16x3 (unchanged from R8)
// ============================================================
#define KVNIT 48
#define KV_ASTG (64 * LDT * 2)
#define KV_BSTG (256 * LDT * 2)
#define KV_SMEM (3 * (KV_ASTG + KV_BSTG))

__global__ __launch_bounds__(256, 2) void kv_mma_kernel(
    const bf16* __restrict__ vthi, const bf16* __restrict__ vtlo,
    const bf16* __restrict__ kfthi, const bf16* __restrict__ kftlo,
    float* __restrict__ kvtf)
{
    extern __shared__ char ksm[];
    const int bh = blockIdx.y;
    const int l0 = blockIdx.x * 512;
    const int tid = threadIdx.x;
    const int lane = tid & 31, wid = tid >> 5;
    const int wn = wid * 32;

    uint32_t as_b[3], bs_b[3];
#pragma unroll
    for (int s = 0; s < 3; s++) {
        as_b[s] = smem_u32(ksm + s * (KV_ASTG + KV_BSTG));
        bs_b[s] = as_b[s] + KV_ASTG;
    }

    const int a_row = (lane & 15);
    const int a_col = (lane >> 4) << 3;
    const int b_row = wn + (lane & 7) + ((lane >> 4) << 3);
    const int b_col = ((lane >> 3) & 1) << 3;

    const size_t abase = (size_t)bh * DHc * Lc + l0;
    const size_t bbase = (size_t)bh * Mc * Lc + l0;

    const int ga_row = tid >> 2, ga_c8 = (tid & 3) << 3;

    auto stage = [&](int kt) {
        const int s  = kt % 3;
        const int p  = kt >> 4;
        const int kk = (kt & 15) << 5;
        const bf16* Ag = ((p < 2) ? vthi : vtlo) + abase;
        const bf16* Bg = ((p == 1) ? kftlo : kfthi) + bbase;
        cp_async16(as_b[s] + (uint32_t)(ga_row * LDT + ga_c8) * 2,
                   Ag + (size_t)ga_row * Lc + kk + ga_c8);
#pragma unroll
        for (int i = 0; i < 4; i++) {
            int row = ga_row + i * 64;
            cp_async16(bs_b[s] + (uint32_t)(row * LDT + ga_c8) * 2,
                       Bg + (size_t)row * Lc + kk + ga_c8);
        }
        CP_COMMIT();
    };

    float acc[4][4][4];
#pragma unroll
    for (int mi = 0; mi < 4; mi++)
#pragma unroll
        for (int ni = 0; ni < 4; ni++)
#pragma unroll
            for (int e = 0; e < 4; e++) acc[mi][ni][e] = 0.f;

    stage(0); stage(1);

    for (int kt = 0; kt < KVNIT; kt++) {
        const int s = kt % 3;
        if (kt + 1 < KVNIT) CP_WAIT(1); else CP_WAIT(0);
        __syncthreads();
        if (kt + 2 < KVNIT) stage(kt + 2);

#pragma unroll
        for (int k0 = 0; k0 < 32; k0 += 16) {
            uint32_t a[4][4];
#pragma unroll
            for (int mi = 0; mi < 4; mi++)
                ldsm_x4(a[mi], as_b[s] +
                        (uint32_t)((a_row + mi * 16) * LDT + k0 + a_col) * 2);
            uint32_t bf_[2][4];
#pragma unroll
            for (int pr = 0; pr < 2; pr++)
                ldsm_x4(bf_[pr], bs_b[s] +
                        (uint32_t)((b_row + pr * 16) * LDT + k0 + b_col) * 2);
#pragma unroll
            for (int mi = 0; mi < 4; mi++) {
                mma16816(acc[mi][0], a[mi], bf_[0][0], bf_[0][1]);
                mma16816(acc[mi][1], a[mi], bf_[0][2], bf_[0][3]);
                mma16816(acc[mi][2], a[mi], bf_[1][0], bf_[1][1]);
                mma16816(acc[mi][3], a[mi], bf_[1][2], bf_[1][3]);
            }
        }
    }

    const int lr = lane >> 2;
    const int c0 = wn + ((lane & 3) << 1);
    float* dst = kvtf + (size_t)bh * DHc * Mc;
#pragma unroll
    for (int mi = 0; mi < 4; mi++) {
        const int d0 = mi * 16 + lr;
        const int d1 = d0 + 8;
#pragma unroll
        for (int ni = 0; ni < 4; ni++) {
            int c = c0 + ni * 8;
            atomicAdd(&dst[d0 * Mc + c],     acc[mi][ni][0]);
            atomicAdd(&dst[d0 * Mc + c + 1], acc[mi][ni][1]);
            atomicAdd(&dst[d1 * Mc + c],     acc[mi][ni][2]);
            atomicAdd(&dst[d1 * Mc + c + 1], acc[mi][ni][3]);
        }
    }
}

// ============================================================
// kvtf fp32 -> kvthi/kvtlo
// ============================================================
__global__ __launch_bounds__(256) void kvsplit_kernel(
    const float* __restrict__ kvtf, bf16* __restrict__ Thi, bf16* __restrict__ Tlo)
{
    int i = blockIdx.x * 256 + threadIdx.x;
    float v = kvtf[i];
    bf16 h, l; split2(v, h, l);
    Thi[i] = h; Tlo[i] = l;
}

// ============================================================
// z[bh,l] = 1 / (dot(qf_hi+qf_lo, ksum) + 1e-6)
// ============================================================
__global__ __launch_bounds__(256) void z_kernel(
    const bf16* __restrict__ qfhi, const bf16* __restrict__ qflo,
    const float* __restrict__ ksum, float* __restrict__ z)
{
    __shared__ float ks[256];
    const int bh = blockIdx.y;
    ks[threadIdx.x] = ksum[bh * Mc + threadIdx.x];
    __syncthreads();
    const int w = threadIdx.x >> 5, lane = threadIdx.x & 31;
    const int l = blockIdx.x * 8 + w;
    const size_t base = ((size_t)bh * Lc + l) * Mc;
    float s = 0.f;
#pragma unroll
    for (int q8 = 0; q8 < 8; q8++) {
        int c = lane + q8 * 32;
        s += (__bfloat162float(qfhi[base + c]) + __bfloat162float(qflo[base + c])) * ks[c];
    }
#pragma unroll
    for (int off = 16; off; off >>= 1) s += __shfl_xor_sync(0xffffffffu, s, off);
    if (lane == 0) z[bh * Lc + l] = 1.0f / (s + 1e-6f);
}

// ============================================================
// attn via mma bf16x3 (unchanged from R8)
// ============================================================
#define ANIT 24
#define ATT_ASTG (256 * LDT * 2)
#define ATT_BSTG (64 * LDT * 2)
#define ATT_SMEM (3 * (ATT_ASTG + ATT_BSTG))

__global__ __launch_bounds__(256, 2) void attn_mma_kernel(
    const bf16* __restrict__ qfhi, const bf16* __restrict__ qflo,
    const bf16* __restrict__ kvthi, const bf16* __restrict__ kvtlo,
    const float* __restrict__ z,
    bf16* __restrict__ Ohi, bf16* __restrict__ Olo)
{
    extern __shared__ char asm_[];
    const int bh = blockIdx.y;
    const int b = bh >> 4, h = bh & 15;
    const int l0 = blockIdx.x * 256;
    const int tid = threadIdx.x;
    const int lane = tid & 31, wid = tid >> 5;
    const int wm = (wid >> 1) * 64;
    const int wn = (wid & 1) * 32;

    uint32_t as_b[3], bs_b[3];
#pragma unroll
    for (int s = 0; s < 3; s++) {
        as_b[s] = smem_u32(asm_ + s * (ATT_ASTG + ATT_BSTG));
        bs_b[s] = as_b[s] + ATT_ASTG;
    }

    const int a_row = wm + (lane & 15);
    const int a_col = (lane >> 4) << 3;
    const int b_row = wn + (lane & 7) + ((lane >> 4) << 3);
    const int b_col = ((lane >> 3) & 1) << 3;

    const size_t qbase = ((size_t)bh * Lc + l0) * Mc;
    const size_t kbase = (size_t)bh * DHc * Mc;

    const int ga_row0 = tid >> 2, ga_c8 = (tid & 3) << 3;
    const int gb_row = tid >> 2, gb_c8 = (tid & 3) << 3;

    auto stage = [&](int kt) {
        const int s  = kt % 3;
        const int p  = kt >> 3;
        const int kk = (kt & 7) << 5;
        const bf16* Ag = ((p < 2) ? qfhi : qflo) + qbase;
        const bf16* Bg = ((p == 1) ? kvtlo : kvthi) + kbase;
#pragma unroll
        for (int i = 0; i < 4; i++) {
            int row = ga_row0 + i * 64;
            cp_async16(as_b[s] + (uint32_t)(row * LDT + ga_c8) * 2,
                       Ag + (size_t)row * Mc + kk + ga_c8);
        }
        cp_async16(bs_b[s] + (uint32_t)(gb_row * LDT + gb_c8) * 2,
                   Bg + (size_t)gb_row * Mc + kk + gb_c8);
        CP_COMMIT();
    };

    float acc[4][4][4];
#pragma unroll
    for (int mi = 0; mi < 4; mi++)
#pragma unroll
        for (int ni = 0; ni < 4; ni++)
#pragma unroll
            for (int e = 0; e < 4; e++) acc[mi][ni][e] = 0.f;

    stage(0); stage(1);

    for (int kt = 0; kt < ANIT; kt++) {
        const int s = kt % 3;
        if (kt + 1 < ANIT) CP_WAIT(1); else CP_WAIT(0);
        __syncthreads();
        if (kt + 2 < ANIT) stage(kt + 2);

#pragma unroll
        for (int k0 = 0; k0 < 32; k0 += 16) {
            uint32_t a[4][4];
#pragma unroll
            for (int mi = 0; mi < 4; mi++)
                ldsm_x4(a[mi], as_b[s] +
                        (uint32_t)((a_row + mi * 16) * LDT + k0 + a_col) * 2);
            uint32_t bf_[2][4];
#pragma unroll
            for (int pr = 0; pr < 2; pr++)
                ldsm_x4(bf_[pr], bs_b[s] +
                        (uint32_t)((b_row + pr * 16) * LDT + k0 + b_col) * 2);
#pragma unroll
            for (int mi = 0; mi < 4; mi++) {
                mma16816(acc[mi][0], a[mi], bf_[0][0], bf_[0][1]);
                mma16816(acc[mi][1], a[mi], bf_[0][2], bf_[0][3]);
                mma16816(acc[mi][2], a[mi], bf_[1][0], bf_[1][1]);
                mma16816(acc[mi][3], a[mi], bf_[1][2], bf_[1][3]);
            }
        }
    }

    const int lr = lane >> 2;
    const int occ0 = wn + ((lane & 3) << 1);
#pragma unroll
    for (int mi = 0; mi < 4; mi++) {
        const int r0 = wm + mi * 16 + lr;
        const int r1 = r0 + 8;
        const float z0 = z[(size_t)bh * Lc + l0 + r0];
        const float z1 = z[(size_t)bh * Lc + l0 + r1];
        const size_t i0 = (size_t)(b * Lc + l0 + r0) * Dc + h * DHc;
        const size_t i1 = (size_t)(b * Lc + l0 + r1) * Dc + h * DHc;
#pragma unroll
        for (int ni = 0; ni < 4; ni++) {
            int c = occ0 + ni * 8;
            bf16 h0,l0b,h1,l1b,h2,l2b,h3,l3b;
            split2(acc[mi][ni][0] * z0, h0, l0b);
            split2(acc[mi][ni][1] * z0, h1, l1b);
            split2(acc[mi][ni][2] * z1, h2, l2b);
            split2(acc[mi][ni][3] * z1, h3, l3b);
            *(__nv_bfloat162*)&Ohi[i0 + c] = __halves2bfloat162(h0, h1);
            *(__nv_bfloat162*)&Ohi[i1 + c] = __halves2bfloat162(h2, h3);
            *(__nv_bfloat162*)&Olo[i0 + c] = __halves2bfloat162(l0b, l1b);
            *(__nv_bfloat162*)&Olo[i1 + c] = __halves2bfloat162(l2b, l3b);
        }
    }
}

// ============================================================
// LayerNorm + duplicate rows
// ============================================================
__global__ __launch_bounds__(256) void ln_dup_kernel(
    const float* __restrict__ y, const float* __restrict__ g,
    const float* __restrict__ beta, float* __restrict__ out)
{
    __shared__ float red[18];
    const int row = blockIdx.x;
    const int b = row >> 12, l = row & 4095;
    const int tid = threadIdx.x;
    const float* yr = y + (size_t)row * Dc;

    float v[4];
    float s = 0.f, ss = 0.f;
#pragma unroll
    for (int i = 0; i < 4; i++) {
        float t = yr[tid + i * 256];
        v[i] = t; s += t; ss += t * t;
    }
#pragma unroll
    for (int off = 16; off; off >>= 1) {
        s  += __shfl_xor_sync(0xffffffffu, s, off);
        ss += __shfl_xor_sync(0xffffffffu, ss, off);
    }
    const int w = tid >> 5, lane = tid & 31;
    if (lane == 0) { red[w] = s; red[8 + w] = ss; }
    __syncthreads();
    if (tid == 0) {
        float ts = 0.f, tss = 0.f;
#pragma unroll
        for (int i = 0; i < 8; i++) { ts += red[i]; tss += red[8 + i]; }
        float mean = ts * (1.0f / 1024.0f);
        float var = tss * (1.0f / 1024.0f) - mean * mean;
        red[16] = mean;
        red[17] = rsqrtf(var + 1e-5f);
    }
    __syncthreads();
    const float mean = red[16], rstd = red[17];
    float* o0 = out + ((size_t)b * 8192 + 2 * (size_t)l) * Dc;
#pragma unroll
    for (int i = 0; i < 4; i++) {
        int c = tid + i * 256;
        float o = (v[i] - mean) * rstd * g[c] + beta[c];
        o0[c] = o;
        o0[Dc + c] = o;
    }
}

// ============================================================
// host launch
// ============================================================
extern "C" void kernel_launch(void* const* d_in, const int* in_sizes, int n_in,
                              void* d_out, int out_size)
{
    const float* x    = (const float*)d_in[0];
    const float* Wq   = (const float*)d_in[1];
    const float* Wk   = (const float*)d_in[2];
    const float* Wv   = (const float*)d_in[3];
    const float* Wo   = (const float*)d_in[4];
    const float* proj = (const float*)d_in[5];
    const float* ln_g = (const float*)d_in[6];
    const float* ln_b = (const float*)d_in[7];
    float* out = (float*)d_out;

    float *v, *kvtf, *ksum, *z, *y;
    bf16 *qfhi, *qflo, *kfthi, *kftlo, *vthi, *vtlo, *kvthi, *kvtlo;
    bf16 *ahi, *alo, *bthi, *btlo, *qhi, *qlo, *khi, *klo, *phi, *plo;
    cudaGetSymbolAddress((void**)&v,     g_v);
    cudaGetSymbolAddress((void**)&qfhi,  g_qfhi);
    cudaGetSymbolAddress((void**)&qflo,  g_qflo);
    cudaGetSymbolAddress((void**)&kfthi, g_kfthi);
    cudaGetSymbolAddress((void**)&kftlo, g_kftlo);
    cudaGetSymbolAddress((void**)&vthi,  g_vthi);
    cudaGetSymbolAddress((void**)&vtlo,  g_vtlo);
    cudaGetSymbolAddress((void**)&kvtf,  g_kvtf);
    cudaGetSymbolAddress((void**)&kvthi, g_kvthi);
    cudaGetSymbolAddress((void**)&kvtlo, g_kvtlo);
    cudaGetSymbolAddress((void**)&ksum,  g_ksum);
    cudaGetSymbolAddress((void**)&z,     g_z);
    cudaGetSymbolAddress((void**)&y,     g_y);
    cudaGetSymbolAddress((void**)&ahi,   g_ahi);
    cudaGetSymbolAddress((void**)&alo,   g_alo);
    cudaGetSymbolAddress((void**)&bthi,  g_bthi);
    cudaGetSymbolAddress((void**)&btlo,  g_btlo);
    cudaGetSymbolAddress((void**)&qhi,   g_qhi);
    cudaGetSymbolAddress((void**)&qlo,   g_qlo);
    cudaGetSymbolAddress((void**)&khi,   g_khi);
    cudaGetSymbolAddress((void**)&klo,   g_klo);
    cudaGetSymbolAddress((void**)&phi,   g_phi);
    cudaGetSymbolAddress((void**)&plo,   g_plo);

    const float qscale = 0.35355339059327379f;  // 64^-0.25

    cudaFuncSetAttribute(mma_gemm_kernel<0>,
                         cudaFuncAttributeMaxDynamicSharedMemorySize, GEMM_SMEM64);
    cudaFuncSetAttribute(mma_gemm_kernel<1>,
                         cudaFuncAttributeMaxDynamicSharedMemorySize, GEMM_SMEM64);
    cudaFuncSetAttribute(feature_mma_kernel<1>,
                         cudaFuncAttributeMaxDynamicSharedMemorySize, FEAT2_SMEM);
    cudaFuncSetAttribute(feature_mma_kernel<2>,
                         cudaFuncAttributeMaxDynamicSharedMemorySize, FEAT2_SMEM);
    cudaFuncSetAttribute(kv_mma_kernel,
                         cudaFuncAttributeMaxDynamicSharedMemorySize, KV_SMEM);
    cudaFuncSetAttribute(attn_mma_kernel,
                         cudaFuncAttributeMaxDynamicSharedMemorySize, ATT_SMEM);

    const int n4 = ROWS * Dc / 4;
    dim3 tgrid(32, 32), tblk(32, 8);

    // splits
    split_kernel<<<n4 / 256, 256>>>(x, ahi, alo, n4);
    split_kernel<<<(Hc * Mc * DHc / 4) / 256, 256>>>(proj, phi, plo, Hc * Mc * DHc / 4);
    tsplit_kernel<<<tgrid, tblk>>>(Wq, bthi,                   btlo);
    tsplit_kernel<<<tgrid, tblk>>>(Wk, bthi + (size_t)Dc*Dc,   btlo + (size_t)Dc*Dc);
    tsplit_kernel<<<tgrid, tblk>>>(Wv, bthi + (size_t)2*Dc*Dc, btlo + (size_t)2*Dc*Dc);

    // zero accumulators (consumed by feature<2> and kv_mma)
    cudaMemsetAsync(ksum, 0, (size_t)BHc * Mc * sizeof(float), 0);
    cudaMemsetAsync(kvtf, 0, (size_t)BHc * DHc * Mc * sizeof(float), 0);

    // fused QKV GEMM (BK=64)
    mma_gemm_kernel<0><<<dim3(24, 64), 256, GEMM_SMEM64>>>(
        ahi, alo, bthi, btlo, v, qhi, qlo, khi, klo, qscale);

    // features: Q -> qf hi/lo [l][m]; K -> kf_t hi/lo [m][l] + ksum
    feature_mma_kernel<1><<<dim3(Lc / 128, BHc), 256, FEAT2_SMEM>>>(
        qhi, qlo, phi, plo, qfhi, qflo, nullptr);
    feature_mma_kernel<2><<<dim3(Lc / 128, BHc), 256, FEAT2_SMEM>>>(
        khi, klo, phi, plo, kfthi, kftlo, ksum);

    // v transpose+split, then kv via tensor cores
    vt_kernel<<<dim3(Lc / 32, BHc), 256>>>(v, vthi, vtlo);
    kv_mma_kernel<<<dim3(8, BHc), 256, KV_SMEM>>>(vthi, vtlo, kfthi, kftlo, kvtf);
    kvsplit_kernel<<<(BHc * DHc * Mc) / 256, 256>>>(kvtf, kvthi, kvtlo);

    z_kernel<<<dim3(Lc / 8, BHc), 256>>>(qfhi, qflo, ksum, z);

    // attn -> hi/lo directly into O-GEMM A buffers
    attn_mma_kernel<<<dim3(Lc / 256, BHc), 256, ATT_SMEM>>>(
        qfhi, qflo, kvthi, kvtlo, z, ahi, alo);

    // O projection + exact GELU (BK=64)
    tsplit_kernel<<<tgrid, tblk>>>(Wo, bthi, btlo);
    mma_gemm_kernel<1><<<dim3(8, 64), 256, GEMM_SMEM64>>>(
        ahi, alo, bthi, btlo, y, nullptr, nullptr, nullptr, nullptr, 1.0f);

    ln_dup_kernel<<<ROWS, 256>>>(y, ln_g, ln_b, out);
}

// round 10
// speedup vs baseline: 1.3006x; 1.0610x over previous
#include <cuda_runtime.h>
#include <cuda_bf16.h>
#include <math.h>
#include <stdint.h>

// Shapes (fixed)
#define Bc   2
#define Lc   4096
#define Dc   1024
#define Hc   16
#define DHc  64
#define Mc   256
#define BHc  32
#define ROWS 8192   // B*L

typedef __nv_bfloat16 bf16;

// -------- scratch (device globals; no allocations allowed) --------
__device__ float g_v    [(size_t)ROWS * Dc];
__device__ bf16  g_qfhi [(size_t)BHc * Lc * Mc];
__device__ bf16  g_qflo [(size_t)BHc * Lc * Mc];
__device__ bf16  g_kfthi[(size_t)BHc * Mc * Lc];
__device__ bf16  g_kftlo[(size_t)BHc * Mc * Lc];
__device__ bf16  g_vthi [(size_t)BHc * DHc * Lc];
__device__ bf16  g_vtlo [(size_t)BHc * DHc * Lc];
__device__ float g_kvtf [(size_t)BHc * DHc * Mc];
__device__ bf16  g_kvthi[(size_t)BHc * DHc * Mc];
__device__ bf16  g_kvtlo[(size_t)BHc * DHc * Mc];
__device__ float g_ksum [(size_t)BHc * Mc];
__device__ float g_z    [(size_t)BHc * Lc];
__device__ float g_y    [(size_t)ROWS * Dc];
__device__ bf16  g_ahi  [(size_t)ROWS * Dc];
__device__ bf16  g_alo  [(size_t)ROWS * Dc];
__device__ bf16  g_bthi [(size_t)3 * Dc * Dc];
__device__ bf16  g_btlo [(size_t)3 * Dc * Dc];
__device__ bf16  g_qhi  [(size_t)ROWS * Dc];
__device__ bf16  g_qlo  [(size_t)ROWS * Dc];
__device__ bf16  g_khi  [(size_t)ROWS * Dc];
__device__ bf16  g_klo  [(size_t)ROWS * Dc];
__device__ bf16  g_phi  [(size_t)Hc * Mc * DHc];
__device__ bf16  g_plo  [(size_t)Hc * Mc * DHc];

// ================= baseline-PTX tensor-core helpers (sm_80+) ==========
__device__ __forceinline__ uint32_t smem_u32(const void* p) {
    uint32_t a;
    asm("{ .reg .u64 t; cvta.to.shared.u64 t, %1; cvt.u32.u64 %0, t; }"
        : "=r"(a) : "l"(p));
    return a;
}
__device__ __forceinline__ void cp_async16(uint32_t saddr, const void* g) {
    asm volatile("cp.async.cg.shared.global [%0], [%1], 16;"
                 :: "r"(saddr), "l"(g) : "memory");
}
#define CP_COMMIT() asm volatile("cp.async.commit_group;" ::: "memory")
#define CP_WAIT(n)  asm volatile("cp.async.wait_group %0;" :: "n"(n) : "memory")

__device__ __forceinline__ void ldsm_x4(uint32_t r[4], uint32_t addr) {
    asm volatile("ldmatrix.sync.aligned.m8n8.x4.shared.b16 {%0,%1,%2,%3}, [%4];"
                 : "=r"(r[0]), "=r"(r[1]), "=r"(r[2]), "=r"(r[3]) : "r"(addr));
}
__device__ __forceinline__ void mma16816(float c[4], const uint32_t a[4],
                                         uint32_t b0, uint32_t b1) {
    asm volatile(
        "mma.sync.aligned.m16n8k16.row.col.f32.bf16.bf16.f32 "
        "{%0,%1,%2,%3}, {%4,%5,%6,%7}, {%8,%9}, {%0,%1,%2,%3};"
        : "+f"(c[0]), "+f"(c[1]), "+f"(c[2]), "+f"(c[3])
        : "r"(a[0]), "r"(a[1]), "r"(a[2]), "r"(a[3]), "r"(b0), "r"(b1));
}
__device__ __forceinline__ void split2(float v, bf16& h, bf16& l) {
    h = __float2bfloat16_rn(v);
    l = __float2bfloat16_rn(v - __bfloat162float(h));
}

// ============================================================
// fp32 -> (hi, lo) bf16 split
// ============================================================
__global__ __launch_bounds__(256) void split_kernel(
    const float* __restrict__ in, bf16* __restrict__ hi,
    bf16* __restrict__ lo, int n4)
{
    int i = blockIdx.x * 256 + threadIdx.x;
    if (i >= n4) return;
    float4 v = ((const float4*)in)[i];
    bf16 h0, h1, h2, h3, l0, l1, l2, l3;
    split2(v.x, h0, l0); split2(v.y, h1, l1);
    split2(v.z, h2, l2); split2(v.w, h3, l3);
    ((__nv_bfloat162*)hi)[2*i]   = __halves2bfloat162(h0, h1);
    ((__nv_bfloat162*)hi)[2*i+1] = __halves2bfloat162(h2, h3);
    ((__nv_bfloat162*)lo)[2*i]   = __halves2bfloat162(l0, l1);
    ((__nv_bfloat162*)lo)[2*i+1] = __halves2bfloat162(l2, l3);
}

// ============================================================
// W [K=1024, N=1024] -> W^T [N,K] with bf16 hi/lo split
// ============================================================
__global__ void tsplit_kernel(const float* __restrict__ W,
    bf16* __restrict__ Thi, bf16* __restrict__ Tlo)
{
    __shared__ float t[32][33];
    int bx = blockIdx.x * 32, by = blockIdx.y * 32;
    int tx = threadIdx.x, ty = threadIdx.y;   // 32 x 8
#pragma unroll
    for (int i = 0; i < 32; i += 8)
        t[ty + i][tx] = W[(size_t)(by + ty + i) * Dc + bx + tx];
    __syncthreads();
#pragma unroll
    for (int i = 0; i < 32; i += 8) {
        float v = t[tx][ty + i];
        int orow = bx + ty + i, ocol = by + tx;
        bf16 h, l; split2(v, h, l);
        Thi[(size_t)orow * Dc + ocol] = h;
        Tlo[(size_t)orow * Dc + ocol] = l;
    }
}

// ============================================================
// v [b*L][D] fp32 -> v_t [bh][d][l] bf16 hi/lo
// ============================================================
__global__ __launch_bounds__(256) void vt_kernel(
    const float* __restrict__ v, bf16* __restrict__ Thi, bf16* __restrict__ Tlo)
{
    __shared__ float t[64][33];
    const int bh = blockIdx.y;
    const int b = bh >> 4, h = bh & 15;
    const int l0 = blockIdx.x * 32;
    const int tid = threadIdx.x;
#pragma unroll
    for (int i = 0; i < 8; i++) {
        int s = tid + i * 256;
        int r = s >> 6, c = s & 63;
        t[c][r & 31] = v[(size_t)(b * Lc + l0 + r) * Dc + h * DHc + c];
    }
    __syncthreads();
#pragma unroll
    for (int i = 0; i < 8; i++) {
        int s = tid + i * 256;
        int d = s >> 5, c = s & 31;
        float val = t[d][c];
        bf16 hh, ll; split2(val, hh, ll);
        size_t o = ((size_t)bh * DHc + d) * Lc + l0 + c;
        Thi[o] = hh; Tlo[o] = ll;
    }
}

// ============================================================
// bf16x3 FUSED-PASS tensor-core GEMM:
// each BK=32 k-tile stages Ah, Al, Bh, Bl together; inner loop does
// Ah*Bh + Ah*Bl + Al*Bh from one staging (GMEM reads 6 -> 4 matrix passes,
// sync rounds 48 -> 32, ldsm:mma 1:4). 2 stages, 2 CTAs/SM.
// MODE 0 (fused QKV), MODE 1 (single + exact GELU).
// CTA tile 128x128, 8 warps x (64x32 warp tile).
// ============================================================
#define LDT 40
#define GNITF 16                           // 1024 / 64... no: 1024/64? K-tiles of 64? (=1024/64)  -> see below
#undef GNITF
#define GNITF 32                           // 1024 / 32 k-tiles
#define GEMM_MSTG (128 * LDT * 2)          // 10240 B per matrix
#define GEMM_STAGE (4 * GEMM_MSTG)         // 40960 B per stage (Ah,Al,Bh,Bl)
#define GEMM_SMEMF (2 * GEMM_STAGE)        // 81920 B

template<int MODE>
__global__ __launch_bounds__(256, 2) void mma_gemm_kernel(
    const bf16* __restrict__ Ahi, const bf16* __restrict__ Alo,
    const bf16* __restrict__ Bhi, const bf16* __restrict__ Blo,
    float* __restrict__ Cv,
    bf16* __restrict__ Qhi, bf16* __restrict__ Qlo,
    bf16* __restrict__ Khi, bf16* __restrict__ Klo,
    float qalpha)
{
    extern __shared__ char gsm[];
    const int tid  = threadIdx.x;
    const int lane = tid & 31, wid = tid >> 5;
    const int bm = blockIdx.y * 128;
    const int bn = blockIdx.x * 128;
    const int wm = (wid >> 2) * 64;
    const int wn = (wid & 3) * 32;

    // buffers: [stage][Ah | Al | Bh | Bl]
    uint32_t ah_b[2], al_b[2], bh_b[2], bl_b[2];
#pragma unroll
    for (int s = 0; s < 2; s++) {
        uint32_t base = smem_u32(gsm + s * GEMM_STAGE);
        ah_b[s] = base;
        al_b[s] = base + GEMM_MSTG;
        bh_b[s] = base + 2 * GEMM_MSTG;
        bl_b[s] = base + 3 * GEMM_MSTG;
    }

    const int a_row = wm + (lane & 15);
    const int a_col = (lane >> 4) << 3;
    const int b_row = wn + (lane & 7) + ((lane >> 4) << 3);
    const int b_col = ((lane >> 3) & 1) << 3;

    const int g_row0 = tid >> 2;            // 0..63 (+64)
    const int g_c8   = (tid & 3) << 3;      // 0,8,16,24

    auto stage = [&](int kt) {
        const int s  = kt & 1;
        const int kk = kt << 5;
#pragma unroll
        for (int i = 0; i < 2; i++) {
            int row = g_row0 + i * 64;
            uint32_t soff = (uint32_t)(row * LDT + g_c8) * 2;
            const size_t ga = (size_t)(bm + row) * Dc + kk + g_c8;
            const size_t gb = (size_t)(bn + row) * Dc + kk + g_c8;
            cp_async16(ah_b[s] + soff, Ahi + ga);
            cp_async16(al_b[s] + soff, Alo + ga);
            cp_async16(bh_b[s] + soff, Bhi + gb);
            cp_async16(bl_b[s] + soff, Blo + gb);
        }
        CP_COMMIT();
    };

    float acc[4][4][4];
#pragma unroll
    for (int mi = 0; mi < 4; mi++)
#pragma unroll
        for (int ni = 0; ni < 4; ni++)
#pragma unroll
            for (int e = 0; e < 4; e++) acc[mi][ni][e] = 0.f;

    stage(0); stage(1);

    for (int kt = 0; kt < GNITF; kt++) {
        const int s = kt & 1;
        if (kt + 1 < GNITF) CP_WAIT(1); else CP_WAIT(0);
        __syncthreads();

#pragma unroll
        for (int k0 = 0; k0 < 32; k0 += 16) {
            // B fragments (hi and lo held simultaneously)
            uint32_t bh_[2][4], bl_[2][4];
#pragma unroll
            for (int pr = 0; pr < 2; pr++) {
                uint32_t boff = (uint32_t)((b_row + pr * 16) * LDT + k0 + b_col) * 2;
                ldsm_x4(bh_[pr], bh_b[s] + boff);
                ldsm_x4(bl_[pr], bl_b[s] + boff);
            }
            // A hi fragments -> two mma groups
            uint32_t a[4][4];
#pragma unroll
            for (int mi = 0; mi < 4; mi++)
                ldsm_x4(a[mi], ah_b[s] +
                        (uint32_t)((a_row + mi * 16) * LDT + k0 + a_col) * 2);
#pragma unroll
            for (int mi = 0; mi < 4; mi++) {
                mma16816(acc[mi][0], a[mi], bh_[0][0], bh_[0][1]);
                mma16816(acc[mi][1], a[mi], bh_[0][2], bh_[0][3]);
                mma16816(acc[mi][2], a[mi], bh_[1][0], bh_[1][1]);
                mma16816(acc[mi][3], a[mi], bh_[1][2], bh_[1][3]);
            }
#pragma unroll
            for (int mi = 0; mi < 4; mi++) {
                mma16816(acc[mi][0], a[mi], bl_[0][0], bl_[0][1]);
                mma16816(acc[mi][1], a[mi], bl_[0][2], bl_[0][3]);
                mma16816(acc[mi][2], a[mi], bl_[1][0], bl_[1][1]);
                mma16816(acc[mi][3], a[mi], bl_[1][2], bl_[1][3]);
            }
            // A lo fragments (overwrite a) -> third mma group
#pragma unroll
            for (int mi = 0; mi < 4; mi++)
                ldsm_x4(a[mi], al_b[s] +
                        (uint32_t)((a_row + mi * 16) * LDT + k0 + a_col) * 2);
#pragma unroll
            for (int mi = 0; mi < 4; mi++) {
                mma16816(acc[mi][0], a[mi], bh_[0][0], bh_[0][1]);
                mma16816(acc[mi][1], a[mi], bh_[0][2], bh_[0][3]);
                mma16816(acc[mi][2], a[mi], bh_[1][0], bh_[1][1]);
                mma16816(acc[mi][3], a[mi], bh_[1][2], bh_[1][3]);
            }
        }
        __syncthreads();
        if (kt + 2 < GNITF) stage(kt + 2);
    }

    const int orow = bm + wm + (lane >> 2);
    const int occ0 = wn + ((lane & 3) << 1);

    if (MODE == 0) {
        const int which = bn >> 10;        // 0 q, 1 k, 2 v
        const int bnl = bn & 1023;
        if (which < 2) {
            bf16* Oh = which ? Khi : Qhi;
            bf16* Ol = which ? Klo : Qlo;
#pragma unroll
            for (int mi = 0; mi < 4; mi++)
#pragma unroll
                for (int ni = 0; ni < 4; ni++) {
                    const size_t i0 = (size_t)(orow + mi * 16) * Dc + bnl + occ0 + ni * 8;
                    const size_t i1 = (size_t)(orow + mi * 16 + 8) * Dc + bnl + occ0 + ni * 8;
                    bf16 h0,l0,h1,l1,h2,l2,h3,l3;
                    split2(acc[mi][ni][0] * qalpha, h0, l0);
                    split2(acc[mi][ni][1] * qalpha, h1, l1);
                    split2(acc[mi][ni][2] * qalpha, h2, l2);
                    split2(acc[mi][ni][3] * qalpha, h3, l3);
                    *(__nv_bfloat162*)&Oh[i0] = __halves2bfloat162(h0, h1);
                    *(__nv_bfloat162*)&Oh[i1] = __halves2bfloat162(h2, h3);
                    *(__nv_bfloat162*)&Ol[i0] = __halves2bfloat162(l0, l1);
                    *(__nv_bfloat162*)&Ol[i1] = __halves2bfloat162(l2, l3);
                }
        } else {
#pragma unroll
            for (int mi = 0; mi < 4; mi++)
#pragma unroll
                for (int ni = 0; ni < 4; ni++) {
                    const size_t i0 = (size_t)(orow + mi * 16) * Dc + bnl + occ0 + ni * 8;
                    const size_t i1 = (size_t)(orow + mi * 16 + 8) * Dc + bnl + occ0 + ni * 8;
                    *(float2*)&Cv[i0] = make_float2(acc[mi][ni][0], acc[mi][ni][1]);
                    *(float2*)&Cv[i1] = make_float2(acc[mi][ni][2], acc[mi][ni][3]);
                }
        }
    } else {
#pragma unroll
        for (int mi = 0; mi < 4; mi++)
#pragma unroll
            for (int ni = 0; ni < 4; ni++) {
                float v0 = acc[mi][ni][0], v1 = acc[mi][ni][1];
                float v2 = acc[mi][ni][2], v3 = acc[mi][ni][3];
                v0 = 0.5f * v0 * (1.f + erff(v0 * 0.70710678118654752f));
                v1 = 0.5f * v1 * (1.f + erff(v1 * 0.70710678118654752f));
                v2 = 0.5f * v2 * (1.f + erff(v2 * 0.70710678118654752f));
                v3 = 0.5f * v3 * (1.f + erff(v3 * 0.70710678118654752f));
                const size_t i0 = (size_t)(orow + mi * 16) * Dc + bn + occ0 + ni * 8;
                const size_t i1 = (size_t)(orow + mi * 16 + 8) * Dc + bn + occ0 + ni * 8;
                *(float2*)&Cv[i0] = make_float2(v0, v1);
                *(float2*)&Cv[i1] = make_float2(v2, v3);
            }
    }
}

// ============================================================
// FAVOR+ feature via mma.sync bf16x3 (unchanged from R9)
// OMODE 1: [bh][l][m] hi/lo.  OMODE 2: transposed [bh][m][l] + ksum.
// ============================================================
#define FLDK 72
#define FEAT2_SMEM ((128 + 128 + 256 + 256) * FLDK * 2 + 128 * 4 + 4 * 128 * 4 + 256 * 4)

template<int OMODE>
__global__ __launch_bounds__(256) void feature_mma_kernel(
    const bf16* __restrict__ Uhi, const bf16* __restrict__ Ulo,
    const bf16* __restrict__ Phi, const bf16* __restrict__ Plo,
    bf16* __restrict__ Fhi, bf16* __restrict__ Flo,
    float* __restrict__ ksum)
{
    extern __shared__ char fsm[];
    bf16* us_h = (bf16*)fsm;
    bf16* us_l = us_h + 128 * FLDK;
    bf16* ps_h = us_l + 128 * FLDK;
    bf16* ps_l = ps_h + 256 * FLDK;
    float* diag   = (float*)(ps_l + 256 * FLDK);
    float* rmaxp  = diag + 128;
    float* colsum = rmaxp + 4 * 128;

    const int bh = blockIdx.y;
    const int b = bh >> 4, h = bh & 15;
    const int l0 = blockIdx.x * 128;
    const int tid = threadIdx.x;
    const int lane = tid & 31, wid = tid >> 5;

#pragma unroll
    for (int i = 0; i < 4; i++) {
        int s = tid + i * 256;
        int r = s >> 3, c8 = (s & 7) << 3;
        size_t gi = (size_t)(b * Lc + l0 + r) * Dc + h * DHc + c8;
        *(uint4*)&us_h[r * FLDK + c8] = *(const uint4*)&Uhi[gi];
        *(uint4*)&us_l[r * FLDK + c8] = *(const uint4*)&Ulo[gi];
    }
#pragma unroll
    for (int i = 0; i < 8; i++) {
        int s = tid + i * 256;
        int r = s >> 3, c8 = (s & 7) << 3;
        size_t gi = (size_t)(h * Mc + r) * DHc + c8;
        *(uint4*)&ps_h[r * FLDK + c8] = *(const uint4*)&Phi[gi];
        *(uint4*)&ps_l[r * FLDK + c8] = *(const uint4*)&Plo[gi];
    }
    __syncthreads();

    if (tid < 128) {
        float s = 0.f;
#pragma unroll
        for (int d2 = 0; d2 < 32; d2++) {
            __nv_bfloat162 hh = *(__nv_bfloat162*)&us_h[tid * FLDK + d2 * 2];
            __nv_bfloat162 ll = *(__nv_bfloat162*)&us_l[tid * FLDK + d2 * 2];
            float u0 = __bfloat162float(hh.x) + __bfloat162float(ll.x);
            float u1 = __bfloat162float(hh.y) + __bfloat162float(ll.y);
            s += u0 * u0 + u1 * u1;
        }
        diag[tid] = 0.5f * s;
    }

    const int wm = (wid >> 2) * 64;
    const int wn = (wid & 3) * 64;
    const int a_row = wm + (lane & 15);
    const int a_col = (lane >> 4) << 3;
    const int b_row = wn + (lane & 7) + ((lane >> 4) << 3);
    const int b_col = ((lane >> 3) & 1) << 3;

    float acc[4][8][4];
#pragma unroll
    for (int mi = 0; mi < 4; mi++)
#pragma unroll
        for (int ni = 0; ni < 8; ni++)
#pragma unroll
            for (int e = 0; e < 4; e++) acc[mi][ni][e] = 0.f;

    const uint32_t ush = smem_u32(us_h), usl = smem_u32(us_l);
    const uint32_t psh = smem_u32(ps_h), psl = smem_u32(ps_l);
    __syncthreads();

#pragma unroll
    for (int p = 0; p < 3; p++) {
        const uint32_t ab = (p < 2) ? ush : usl;
        const uint32_t bb = (p == 1) ? psl : psh;
#pragma unroll
        for (int k0 = 0; k0 < 64; k0 += 16) {
            uint32_t a[4][4], bfr[4][4];
#pragma unroll
            for (int mi = 0; mi < 4; mi++)
                ldsm_x4(a[mi], ab + (uint32_t)((a_row + mi * 16) * FLDK + k0 + a_col) * 2);
#pragma unroll
            for (int pr = 0; pr < 4; pr++)
                ldsm_x4(bfr[pr], bb + (uint32_t)((b_row + pr * 16) * FLDK + k0 + b_col) * 2);
#pragma unroll
            for (int mi = 0; mi < 4; mi++)
#pragma unroll
                for (int pr = 0; pr < 4; pr++) {
                    mma16816(acc[mi][2 * pr],     a[mi], bfr[pr][0], bfr[pr][1]);
                    mma16816(acc[mi][2 * pr + 1], a[mi], bfr[pr][2], bfr[pr][3]);
                }
        }
    }

    float tmax[4][2];
#pragma unroll
    for (int mi = 0; mi < 4; mi++) {
        float m0 = -1e30f, m1 = -1e30f;
#pragma unroll
        for (int ni = 0; ni < 8; ni++) {
            m0 = fmaxf(m0, fmaxf(acc[mi][ni][0], acc[mi][ni][1]));
            m1 = fmaxf(m1, fmaxf(acc[mi][ni][2], acc[mi][ni][3]));
        }
#pragma unroll
        for (int off = 1; off <= 2; off <<= 1) {
            m0 = fmaxf(m0, __shfl_xor_sync(0xffffffffu, m0, off));
            m1 = fmaxf(m1, __shfl_xor_sync(0xffffffffu, m1, off));
        }
        tmax[mi][0] = m0; tmax[mi][1] = m1;
    }
    if ((lane & 3) == 0) {
        const int slab = wid & 3;
#pragma unroll
        for (int mi = 0; mi < 4; mi++) {
            int r = wm + mi * 16 + (lane >> 2);
            rmaxp[slab * 128 + r]     = tmax[mi][0];
            rmaxp[slab * 128 + r + 8] = tmax[mi][1];
        }
    }
    if (OMODE == 2 && tid < 256) colsum[tid] = 0.f;
    __syncthreads();

    float base[4][2];
#pragma unroll
    for (int mi = 0; mi < 4; mi++) {
        const int r0 = wm + mi * 16 + (lane >> 2);
        const int r1 = r0 + 8;
        float rm0 = fmaxf(fmaxf(rmaxp[r0], rmaxp[128 + r0]),
                          fmaxf(rmaxp[256 + r0], rmaxp[384 + r0]));
        float rm1 = fmaxf(fmaxf(rmaxp[r1], rmaxp[128 + r1]),
                          fmaxf(rmaxp[256 + r1], rmaxp[384 + r1]));
        base[mi][0] = -diag[r0] - rm0;
        base[mi][1] = -diag[r1] - rm1;
    }

    if (OMODE == 1) {
#pragma unroll
        for (int mi = 0; mi < 4; mi++) {
            const int r0 = wm + mi * 16 + (lane >> 2);
            const size_t o0 = ((size_t)bh * Lc + l0 + r0) * Mc;
            const size_t o1 = ((size_t)bh * Lc + l0 + r0 + 8) * Mc;
            const int c0 = wn + ((lane & 3) << 1);
#pragma unroll
            for (int ni = 0; ni < 8; ni++) {
                int c = c0 + ni * 8;
                float f0 = __expf(acc[mi][ni][0] + base[mi][0]) * 0.0625f;
                float f1 = __expf(acc[mi][ni][1] + base[mi][0]) * 0.0625f;
                float f2 = __expf(acc[mi][ni][2] + base[mi][1]) * 0.0625f;
                float f3 = __expf(acc[mi][ni][3] + base[mi][1]) * 0.0625f;
                bf16 h0,l0b,h1,l1b,h2,l2b,h3,l3b;
                split2(f0, h0, l0b); split2(f1, h1, l1b);
                split2(f2, h2, l2b); split2(f3, h3, l3b);
                *(__nv_bfloat162*)&Fhi[o0 + c] = __halves2bfloat162(h0, h1);
                *(__nv_bfloat162*)&Fhi[o1 + c] = __halves2bfloat162(h2, h3);
                *(__nv_bfloat162*)&Flo[o0 + c] = __halves2bfloat162(l0b, l1b);
                *(__nv_bfloat162*)&Flo[o1 + c] = __halves2bfloat162(l2b, l3b);
            }
        }
    } else {
        const int lr = lane >> 2;
#pragma unroll
        for (int ni = 0; ni < 8; ni++) {
            const int c = wn + ((lane & 3) << 1) + ni * 8;
            float s0 = 0.f, s1 = 0.f;
#pragma unroll
            for (int mi = 0; mi < 4; mi++) {
                const int r0 = wm + mi * 16 + lr;
                float f0 = __expf(acc[mi][ni][0] + base[mi][0]) * 0.0625f;
                float f1 = __expf(acc[mi][ni][1] + base[mi][0]) * 0.0625f;
                float f2 = __expf(acc[mi][ni][2] + base[mi][1]) * 0.0625f;
                float f3 = __expf(acc[mi][ni][3] + base[mi][1]) * 0.0625f;
                s0 += f0 + f2; s1 += f1 + f3;
                const size_t t0 = ((size_t)bh * Mc + c) * Lc + l0;
                const size_t t1 = t0 + Lc;
                bf16 hh, ll;
                split2(f0, hh, ll); Fhi[t0 + r0] = hh;     Flo[t0 + r0] = ll;
                split2(f2, hh, ll); Fhi[t0 + r0 + 8] = hh; Flo[t0 + r0 + 8] = ll;
                split2(f1, hh, ll); Fhi[t1 + r0] = hh;     Flo[t1 + r0] = ll;
                split2(f3, hh, ll); Fhi[t1 + r0 + 8] = hh; Flo[t1 + r0 + 8] = ll;
            }
            atomicAdd(&colsum[c], s0);
            atomicAdd(&colsum[c + 1], s1);
        }
        __syncthreads();
        if (tid < 256) atomicAdd(&ksum[bh * Mc + tid], colsum[tid]);
    }
}

// ============================================================
// kv via mma bf16x3 (unchanged from R9)
// ============================================================
#define KVNIT 48
#define KV_ASTG (64 * LDT * 2)
#define KV_BSTG (256 * LDT * 2)
#define KV_SMEM (3 * (KV_ASTG + KV_BSTG))

__global__ __launch_bounds__(256, 2) void kv_mma_kernel(
    const bf16* __restrict__ vthi, const bf16* __restrict__ vtlo,
    const bf16* __restrict__ kfthi, const bf16* __restrict__ kftlo,
    float* __restrict__ kvtf)
{
    extern __shared__ char ksm[];
    const int bh = blockIdx.y;
    const int l0 = blockIdx.x * 512;
    const int tid = threadIdx.x;
    const int lane = tid & 31, wid = tid >> 5;
    const int wn = wid * 32;

    uint32_t as_b[3], bs_b[3];
#pragma unroll
    for (int s = 0; s < 3; s++) {
        as_b[s] = smem_u32(ksm + s * (KV_ASTG + KV_BSTG));
        bs_b[s] = as_b[s] + KV_ASTG;
    }

    const int a_row = (lane & 15);
    const int a_col = (lane >> 4) << 3;
    const int b_row = wn + (lane & 7) + ((lane >> 4) << 3);
    const int b_col = ((lane >> 3) & 1) << 3;

    const size_t abase = (size_t)bh * DHc * Lc + l0;
    const size_t bbase = (size_t)bh * Mc * Lc + l0;

    const int ga_row = tid >> 2, ga_c8 = (tid & 3) << 3;

    auto stage = [&](int kt) {
        const int s  = kt % 3;
        const int p  = kt >> 4;
        const int kk = (kt & 15) << 5;
        const bf16* Ag = ((p < 2) ? vthi : vtlo) + abase;
        const bf16* Bg = ((p == 1) ? kftlo : kfthi) + bbase;
        cp_async16(as_b[s] + (uint32_t)(ga_row * LDT + ga_c8) * 2,
                   Ag + (size_t)ga_row * Lc + kk + ga_c8);
#pragma unroll
        for (int i = 0; i < 4; i++) {
            int row = ga_row + i * 64;
            cp_async16(bs_b[s] + (uint32_t)(row * LDT + ga_c8) * 2,
                       Bg + (size_t)row * Lc + kk + ga_c8);
        }
        CP_COMMIT();
    };

    float acc[4][4][4];
#pragma unroll
    for (int mi = 0; mi < 4; mi++)
#pragma unroll
        for (int ni = 0; ni < 4; ni++)
#pragma unroll
            for (int e = 0; e < 4; e++) acc[mi][ni][e] = 0.f;

    stage(0); stage(1);

    for (int kt = 0; kt < KVNIT; kt++) {
        const int s = kt % 3;
        if (kt + 1 < KVNIT) CP_WAIT(1); else CP_WAIT(0);
        __syncthreads();
        if (kt + 2 < KVNIT) stage(kt + 2);

#pragma unroll
        for (int k0 = 0; k0 < 32; k0 += 16) {
            uint32_t a[4][4];
#pragma unroll
            for (int mi = 0; mi < 4; mi++)
                ldsm_x4(a[mi], as_b[s] +
                        (uint32_t)((a_row + mi * 16) * LDT + k0 + a_col) * 2);
            uint32_t bf_[2][4];
#pragma unroll
            for (int pr = 0; pr < 2; pr++)
                ldsm_x4(bf_[pr], bs_b[s] +
                        (uint32_t)((b_row + pr * 16) * LDT + k0 + b_col) * 2);
#pragma unroll
            for (int mi = 0; mi < 4; mi++) {
                mma16816(acc[mi][0], a[mi], bf_[0][0], bf_[0][1]);
                mma16816(acc[mi][1], a[mi], bf_[0][2], bf_[0][3]);
                mma16816(acc[mi][2], a[mi], bf_[1][0], bf_[1][1]);
                mma16816(acc[mi][3], a[mi], bf_[1][2], bf_[1][3]);
            }
        }
    }

    const int lr = lane >> 2;
    const int c0 = wn + ((lane & 3) << 1);
    float* dst = kvtf + (size_t)bh * DHc * Mc;
#pragma unroll
    for (int mi = 0; mi < 4; mi++) {
        const int d0 = mi * 16 + lr;
        const int d1 = d0 + 8;
#pragma unroll
        for (int ni = 0; ni < 4; ni++) {
            int c = c0 + ni * 8;
            atomicAdd(&dst[d0 * Mc + c],     acc[mi][ni][0]);
            atomicAdd(&dst[d0 * Mc + c + 1], acc[mi][ni][1]);
            atomicAdd(&dst[d1 * Mc + c],     acc[mi][ni][2]);
            atomicAdd(&dst[d1 * Mc + c + 1], acc[mi][ni][3]);
        }
    }
}

// ============================================================
// kvtf fp32 -> kvthi/kvtlo
// ============================================================
__global__ __launch_bounds__(256) void kvsplit_kernel(
    const float* __restrict__ kvtf, bf16* __restrict__ Thi, bf16* __restrict__ Tlo)
{
    int i = blockIdx.x * 256 + threadIdx.x;
    float v = kvtf[i];
    bf16 h, l; split2(v, h, l);
    Thi[i] = h; Tlo[i] = l;
}

// ============================================================
// z[bh,l] = 1 / (dot(qf_hi+qf_lo, ksum) + 1e-6)
// ============================================================
__global__ __launch_bounds__(256) void z_kernel(
    const bf16* __restrict__ qfhi, const bf16* __restrict__ qflo,
    const float* __restrict__ ksum, float* __restrict__ z)
{
    __shared__ float ks[256];
    const int bh = blockIdx.y;
    ks[threadIdx.x] = ksum[bh * Mc + threadIdx.x];
    __syncthreads();
    const int w = threadIdx.x >> 5, lane = threadIdx.x & 31;
    const int l = blockIdx.x * 8 + w;
    const size_t base = ((size_t)bh * Lc + l) * Mc;
    float s = 0.f;
#pragma unroll
    for (int q8 = 0; q8 < 8; q8++) {
        int c = lane + q8 * 32;
        s += (__bfloat162float(qfhi[base + c]) + __bfloat162float(qflo[base + c])) * ks[c];
    }
#pragma unroll
    for (int off = 16; off; off >>= 1) s += __shfl_xor_sync(0xffffffffu, s, off);
    if (lane == 0) z[bh * Lc + l] = 1.0f / (s + 1e-6f);
}

// ============================================================
// attn via mma bf16x3 (unchanged from R9)
// ============================================================
#define ANIT 24
#define ATT_ASTG (256 * LDT * 2)
#define ATT_BSTG (64 * LDT * 2)
#define ATT_SMEM (3 * (ATT_ASTG + ATT_BSTG))

__global__ __launch_bounds__(256, 2) void attn_mma_kernel(
    const bf16* __restrict__ qfhi, const bf16* __restrict__ qflo,
    const bf16* __restrict__ kvthi, const bf16* __restrict__ kvtlo,
    const float* __restrict__ z,
    bf16* __restrict__ Ohi, bf16* __restrict__ Olo)
{
    extern __shared__ char asm_[];
    const int bh = blockIdx.y;
    const int b = bh >> 4, h = bh & 15;
    const int l0 = blockIdx.x * 256;
    const int tid = threadIdx.x;
    const int lane = tid & 31, wid = tid >> 5;
    const int wm = (wid >> 1) * 64;
    const int wn = (wid & 1) * 32;

    uint32_t as_b[3], bs_b[3];
#pragma unroll
    for (int s = 0; s < 3; s++) {
        as_b[s] = smem_u32(asm_ + s * (ATT_ASTG + ATT_BSTG));
        bs_b[s] = as_b[s] + ATT_ASTG;
    }

    const int a_row = wm + (lane & 15);
    const int a_col = (lane >> 4) << 3;
    const int b_row = wn + (lane & 7) + ((lane >> 4) << 3);
    const int b_col = ((lane >> 3) & 1) << 3;

    const size_t qbase = ((size_t)bh * Lc + l0) * Mc;
    const size_t kbase = (size_t)bh * DHc * Mc;

    const int ga_row0 = tid >> 2, ga_c8 = (tid & 3) << 3;
    const int gb_row = tid >> 2, gb_c8 = (tid & 3) << 3;

    auto stage = [&](int kt) {
        const int s  = kt % 3;
        const int p  = kt >> 3;
        const int kk = (kt & 7) << 5;
        const bf16* Ag = ((p < 2) ? qfhi : qflo) + qbase;
        const bf16* Bg = ((p == 1) ? kvtlo : kvthi) + kbase;
#pragma unroll
        for (int i = 0; i < 4; i++) {
            int row = ga_row0 + i * 64;
            cp_async16(as_b[s] + (uint32_t)(row * LDT + ga_c8) * 2,
                       Ag + (size_t)row * Mc + kk + ga_c8);
        }
        cp_async16(bs_b[s] + (uint32_t)(gb_row * LDT + gb_c8) * 2,
                   Bg + (size_t)gb_row * Mc + kk + gb_c8);
        CP_COMMIT();
    };

    float acc[4][4][4];
#pragma unroll
    for (int mi = 0; mi < 4; mi++)
#pragma unroll
        for (int ni = 0; ni < 4; ni++)
#pragma unroll
            for (int e = 0; e < 4; e++) acc[mi][ni][e] = 0.f;

    stage(0); stage(1);

    for (int kt = 0; kt < ANIT; kt++) {
        const int s = kt % 3;
        if (kt + 1 < ANIT) CP_WAIT(1); else CP_WAIT(0);
        __syncthreads();
        if (kt + 2 < ANIT) stage(kt + 2);

#pragma unroll
        for (int k0 = 0; k0 < 32; k0 += 16) {
            uint32_t a[4][4];
#pragma unroll
            for (int mi = 0; mi < 4; mi++)
                ldsm_x4(a[mi], as_b[s] +
                        (uint32_t)((a_row + mi * 16) * LDT + k0 + a_col) * 2);
            uint32_t bf_[2][4];
#pragma unroll
            for (int pr = 0; pr < 2; pr++)
                ldsm_x4(bf_[pr], bs_b[s] +
                        (uint32_t)((b_row + pr * 16) * LDT + k0 + b_col) * 2);
#pragma unroll
            for (int mi = 0; mi < 4; mi++) {
                mma16816(acc[mi][0], a[mi], bf_[0][0], bf_[0][1]);
                mma16816(acc[mi][1], a[mi], bf_[0][2], bf_[0][3]);
                mma16816(acc[mi][2], a[mi], bf_[1][0], bf_[1][1]);
                mma16816(acc[mi][3], a[mi], bf_[1][2], bf_[1][3]);
            }
        }
    }

    const int lr = lane >> 2;
    const int occ0 = wn + ((lane & 3) << 1);
#pragma unroll
    for (int mi = 0; mi < 4; mi++) {
        const int r0 = wm + mi * 16 + lr;
        const int r1 = r0 + 8;
        const float z0 = z[(size_t)bh * Lc + l0 + r0];
        const float z1 = z[(size_t)bh * Lc + l0 + r1];
        const size_t i0 = (size_t)(b * Lc + l0 + r0) * Dc + h * DHc;
        const size_t i1 = (size_t)(b * Lc + l0 + r1) * Dc + h * DHc;
#pragma unroll
        for (int ni = 0; ni < 4; ni++) {
            int c = occ0 + ni * 8;
            bf16 h0,l0b,h1,l1b,h2,l2b,h3,l3b;
            split2(acc[mi][ni][0] * z0, h0, l0b);
            split2(acc[mi][ni][1] * z0, h1, l1b);
            split2(acc[mi][ni][2] * z1, h2, l2b);
            split2(acc[mi][ni][3] * z1, h3, l3b);
            *(__nv_bfloat162*)&Ohi[i0 + c] = __halves2bfloat162(h0, h1);
            *(__nv_bfloat162*)&Ohi[i1 + c] = __halves2bfloat162(h2, h3);
            *(__nv_bfloat162*)&Olo[i0 + c] = __halves2bfloat162(l0b, l1b);
            *(__nv_bfloat162*)&Olo[i1 + c] = __halves2bfloat162(l2b, l3b);
        }
    }
}

// ============================================================
// LayerNorm + duplicate rows
// ============================================================
__global__ __launch_bounds__(256) void ln_dup_kernel(
    const float* __restrict__ y, const float* __restrict__ g,
    const float* __restrict__ beta, float* __restrict__ out)
{
    __shared__ float red[18];
    const int row = blockIdx.x;
    const int b = row >> 12, l = row & 4095;
    const int tid = threadIdx.x;
    const float* yr = y + (size_t)row * Dc;

    float v[4];
    float s = 0.f, ss = 0.f;
#pragma unroll
    for (int i = 0; i < 4; i++) {
        float t = yr[tid + i * 256];
        v[i] = t; s += t; ss += t * t;
    }
#pragma unroll
    for (int off = 16; off; off >>= 1) {
        s  += __shfl_xor_sync(0xffffffffu, s, off);
        ss += __shfl_xor_sync(0xffffffffu, ss, off);
    }
    const int w = tid >> 5, lane = tid & 31;
    if (lane == 0) { red[w] = s; red[8 + w] = ss; }
    __syncthreads();
    if (tid == 0) {
        float ts = 0.f, tss = 0.f;
#pragma unroll
        for (int i = 0; i < 8; i++) { ts += red[i]; tss += red[8 + i]; }
        float mean = ts * (1.0f / 1024.0f);
        float var = tss * (1.0f / 1024.0f) - mean * mean;
        red[16] = mean;
        red[17] = rsqrtf(var + 1e-5f);
    }
    __syncthreads();
    const float mean = red[16], rstd = red[17];
    float* o0 = out + ((size_t)b * 8192 + 2 * (size_t)l) * Dc;
#pragma unroll
    for (int i = 0; i < 4; i++) {
        int c = tid + i * 256;
        float o = (v[i] - mean) * rstd * g[c] + beta[c];
        o0[c] = o;
        o0[Dc + c] = o;
    }
}

// ============================================================
// host launch
// ============================================================
extern "C" void kernel_launch(void* const* d_in, const int* in_sizes, int n_in,
                              void* d_out, int out_size)
{
    const float* x    = (const float*)d_in[0];
    const float* Wq   = (const float*)d_in[1];
    const float* Wk   = (const float*)d_in[2];
    const float* Wv   = (const float*)d_in[3];
    const float* Wo   = (const float*)d_in[4];
    const float* proj = (const float*)d_in[5];
    const float* ln_g = (const float*)d_in[6];
    const float* ln_b = (const float*)d_in[7];
    float* out = (float*)d_out;

    float *v, *kvtf, *ksum, *z, *y;
    bf16 *qfhi, *qflo, *kfthi, *kftlo, *vthi, *vtlo, *kvthi, *kvtlo;
    bf16 *ahi, *alo, *bthi, *btlo, *qhi, *qlo, *khi, *klo, *phi, *plo;
    cudaGetSymbolAddress((void**)&v,     g_v);
    cudaGetSymbolAddress((void**)&qfhi,  g_qfhi);
    cudaGetSymbolAddress((void**)&qflo,  g_qflo);
    cudaGetSymbolAddress((void**)&kfthi, g_kfthi);
    cudaGetSymbolAddress((void**)&kftlo, g_kftlo);
    cudaGetSymbolAddress((void**)&vthi,  g_vthi);
    cudaGetSymbolAddress((void**)&vtlo,  g_vtlo);
    cudaGetSymbolAddress((void**)&kvtf,  g_kvtf);
    cudaGetSymbolAddress((void**)&kvthi, g_kvthi);
    cudaGetSymbolAddress((void**)&kvtlo, g_kvtlo);
    cudaGetSymbolAddress((void**)&ksum,  g_ksum);
    cudaGetSymbolAddress((void**)&z,     g_z);
    cudaGetSymbolAddress((void**)&y,     g_y);
    cudaGetSymbolAddress((void**)&ahi,   g_ahi);
    cudaGetSymbolAddress((void**)&alo,   g_alo);
    cudaGetSymbolAddress((void**)&bthi,  g_bthi);
    cudaGetSymbolAddress((void**)&btlo,  g_btlo);
    cudaGetSymbolAddress((void**)&qhi,   g_qhi);
    cudaGetSymbolAddress((void**)&qlo,   g_qlo);
    cudaGetSymbolAddress((void**)&khi,   g_khi);
    cudaGetSymbolAddress((void**)&klo,   g_klo);
    cudaGetSymbolAddress((void**)&phi,   g_phi);
    cudaGetSymbolAddress((void**)&plo,   g_plo);

    const float qscale = 0.35355339059327379f;  // 64^-0.25

    cudaFuncSetAttribute(mma_gemm_kernel<0>,
                         cudaFuncAttributeMaxDynamicSharedMemorySize, GEMM_SMEMF);
    cudaFuncSetAttribute(mma_gemm_kernel<1>,
                         cudaFuncAttributeMaxDynamicSharedMemorySize, GEMM_SMEMF);
    cudaFuncSetAttribute(feature_mma_kernel<1>,
                         cudaFuncAttributeMaxDynamicSharedMemorySize, FEAT2_SMEM);
    cudaFuncSetAttribute(feature_mma_kernel<2>,
                         cudaFuncAttributeMaxDynamicSharedMemorySize, FEAT2_SMEM);
    cudaFuncSetAttribute(kv_mma_kernel,
                         cudaFuncAttributeMaxDynamicSharedMemorySize, KV_SMEM);
    cudaFuncSetAttribute(attn_mma_kernel,
                         cudaFuncAttributeMaxDynamicSharedMemorySize, ATT_SMEM);

    const int n4 = ROWS * Dc / 4;
    dim3 tgrid(32, 32), tblk(32, 8);

    // splits
    split_kernel<<<n4 / 256, 256>>>(x, ahi, alo, n4);
    split_kernel<<<(Hc * Mc * DHc / 4) / 256, 256>>>(proj, phi, plo, Hc * Mc * DHc / 4);
    tsplit_kernel<<<tgrid, tblk>>>(Wq, bthi,                   btlo);
    tsplit_kernel<<<tgrid, tblk>>>(Wk, bthi + (size_t)Dc*Dc,   btlo + (size_t)Dc*Dc);
    tsplit_kernel<<<tgrid, tblk>>>(Wv, bthi + (size_t)2*Dc*Dc, btlo + (size_t)2*Dc*Dc);

    // zero accumulators (consumed by feature<2> and kv_mma)
    cudaMemsetAsync(ksum, 0, (size_t)BHc * Mc * sizeof(float), 0);
    cudaMemsetAsync(kvtf, 0, (size_t)BHc * DHc * Mc * sizeof(float), 0);

    // fused QKV GEMM (fused-pass)
    mma_gemm_kernel<0><<<dim3(24, 64), 256, GEMM_SMEMF>>>(
        ahi, alo, bthi, btlo, v, qhi, qlo, khi, klo, qscale);

    // features: Q -> qf hi/lo [l][m]; K -> kf_t hi/lo [m][l] + ksum
    feature_mma_kernel<1><<<dim3(Lc / 128, BHc), 256, FEAT2_SMEM>>>(
        qhi, qlo, phi, plo, qfhi, qflo, nullptr);
    feature_mma_kernel<2><<<dim3(Lc / 128, BHc), 256, FEAT2_SMEM>>>(
        khi, klo, phi, plo, kfthi, kftlo, ksum);

    // v transpose+split, then kv via tensor cores
    vt_kernel<<<dim3(Lc / 32, BHc), 256>>>(v, vthi, vtlo);
    kv_mma_kernel<<<dim3(8, BHc), 256, KV_SMEM>>>(vthi, vtlo, kfthi, kftlo, kvtf);
    kvsplit_kernel<<<(BHc * DHc * Mc) / 256, 256>>>(kvtf, kvthi, kvtlo);

    z_kernel<<<dim3(Lc / 8, BHc), 256>>>(qfhi, qflo, ksum, z);

    // attn -> hi/lo directly into O-GEMM A buffers
    attn_mma_kernel<<<dim3(Lc / 256, BHc), 256, ATT_SMEM>>>(
        qfhi, qflo, kvthi, kvtlo, z, ahi, alo);

    // O projection + exact GELU (fused-pass)
    tsplit_kernel<<<tgrid, tblk>>>(Wo, bthi, btlo);
    mma_gemm_kernel<1><<<dim3(8, 64), 256, GEMM_SMEMF>>>(
        ahi, alo, bthi, btlo, y, nullptr, nullptr, nullptr, nullptr, 1.0f);

    ln_dup_kernel<<<ROWS, 256>>>(y, ln_g, ln_b, out);
}

// round 11
// speedup vs baseline: 1.3370x; 1.0280x over previous
#include <cuda_runtime.h>
#include <cuda_bf16.h>
#include <math.h>
#include <stdint.h>

// Shapes (fixed)
#define Bc   2
#define Lc   4096
#define Dc   1024
#define Hc   16
#define DHc  64
#define Mc   256
#define BHc  32
#define ROWS 8192   // B*L

typedef __nv_bfloat16 bf16;

// -------- scratch (device globals; no allocations allowed) --------
__device__ float g_v    [(size_t)ROWS * Dc];
__device__ bf16  g_qfhi [(size_t)BHc * Lc * Mc];
__device__ bf16  g_qflo [(size_t)BHc * Lc * Mc];
__device__ bf16  g_kfthi[(size_t)BHc * Mc * Lc];
__device__ bf16  g_kftlo[(size_t)BHc * Mc * Lc];
__device__ bf16  g_vthi [(size_t)BHc * DHc * Lc];
__device__ bf16  g_vtlo [(size_t)BHc * DHc * Lc];
__device__ float g_kvtf [(size_t)BHc * DHc * Mc];
__device__ bf16  g_kvthi[(size_t)BHc * DHc * Mc];
__device__ bf16  g_kvtlo[(size_t)BHc * DHc * Mc];
__device__ float g_ksum [(size_t)BHc * Mc];
__device__ float g_z    [(size_t)BHc * Lc];
__device__ float g_y    [(size_t)ROWS * Dc];
__device__ bf16  g_ahi  [(size_t)ROWS * Dc];
__device__ bf16  g_alo  [(size_t)ROWS * Dc];
__device__ bf16  g_bthi [(size_t)3 * Dc * Dc];
__device__ bf16  g_btlo [(size_t)3 * Dc * Dc];
__device__ bf16  g_qhi  [(size_t)ROWS * Dc];
__device__ bf16  g_qlo  [(size_t)ROWS * Dc];
__device__ bf16  g_khi  [(size_t)ROWS * Dc];
__device__ bf16  g_klo  [(size_t)ROWS * Dc];
__device__ bf16  g_phi  [(size_t)Hc * Mc * DHc];
__device__ bf16  g_plo  [(size_t)Hc * Mc * DHc];

// ================= baseline-PTX tensor-core helpers (sm_80+) ==========
__device__ __forceinline__ uint32_t smem_u32(const void* p) {
    uint32_t a;
    asm("{ .reg .u64 t; cvta.to.shared.u64 t, %1; cvt.u32.u64 %0, t; }"
        : "=r"(a) : "l"(p));
    return a;
}
__device__ __forceinline__ void cp_async16(uint32_t saddr, const void* g) {
    asm volatile("cp.async.cg.shared.global [%0], [%1], 16;"
                 :: "r"(saddr), "l"(g) : "memory");
}
#define CP_COMMIT() asm volatile("cp.async.commit_group;" ::: "memory")
#define CP_WAIT(n)  asm volatile("cp.async.wait_group %0;" :: "n"(n) : "memory")

__device__ __forceinline__ void ldsm_x4(uint32_t r[4], uint32_t addr) {
    asm volatile("ldmatrix.sync.aligned.m8n8.x4.shared.b16 {%0,%1,%2,%3}, [%4];"
                 : "=r"(r[0]), "=r"(r[1]), "=r"(r[2]), "=r"(r[3]) : "r"(addr));
}
__device__ __forceinline__ void mma16816(float c[4], const uint32_t a[4],
                                         uint32_t b0, uint32_t b1) {
    asm volatile(
        "mma.sync.aligned.m16n8k16.row.col.f32.bf16.bf16.f32 "
        "{%0,%1,%2,%3}, {%4,%5,%6,%7}, {%8,%9}, {%0,%1,%2,%3};"
        : "+f"(c[0]), "+f"(c[1]), "+f"(c[2]), "+f"(c[3])
        : "r"(a[0]), "r"(a[1]), "r"(a[2]), "r"(a[3]), "r"(b0), "r"(b1));
}
__device__ __forceinline__ void split2(float v, bf16& h, bf16& l) {
    h = __float2bfloat16_rn(v);
    l = __float2bfloat16_rn(v - __bfloat162float(h));
}

// ============================================================
// fp32 -> (hi, lo) bf16 split
// ============================================================
__global__ __launch_bounds__(256) void split_kernel(
    const float* __restrict__ in, bf16* __restrict__ hi,
    bf16* __restrict__ lo, int n4)
{
    int i = blockIdx.x * 256 + threadIdx.x;
    if (i >= n4) return;
    float4 v = ((const float4*)in)[i];
    bf16 h0, h1, h2, h3, l0, l1, l2, l3;
    split2(v.x, h0, l0); split2(v.y, h1, l1);
    split2(v.z, h2, l2); split2(v.w, h3, l3);
    ((__nv_bfloat162*)hi)[2*i]   = __halves2bfloat162(h0, h1);
    ((__nv_bfloat162*)hi)[2*i+1] = __halves2bfloat162(h2, h3);
    ((__nv_bfloat162*)lo)[2*i]   = __halves2bfloat162(l0, l1);
    ((__nv_bfloat162*)lo)[2*i+1] = __halves2bfloat162(l2, l3);
}

// ============================================================
// W [K=1024, N=1024] -> W^T [N,K] with bf16 hi/lo split
// ============================================================
__global__ void tsplit_kernel(const float* __restrict__ W,
    bf16* __restrict__ Thi, bf16* __restrict__ Tlo)
{
    __shared__ float t[32][33];
    int bx = blockIdx.x * 32, by = blockIdx.y * 32;
    int tx = threadIdx.x, ty = threadIdx.y;   // 32 x 8
#pragma unroll
    for (int i = 0; i < 32; i += 8)
        t[ty + i][tx] = W[(size_t)(by + ty + i) * Dc + bx + tx];
    __syncthreads();
#pragma unroll
    for (int i = 0; i < 32; i += 8) {
        float v = t[tx][ty + i];
        int orow = bx + ty + i, ocol = by + tx;
        bf16 h, l; split2(v, h, l);
        Thi[(size_t)orow * Dc + ocol] = h;
        Tlo[(size_t)orow * Dc + ocol] = l;
    }
}

// ============================================================
// v [b*L][D] fp32 -> v_t [bh][d][l] bf16 hi/lo
// ============================================================
__global__ __launch_bounds__(256) void vt_kernel(
    const float* __restrict__ v, bf16* __restrict__ Thi, bf16* __restrict__ Tlo)
{
    __shared__ float t[64][33];
    const int bh = blockIdx.y;
    const int b = bh >> 4, h = bh & 15;
    const int l0 = blockIdx.x * 32;
    const int tid = threadIdx.x;
#pragma unroll
    for (int i = 0; i < 8; i++) {
        int s = tid + i * 256;
        int r = s >> 6, c = s & 63;
        t[c][r & 31] = v[(size_t)(b * Lc + l0 + r) * Dc + h * DHc + c];
    }
    __syncthreads();
#pragma unroll
    for (int i = 0; i < 8; i++) {
        int s = tid + i * 256;
        int d = s >> 5, c = s & 31;
        float val = t[d][c];
        bf16 hh, ll; split2(val, hh, ll);
        size_t o = ((size_t)bh * DHc + d) * Lc + l0 + c;
        Thi[o] = hh; Tlo[o] = ll;
    }
}

// ============================================================
// bf16x3 FUSED-PASS tensor-core GEMM (R10, unchanged):
// MODE 0 (fused QKV), MODE 1 (single + exact GELU). 2 CTAs/SM.
// ============================================================
#define LDT 40
#define GNITF 32                           // 1024 / 32 k-tiles
#define GEMM_MSTG (128 * LDT * 2)          // 10240 B per matrix
#define GEMM_STAGE (4 * GEMM_MSTG)         // 40960 B per stage
#define GEMM_SMEMF (2 * GEMM_STAGE)        // 81920 B

template<int MODE>
__global__ __launch_bounds__(256, 2) void mma_gemm_kernel(
    const bf16* __restrict__ Ahi, const bf16* __restrict__ Alo,
    const bf16* __restrict__ Bhi, const bf16* __restrict__ Blo,
    float* __restrict__ Cv,
    bf16* __restrict__ Qhi, bf16* __restrict__ Qlo,
    bf16* __restrict__ Khi, bf16* __restrict__ Klo,
    float qalpha)
{
    extern __shared__ char gsm[];
    const int tid  = threadIdx.x;
    const int lane = tid & 31, wid = tid >> 5;
    const int bm = blockIdx.y * 128;
    const int bn = blockIdx.x * 128;
    const int wm = (wid >> 2) * 64;
    const int wn = (wid & 3) * 32;

    uint32_t ah_b[2], al_b[2], bh_b[2], bl_b[2];
#pragma unroll
    for (int s = 0; s < 2; s++) {
        uint32_t base = smem_u32(gsm + s * GEMM_STAGE);
        ah_b[s] = base;
        al_b[s] = base + GEMM_MSTG;
        bh_b[s] = base + 2 * GEMM_MSTG;
        bl_b[s] = base + 3 * GEMM_MSTG;
    }

    const int a_row = wm + (lane & 15);
    const int a_col = (lane >> 4) << 3;
    const int b_row = wn + (lane & 7) + ((lane >> 4) << 3);
    const int b_col = ((lane >> 3) & 1) << 3;

    const int g_row0 = tid >> 2;
    const int g_c8   = (tid & 3) << 3;

    auto stage = [&](int kt) {
        const int s  = kt & 1;
        const int kk = kt << 5;
#pragma unroll
        for (int i = 0; i < 2; i++) {
            int row = g_row0 + i * 64;
            uint32_t soff = (uint32_t)(row * LDT + g_c8) * 2;
            const size_t ga = (size_t)(bm + row) * Dc + kk + g_c8;
            const size_t gb = (size_t)(bn + row) * Dc + kk + g_c8;
            cp_async16(ah_b[s] + soff, Ahi + ga);
            cp_async16(al_b[s] + soff, Alo + ga);
            cp_async16(bh_b[s] + soff, Bhi + gb);
            cp_async16(bl_b[s] + soff, Blo + gb);
        }
        CP_COMMIT();
    };

    float acc[4][4][4];
#pragma unroll
    for (int mi = 0; mi < 4; mi++)
#pragma unroll
        for (int ni = 0; ni < 4; ni++)
#pragma unroll
            for (int e = 0; e < 4; e++) acc[mi][ni][e] = 0.f;

    stage(0); stage(1);

    for (int kt = 0; kt < GNITF; kt++) {
        const int s = kt & 1;
        if (kt + 1 < GNITF) CP_WAIT(1); else CP_WAIT(0);
        __syncthreads();

#pragma unroll
        for (int k0 = 0; k0 < 32; k0 += 16) {
            uint32_t bh_[2][4], bl_[2][4];
#pragma unroll
            for (int pr = 0; pr < 2; pr++) {
                uint32_t boff = (uint32_t)((b_row + pr * 16) * LDT + k0 + b_col) * 2;
                ldsm_x4(bh_[pr], bh_b[s] + boff);
                ldsm_x4(bl_[pr], bl_b[s] + boff);
            }
            uint32_t a[4][4];
#pragma unroll
            for (int mi = 0; mi < 4; mi++)
                ldsm_x4(a[mi], ah_b[s] +
                        (uint32_t)((a_row + mi * 16) * LDT + k0 + a_col) * 2);
#pragma unroll
            for (int mi = 0; mi < 4; mi++) {
                mma16816(acc[mi][0], a[mi], bh_[0][0], bh_[0][1]);
                mma16816(acc[mi][1], a[mi], bh_[0][2], bh_[0][3]);
                mma16816(acc[mi][2], a[mi], bh_[1][0], bh_[1][1]);
                mma16816(acc[mi][3], a[mi], bh_[1][2], bh_[1][3]);
            }
#pragma unroll
            for (int mi = 0; mi < 4; mi++) {
                mma16816(acc[mi][0], a[mi], bl_[0][0], bl_[0][1]);
                mma16816(acc[mi][1], a[mi], bl_[0][2], bl_[0][3]);
                mma16816(acc[mi][2], a[mi], bl_[1][0], bl_[1][1]);
                mma16816(acc[mi][3], a[mi], bl_[1][2], bl_[1][3]);
            }
#pragma unroll
            for (int mi = 0; mi < 4; mi++)
                ldsm_x4(a[mi], al_b[s] +
                        (uint32_t)((a_row + mi * 16) * LDT + k0 + a_col) * 2);
#pragma unroll
            for (int mi = 0; mi < 4; mi++) {
                mma16816(acc[mi][0], a[mi], bh_[0][0], bh_[0][1]);
                mma16816(acc[mi][1], a[mi], bh_[0][2], bh_[0][3]);
                mma16816(acc[mi][2], a[mi], bh_[1][0], bh_[1][1]);
                mma16816(acc[mi][3], a[mi], bh_[1][2], bh_[1][3]);
            }
        }
        __syncthreads();
        if (kt + 2 < GNITF) stage(kt + 2);
    }

    const int orow = bm + wm + (lane >> 2);
    const int occ0 = wn + ((lane & 3) << 1);

    if (MODE == 0) {
        const int which = bn >> 10;        // 0 q, 1 k, 2 v
        const int bnl = bn & 1023;
        if (which < 2) {
            bf16* Oh = which ? Khi : Qhi;
            bf16* Ol = which ? Klo : Qlo;
#pragma unroll
            for (int mi = 0; mi < 4; mi++)
#pragma unroll
                for (int ni = 0; ni < 4; ni++) {
                    const size_t i0 = (size_t)(orow + mi * 16) * Dc + bnl + occ0 + ni * 8;
                    const size_t i1 = (size_t)(orow + mi * 16 + 8) * Dc + bnl + occ0 + ni * 8;
                    bf16 h0,l0,h1,l1,h2,l2,h3,l3;
                    split2(acc[mi][ni][0] * qalpha, h0, l0);
                    split2(acc[mi][ni][1] * qalpha, h1, l1);
                    split2(acc[mi][ni][2] * qalpha, h2, l2);
                    split2(acc[mi][ni][3] * qalpha, h3, l3);
                    *(__nv_bfloat162*)&Oh[i0] = __halves2bfloat162(h0, h1);
                    *(__nv_bfloat162*)&Oh[i1] = __halves2bfloat162(h2, h3);
                    *(__nv_bfloat162*)&Ol[i0] = __halves2bfloat162(l0, l1);
                    *(__nv_bfloat162*)&Ol[i1] = __halves2bfloat162(l2, l3);
                }
        } else {
#pragma unroll
            for (int mi = 0; mi < 4; mi++)
#pragma unroll
                for (int ni = 0; ni < 4; ni++) {
                    const size_t i0 = (size_t)(orow + mi * 16) * Dc + bnl + occ0 + ni * 8;
                    const size_t i1 = (size_t)(orow + mi * 16 + 8) * Dc + bnl + occ0 + ni * 8;
                    *(float2*)&Cv[i0] = make_float2(acc[mi][ni][0], acc[mi][ni][1]);
                    *(float2*)&Cv[i1] = make_float2(acc[mi][ni][2], acc[mi][ni][3]);
                }
        }
    } else {
#pragma unroll
        for (int mi = 0; mi < 4; mi++)
#pragma unroll
            for (int ni = 0; ni < 4; ni++) {
                float v0 = acc[mi][ni][0], v1 = acc[mi][ni][1];
                float v2 = acc[mi][ni][2], v3 = acc[mi][ni][3];
                v0 = 0.5f * v0 * (1.f + erff(v0 * 0.70710678118654752f));
                v1 = 0.5f * v1 * (1.f + erff(v1 * 0.70710678118654752f));
                v2 = 0.5f * v2 * (1.f + erff(v2 * 0.70710678118654752f));
                v3 = 0.5f * v3 * (1.f + erff(v3 * 0.70710678118654752f));
                const size_t i0 = (size_t)(orow + mi * 16) * Dc + bn + occ0 + ni * 8;
                const size_t i1 = (size_t)(orow + mi * 16 + 8) * Dc + bn + occ0 + ni * 8;
                *(float2*)&Cv[i0] = make_float2(v0, v1);
                *(float2*)&Cv[i1] = make_float2(v2, v3);
            }
    }
}

// ============================================================
// FAVOR+ feature via mma.sync bf16x3 — FUSED passes in fragment loop.
// OMODE 1: [bh][l][m] hi/lo.  OMODE 2: transposed [bh][m][l] + ksum.
// ============================================================
#define FLDK 72
#define FEAT2_SMEM ((128 + 128 + 256 + 256) * FLDK * 2 + 128 * 4 + 4 * 128 * 4 + 256 * 4)

template<int OMODE>
__global__ __launch_bounds__(256) void feature_mma_kernel(
    const bf16* __restrict__ Uhi, const bf16* __restrict__ Ulo,
    const bf16* __restrict__ Phi, const bf16* __restrict__ Plo,
    bf16* __restrict__ Fhi, bf16* __restrict__ Flo,
    float* __restrict__ ksum)
{
    extern __shared__ char fsm[];
    bf16* us_h = (bf16*)fsm;
    bf16* us_l = us_h + 128 * FLDK;
    bf16* ps_h = us_l + 128 * FLDK;
    bf16* ps_l = ps_h + 256 * FLDK;
    float* diag   = (float*)(ps_l + 256 * FLDK);
    float* rmaxp  = diag + 128;
    float* colsum = rmaxp + 4 * 128;

    const int bh = blockIdx.y;
    const int b = bh >> 4, h = bh & 15;
    const int l0 = blockIdx.x * 128;
    const int tid = threadIdx.x;
    const int lane = tid & 31, wid = tid >> 5;

#pragma unroll
    for (int i = 0; i < 4; i++) {
        int s = tid + i * 256;
        int r = s >> 3, c8 = (s & 7) << 3;
        size_t gi = (size_t)(b * Lc + l0 + r) * Dc + h * DHc + c8;
        *(uint4*)&us_h[r * FLDK + c8] = *(const uint4*)&Uhi[gi];
        *(uint4*)&us_l[r * FLDK + c8] = *(const uint4*)&Ulo[gi];
    }
#pragma unroll
    for (int i = 0; i < 8; i++) {
        int s = tid + i * 256;
        int r = s >> 3, c8 = (s & 7) << 3;
        size_t gi = (size_t)(h * Mc + r) * DHc + c8;
        *(uint4*)&ps_h[r * FLDK + c8] = *(const uint4*)&Phi[gi];
        *(uint4*)&ps_l[r * FLDK + c8] = *(const uint4*)&Plo[gi];
    }
    __syncthreads();

    if (tid < 128) {
        float s = 0.f;
#pragma unroll
        for (int d2 = 0; d2 < 32; d2++) {
            __nv_bfloat162 hh = *(__nv_bfloat162*)&us_h[tid * FLDK + d2 * 2];
            __nv_bfloat162 ll = *(__nv_bfloat162*)&us_l[tid * FLDK + d2 * 2];
            float u0 = __bfloat162float(hh.x) + __bfloat162float(ll.x);
            float u1 = __bfloat162float(hh.y) + __bfloat162float(ll.y);
            s += u0 * u0 + u1 * u1;
        }
        diag[tid] = 0.5f * s;
    }

    const int wm = (wid >> 2) * 64;
    const int wn = (wid & 3) * 64;
    const int a_row = wm + (lane & 15);
    const int a_col = (lane >> 4) << 3;
    const int b_row = wn + (lane & 7) + ((lane >> 4) << 3);
    const int b_col = ((lane >> 3) & 1) << 3;

    float acc[4][8][4];
#pragma unroll
    for (int mi = 0; mi < 4; mi++)
#pragma unroll
        for (int ni = 0; ni < 8; ni++)
#pragma unroll
            for (int e = 0; e < 4; e++) acc[mi][ni][e] = 0.f;

    const uint32_t ush = smem_u32(us_h), usl = smem_u32(us_l);
    const uint32_t psh = smem_u32(ps_h), psl = smem_u32(ps_l);
    __syncthreads();

    // fused passes: per k0 -> ah*bh, al*bh, then bl over bh -> ah*bl
#pragma unroll
    for (int k0 = 0; k0 < 64; k0 += 16) {
        uint32_t ah[4][4], al[4][4], bfr[4][4];
#pragma unroll
        for (int mi = 0; mi < 4; mi++) {
            uint32_t aoff = (uint32_t)((a_row + mi * 16) * FLDK + k0 + a_col) * 2;
            ldsm_x4(ah[mi], ush + aoff);
            ldsm_x4(al[mi], usl + aoff);
        }
#pragma unroll
        for (int pr = 0; pr < 4; pr++)
            ldsm_x4(bfr[pr], psh + (uint32_t)((b_row + pr * 16) * FLDK + k0 + b_col) * 2);
#pragma unroll
        for (int mi = 0; mi < 4; mi++)
#pragma unroll
            for (int pr = 0; pr < 4; pr++) {
                mma16816(acc[mi][2 * pr],     ah[mi], bfr[pr][0], bfr[pr][1]);
                mma16816(acc[mi][2 * pr + 1], ah[mi], bfr[pr][2], bfr[pr][3]);
            }
#pragma unroll
        for (int mi = 0; mi < 4; mi++)
#pragma unroll
            for (int pr = 0; pr < 4; pr++) {
                mma16816(acc[mi][2 * pr],     al[mi], bfr[pr][0], bfr[pr][1]);
                mma16816(acc[mi][2 * pr + 1], al[mi], bfr[pr][2], bfr[pr][3]);
            }
#pragma unroll
        for (int pr = 0; pr < 4; pr++)
            ldsm_x4(bfr[pr], psl + (uint32_t)((b_row + pr * 16) * FLDK + k0 + b_col) * 2);
#pragma unroll
        for (int mi = 0; mi < 4; mi++)
#pragma unroll
            for (int pr = 0; pr < 4; pr++) {
                mma16816(acc[mi][2 * pr],     ah[mi], bfr[pr][0], bfr[pr][1]);
                mma16816(acc[mi][2 * pr + 1], ah[mi], bfr[pr][2], bfr[pr][3]);
            }
    }

    float tmax[4][2];
#pragma unroll
    for (int mi = 0; mi < 4; mi++) {
        float m0 = -1e30f, m1 = -1e30f;
#pragma unroll
        for (int ni = 0; ni < 8; ni++) {
            m0 = fmaxf(m0, fmaxf(acc[mi][ni][0], acc[mi][ni][1]));
            m1 = fmaxf(m1, fmaxf(acc[mi][ni][2], acc[mi][ni][3]));
        }
#pragma unroll
        for (int off = 1; off <= 2; off <<= 1) {
            m0 = fmaxf(m0, __shfl_xor_sync(0xffffffffu, m0, off));
            m1 = fmaxf(m1, __shfl_xor_sync(0xffffffffu, m1, off));
        }
        tmax[mi][0] = m0; tmax[mi][1] = m1;
    }
    if ((lane & 3) == 0) {
        const int slab = wid & 3;
#pragma unroll
        for (int mi = 0; mi < 4; mi++) {
            int r = wm + mi * 16 + (lane >> 2);
            rmaxp[slab * 128 + r]     = tmax[mi][0];
            rmaxp[slab * 128 + r + 8] = tmax[mi][1];
        }
    }
    if (OMODE == 2 && tid < 256) colsum[tid] = 0.f;
    __syncthreads();

    float base[4][2];
#pragma unroll
    for (int mi = 0; mi < 4; mi++) {
        const int r0 = wm + mi * 16 + (lane >> 2);
        const int r1 = r0 + 8;
        float rm0 = fmaxf(fmaxf(rmaxp[r0], rmaxp[128 + r0]),
                          fmaxf(rmaxp[256 + r0], rmaxp[384 + r0]));
        float rm1 = fmaxf(fmaxf(rmaxp[r1], rmaxp[128 + r1]),
                          fmaxf(rmaxp[256 + r1], rmaxp[384 + r1]));
        base[mi][0] = -diag[r0] - rm0;
        base[mi][1] = -diag[r1] - rm1;
    }

    if (OMODE == 1) {
#pragma unroll
        for (int mi = 0; mi < 4; mi++) {
            const int r0 = wm + mi * 16 + (lane >> 2);
            const size_t o0 = ((size_t)bh * Lc + l0 + r0) * Mc;
            const size_t o1 = ((size_t)bh * Lc + l0 + r0 + 8) * Mc;
            const int c0 = wn + ((lane & 3) << 1);
#pragma unroll
            for (int ni = 0; ni < 8; ni++) {
                int c = c0 + ni * 8;
                float f0 = __expf(acc[mi][ni][0] + base[mi][0]) * 0.0625f;
                float f1 = __expf(acc[mi][ni][1] + base[mi][0]) * 0.0625f;
                float f2 = __expf(acc[mi][ni][2] + base[mi][1]) * 0.0625f;
                float f3 = __expf(acc[mi][ni][3] + base[mi][1]) * 0.0625f;
                bf16 h0,l0b,h1,l1b,h2,l2b,h3,l3b;
                split2(f0, h0, l0b); split2(f1, h1, l1b);
                split2(f2, h2, l2b); split2(f3, h3, l3b);
                *(__nv_bfloat162*)&Fhi[o0 + c] = __halves2bfloat162(h0, h1);
                *(__nv_bfloat162*)&Fhi[o1 + c] = __halves2bfloat162(h2, h3);
                *(__nv_bfloat162*)&Flo[o0 + c] = __halves2bfloat162(l0b, l1b);
                *(__nv_bfloat162*)&Flo[o1 + c] = __halves2bfloat162(l2b, l3b);
            }
        }
    } else {
        const int lr = lane >> 2;
#pragma unroll
        for (int ni = 0; ni < 8; ni++) {
            const int c = wn + ((lane & 3) << 1) + ni * 8;
            float s0 = 0.f, s1 = 0.f;
#pragma unroll
            for (int mi = 0; mi < 4; mi++) {
                const int r0 = wm + mi * 16 + lr;
                float f0 = __expf(acc[mi][ni][0] + base[mi][0]) * 0.0625f;
                float f1 = __expf(acc[mi][ni][1] + base[mi][0]) * 0.0625f;
                float f2 = __expf(acc[mi][ni][2] + base[mi][1]) * 0.0625f;
                float f3 = __expf(acc[mi][ni][3] + base[mi][1]) * 0.0625f;
                s0 += f0 + f2; s1 += f1 + f3;
                const size_t t0 = ((size_t)bh * Mc + c) * Lc + l0;
                const size_t t1 = t0 + Lc;
                bf16 hh, ll;
                split2(f0, hh, ll); Fhi[t0 + r0] = hh;     Flo[t0 + r0] = ll;
                split2(f2, hh, ll); Fhi[t0 + r0 + 8] = hh; Flo[t0 + r0 + 8] = ll;
                split2(f1, hh, ll); Fhi[t1 + r0] = hh;     Flo[t1 + r0] = ll;
                split2(f3, hh, ll); Fhi[t1 + r0 + 8] = hh; Flo[t1 + r0 + 8] = ll;
            }
            atomicAdd(&colsum[c], s0);
            atomicAdd(&colsum[c + 1], s1);
        }
        __syncthreads();
        if (tid < 256) atomicAdd(&ksum[bh * Mc + tid], colsum[tid]);
    }
}

// ============================================================
// kv via mma bf16x3 — FUSED-PASS: 16 k-tiles, stage all 4 operands.
// kvt[d][m] = sum_l v_t[d][l] * kf_t[m][l]; fp32 atomic accum.
// ============================================================
#define KVNITF 16                            // 512 / 32
#define KV_AMS (64 * LDT * 2)                // 5120 per matrix
#define KV_BMS (256 * LDT * 2)               // 20480 per matrix
#define KV_STAGEF (2 * KV_AMS + 2 * KV_BMS)  // 51200
#define KV_SMEMF (2 * KV_STAGEF)             // 102400

__global__ __launch_bounds__(256, 2) void kv_mma_kernel(
    const bf16* __restrict__ vthi, const bf16* __restrict__ vtlo,
    const bf16* __restrict__ kfthi, const bf16* __restrict__ kftlo,
    float* __restrict__ kvtf)
{
    extern __shared__ char ksm[];
    const int bh = blockIdx.y;
    const int l0 = blockIdx.x * 512;
    const int tid = threadIdx.x;
    const int lane = tid & 31, wid = tid >> 5;
    const int wn = wid * 32;

    uint32_t ah_b[2], al_b[2], bh_b[2], bl_b[2];
#pragma unroll
    for (int s = 0; s < 2; s++) {
        uint32_t base = smem_u32(ksm + s * KV_STAGEF);
        ah_b[s] = base;
        al_b[s] = base + KV_AMS;
        bh_b[s] = base + 2 * KV_AMS;
        bl_b[s] = base + 2 * KV_AMS + KV_BMS;
    }

    const int a_row = (lane & 15);
    const int a_col = (lane >> 4) << 3;
    const int b_row = wn + (lane & 7) + ((lane >> 4) << 3);
    const int b_col = ((lane >> 3) & 1) << 3;

    const size_t abase = (size_t)bh * DHc * Lc + l0;
    const size_t bbase = (size_t)bh * Mc * Lc + l0;

    const int ga_row = tid >> 2, ga_c8 = (tid & 3) << 3;

    auto stage = [&](int kt) {
        const int s  = kt & 1;
        const int kk = kt << 5;
        // A: 64 rows; 256 x 16B per matrix (1/thread)
        uint32_t asoff = (uint32_t)(ga_row * LDT + ga_c8) * 2;
        const size_t ga = abase + (size_t)ga_row * Lc + kk + ga_c8;
        cp_async16(ah_b[s] + asoff, vthi + ga);
        cp_async16(al_b[s] + asoff, vtlo + ga);
        // B: 256 rows; 1024 x 16B per matrix (4/thread)
#pragma unroll
        for (int i = 0; i < 4; i++) {
            int row = ga_row + i * 64;
            uint32_t bsoff = (uint32_t)(row * LDT + ga_c8) * 2;
            const size_t gb = bbase + (size_t)row * Lc + kk + ga_c8;
            cp_async16(bh_b[s] + bsoff, kfthi + gb);
            cp_async16(bl_b[s] + bsoff, kftlo + gb);
        }
        CP_COMMIT();
    };

    float acc[4][4][4];
#pragma unroll
    for (int mi = 0; mi < 4; mi++)
#pragma unroll
        for (int ni = 0; ni < 4; ni++)
#pragma unroll
            for (int e = 0; e < 4; e++) acc[mi][ni][e] = 0.f;

    stage(0); stage(1);

    for (int kt = 0; kt < KVNITF; kt++) {
        const int s = kt & 1;
        if (kt + 1 < KVNITF) CP_WAIT(1); else CP_WAIT(0);
        __syncthreads();

#pragma unroll
        for (int k0 = 0; k0 < 32; k0 += 16) {
            uint32_t bh_[2][4], bl_[2][4];
#pragma unroll
            for (int pr = 0; pr < 2; pr++) {
                uint32_t boff = (uint32_t)((b_row + pr * 16) * LDT + k0 + b_col) * 2;
                ldsm_x4(bh_[pr], bh_b[s] + boff);
                ldsm_x4(bl_[pr], bl_b[s] + boff);
            }
            uint32_t a[4][4];
#pragma unroll
            for (int mi = 0; mi < 4; mi++)
                ldsm_x4(a[mi], ah_b[s] +
                        (uint32_t)((a_row + mi * 16) * LDT + k0 + a_col) * 2);
#pragma unroll
            for (int mi = 0; mi < 4; mi++) {
                mma16816(acc[mi][0], a[mi], bh_[0][0], bh_[0][1]);
                mma16816(acc[mi][1], a[mi], bh_[0][2], bh_[0][3]);
                mma16816(acc[mi][2], a[mi], bh_[1][0], bh_[1][1]);
                mma16816(acc[mi][3], a[mi], bh_[1][2], bh_[1][3]);
            }
#pragma unroll
            for (int mi = 0; mi < 4; mi++) {
                mma16816(acc[mi][0], a[mi], bl_[0][0], bl_[0][1]);
                mma16816(acc[mi][1], a[mi], bl_[0][2], bl_[0][3]);
                mma16816(acc[mi][2], a[mi], bl_[1][0], bl_[1][1]);
                mma16816(acc[mi][3], a[mi], bl_[1][2], bl_[1][3]);
            }
#pragma unroll
            for (int mi = 0; mi < 4; mi++)
                ldsm_x4(a[mi], al_b[s] +
                        (uint32_t)((a_row + mi * 16) * LDT + k0 + a_col) * 2);
#pragma unroll
            for (int mi = 0; mi < 4; mi++) {
                mma16816(acc[mi][0], a[mi], bh_[0][0], bh_[0][1]);
                mma16816(acc[mi][1], a[mi], bh_[0][2], bh_[0][3]);
                mma16816(acc[mi][2], a[mi], bh_[1][0], bh_[1][1]);
                mma16816(acc[mi][3], a[mi], bh_[1][2], bh_[1][3]);
            }
        }
        __syncthreads();
        if (kt + 2 < KVNITF) stage(kt + 2);
    }

    const int lr = lane >> 2;
    const int c0 = wn + ((lane & 3) << 1);
    float* dst = kvtf + (size_t)bh * DHc * Mc;
#pragma unroll
    for (int mi = 0; mi < 4; mi++) {
        const int d0 = mi * 16 + lr;
        const int d1 = d0 + 8;
#pragma unroll
        for (int ni = 0; ni < 4; ni++) {
            int c = c0 + ni * 8;
            atomicAdd(&dst[d0 * Mc + c],     acc[mi][ni][0]);
            atomicAdd(&dst[d0 * Mc + c + 1], acc[mi][ni][1]);
            atomicAdd(&dst[d1 * Mc + c],     acc[mi][ni][2]);
            atomicAdd(&dst[d1 * Mc + c + 1], acc[mi][ni][3]);
        }
    }
}

// ============================================================
// kvtf fp32 -> kvthi/kvtlo
// ============================================================
__global__ __launch_bounds__(256) void kvsplit_kernel(
    const float* __restrict__ kvtf, bf16* __restrict__ Thi, bf16* __restrict__ Tlo)
{
    int i = blockIdx.x * 256 + threadIdx.x;
    float v = kvtf[i];
    bf16 h, l; split2(v, h, l);
    Thi[i] = h; Tlo[i] = l;
}

// ============================================================
// z[bh,l] = 1 / (dot(qf_hi+qf_lo, ksum) + 1e-6)
// ============================================================
__global__ __launch_bounds__(256) void z_kernel(
    const bf16* __restrict__ qfhi, const bf16* __restrict__ qflo,
    const float* __restrict__ ksum, float* __restrict__ z)
{
    __shared__ float ks[256];
    const int bh = blockIdx.y;
    ks[threadIdx.x] = ksum[bh * Mc + threadIdx.x];
    __syncthreads();
    const int w = threadIdx.x >> 5, lane = threadIdx.x & 31;
    const int l = blockIdx.x * 8 + w;
    const size_t base = ((size_t)bh * Lc + l) * Mc;
    float s = 0.f;
#pragma unroll
    for (int q8 = 0; q8 < 8; q8++) {
        int c = lane + q8 * 32;
        s += (__bfloat162float(qfhi[base + c]) + __bfloat162float(qflo[base + c])) * ks[c];
    }
#pragma unroll
    for (int off = 16; off; off >>= 1) s += __shfl_xor_sync(0xffffffffu, s, off);
    if (lane == 0) z[bh * Lc + l] = 1.0f / (s + 1e-6f);
}

// ============================================================
// attn via mma bf16x3 — FUSED-PASS: 8 k-tiles, stage all 4 operands.
// hi/lo z-scaled output feeds O GEMM directly.
// ============================================================
#define ANITF 8                               // 256 / 32
#define ATT_AMS (256 * LDT * 2)               // 20480 per matrix
#define ATT_BMS (64 * LDT * 2)                // 5120 per matrix
#define ATT_STAGEF (2 * ATT_AMS + 2 * ATT_BMS)  // 51200
#define ATT_SMEMF (2 * ATT_STAGEF)            // 102400

__global__ __launch_bounds__(256, 2) void attn_mma_kernel(
    const bf16* __restrict__ qfhi, const bf16* __restrict__ qflo,
    const bf16* __restrict__ kvthi, const bf16* __restrict__ kvtlo,
    const float* __restrict__ z,
    bf16* __restrict__ Ohi, bf16* __restrict__ Olo)
{
    extern __shared__ char asm_[];
    const int bh = blockIdx.y;
    const int b = bh >> 4, h = bh & 15;
    const int l0 = blockIdx.x * 256;
    const int tid = threadIdx.x;
    const int lane = tid & 31, wid = tid >> 5;
    const int wm = (wid >> 1) * 64;
    const int wn = (wid & 1) * 32;

    uint32_t ah_b[2], al_b[2], bh_b[2], bl_b[2];
#pragma unroll
    for (int s = 0; s < 2; s++) {
        uint32_t base = smem_u32(asm_ + s * ATT_STAGEF);
        ah_b[s] = base;
        al_b[s] = base + ATT_AMS;
        bh_b[s] = base + 2 * ATT_AMS;
        bl_b[s] = base + 2 * ATT_AMS + ATT_BMS;
    }

    const int a_row = wm + (lane & 15);
    const int a_col = (lane >> 4) << 3;
    const int b_row = wn + (lane & 7) + ((lane >> 4) << 3);
    const int b_col = ((lane >> 3) & 1) << 3;

    const size_t qbase = ((size_t)bh * Lc + l0) * Mc;
    const size_t kbase = (size_t)bh * DHc * Mc;

    const int ga_row = tid >> 2, ga_c8 = (tid & 3) << 3;

    auto stage = [&](int kt) {
        const int s  = kt & 1;
        const int kk = kt << 5;
        // A: 256 rows, 1024 x 16B per matrix (4/thread)
#pragma unroll
        for (int i = 0; i < 4; i++) {
            int row = ga_row + i * 64;
            uint32_t soff = (uint32_t)(row * LDT + ga_c8) * 2;
            const size_t ga = qbase + (size_t)row * Mc + kk + ga_c8;
            cp_async16(ah_b[s] + soff, qfhi + ga);
            cp_async16(al_b[s] + soff, qflo + ga);
        }
        // B: 64 rows, 256 x 16B per matrix (1/thread)
        uint32_t bsoff = (uint32_t)(ga_row * LDT + ga_c8) * 2;
        const size_t gb = kbase + (size_t)ga_row * Mc + kk + ga_c8;
        cp_async16(bh_b[s] + bsoff, kvthi + gb);
        cp_async16(bl_b[s] + bsoff, kvtlo + gb);
        CP_COMMIT();
    };

    float acc[4][4][4];
#pragma unroll
    for (int mi = 0; mi < 4; mi++)
#pragma unroll
        for (int ni = 0; ni < 4; ni++)
#pragma unroll
            for (int e = 0; e < 4; e++) acc[mi][ni][e] = 0.f;

    stage(0); stage(1);

    for (int kt = 0; kt < ANITF; kt++) {
        const int s = kt & 1;
        if (kt + 1 < ANITF) CP_WAIT(1); else CP_WAIT(0);
        __syncthreads();

#pragma unroll
        for (int k0 = 0; k0 < 32; k0 += 16) {
            uint32_t bh_[2][4], bl_[2][4];
#pragma unroll
            for (int pr = 0; pr < 2; pr++) {
                uint32_t boff = (uint32_t)((b_row + pr * 16) * LDT + k0 + b_col) * 2;
                ldsm_x4(bh_[pr], bh_b[s] + boff);
                ldsm_x4(bl_[pr], bl_b[s] + boff);
            }
            uint32_t a[4][4];
#pragma unroll
            for (int mi = 0; mi < 4; mi++)
                ldsm_x4(a[mi], ah_b[s] +
                        (uint32_t)((a_row + mi * 16) * LDT + k0 + a_col) * 2);
#pragma unroll
            for (int mi = 0; mi < 4; mi++) {
                mma16816(acc[mi][0], a[mi], bh_[0][0], bh_[0][1]);
                mma16816(acc[mi][1], a[mi], bh_[0][2], bh_[0][3]);
                mma16816(acc[mi][2], a[mi], bh_[1][0], bh_[1][1]);
                mma16816(acc[mi][3], a[mi], bh_[1][2], bh_[1][3]);
            }
#pragma unroll
            for (int mi = 0; mi < 4; mi++) {
                mma16816(acc[mi][0], a[mi], bl_[0][0], bl_[0][1]);
                mma16816(acc[mi][1], a[mi], bl_[0][2], bl_[0][3]);
                mma16816(acc[mi][2], a[mi], bl_[1][0], bl_[1][1]);
                mma16816(acc[mi][3], a[mi], bl_[1][2], bl_[1][3]);
            }
#pragma unroll
            for (int mi = 0; mi < 4; mi++)
                ldsm_x4(a[mi], al_b[s] +
                        (uint32_t)((a_row + mi * 16) * LDT + k0 + a_col) * 2);
#pragma unroll
            for (int mi = 0; mi < 4; mi++) {
                mma16816(acc[mi][0], a[mi], bh_[0][0], bh_[0][1]);
                mma16816(acc[mi][1], a[mi], bh_[0][2], bh_[0][3]);
                mma16816(acc[mi][2], a[mi], bh_[1][0], bh_[1][1]);
                mma16816(acc[mi][3], a[mi], bh_[1][2], bh_[1][3]);
            }
        }
        __syncthreads();
        if (kt + 2 < ANITF) stage(kt + 2);
    }

    const int lr = lane >> 2;
    const int occ0 = wn + ((lane & 3) << 1);
#pragma unroll
    for (int mi = 0; mi < 4; mi++) {
        const int r0 = wm + mi * 16 + lr;
        const int r1 = r0 + 8;
        const float z0 = z[(size_t)bh * Lc + l0 + r0];
        const float z1 = z[(size_t)bh * Lc + l0 + r1];
        const size_t i0 = (size_t)(b * Lc + l0 + r0) * Dc + h * DHc;
        const size_t i1 = (size_t)(b * Lc + l0 + r1) * Dc + h * DHc;
#pragma unroll
        for (int ni = 0; ni < 4; ni++) {
            int c = occ0 + ni * 8;
            bf16 h0,l0b,h1,l1b,h2,l2b,h3,l3b;
            split2(acc[mi][ni][0] * z0, h0, l0b);
            split2(acc[mi][ni][1] * z0, h1, l1b);
            split2(acc[mi][ni][2] * z1, h2, l2b);
            split2(acc[mi][ni][3] * z1, h3, l3b);
            *(__nv_bfloat162*)&Ohi[i0 + c] = __halves2bfloat162(h0, h1);
            *(__nv_bfloat162*)&Ohi[i1 + c] = __halves2bfloat162(h2, h3);
            *(__nv_bfloat162*)&Olo[i0 + c] = __halves2bfloat162(l0b, l1b);
            *(__nv_bfloat162*)&Olo[i1 + c] = __halves2bfloat162(l2b, l3b);
        }
    }
}

// ============================================================
// LayerNorm + duplicate rows
// ============================================================
__global__ __launch_bounds__(256) void ln_dup_kernel(
    const float* __restrict__ y, const float* __restrict__ g,
    const float* __restrict__ beta, float* __restrict__ out)
{
    __shared__ float red[18];
    const int row = blockIdx.x;
    const int b = row >> 12, l = row & 4095;
    const int tid = threadIdx.x;
    const float* yr = y + (size_t)row * Dc;

    float v[4];
    float s = 0.f, ss = 0.f;
#pragma unroll
    for (int i = 0; i < 4; i++) {
        float t = yr[tid + i * 256];
        v[i] = t; s += t; ss += t * t;
    }
#pragma unroll
    for (int off = 16; off; off >>= 1) {
        s  += __shfl_xor_sync(0xffffffffu, s, off);
        ss += __shfl_xor_sync(0xffffffffu, ss, off);
    }
    const int w = tid >> 5, lane = tid & 31;
    if (lane == 0) { red[w] = s; red[8 + w] = ss; }
    __syncthreads();
    if (tid == 0) {
        float ts = 0.f, tss = 0.f;
#pragma unroll
        for (int i = 0; i < 8; i++) { ts += red[i]; tss += red[8 + i]; }
        float mean = ts * (1.0f / 1024.0f);
        float var = tss * (1.0f / 1024.0f) - mean * mean;
        red[16] = mean;
        red[17] = rsqrtf(var + 1e-5f);
    }
    __syncthreads();
    const float mean = red[16], rstd = red[17];
    float* o0 = out + ((size_t)b * 8192 + 2 * (size_t)l) * Dc;
#pragma unroll
    for (int i = 0; i < 4; i++) {
        int c = tid + i * 256;
        float o = (v[i] - mean) * rstd * g[c] + beta[c];
        o0[c] = o;
        o0[Dc + c] = o;
    }
}

// ============================================================
// host launch
// ============================================================
extern "C" void kernel_launch(void* const* d_in, const int* in_sizes, int n_in,
                              void* d_out, int out_size)
{
    const float* x    = (const float*)d_in[0];
    const float* Wq   = (const float*)d_in[1];
    const float* Wk   = (const float*)d_in[2];
    const float* Wv   = (const float*)d_in[3];
    const float* Wo   = (const float*)d_in[4];
    const float* proj = (const float*)d_in[5];
    const float* ln_g = (const float*)d_in[6];
    const float* ln_b = (const float*)d_in[7];
    float* out = (float*)d_out;

    float *v, *kvtf, *ksum, *z, *y;
    bf16 *qfhi, *qflo, *kfthi, *kftlo, *vthi, *vtlo, *kvthi, *kvtlo;
    bf16 *ahi, *alo, *bthi, *btlo, *qhi, *qlo, *khi, *klo, *phi, *plo;
    cudaGetSymbolAddress((void**)&v,     g_v);
    cudaGetSymbolAddress((void**)&qfhi,  g_qfhi);
    cudaGetSymbolAddress((void**)&qflo,  g_qflo);
    cudaGetSymbolAddress((void**)&kfthi, g_kfthi);
    cudaGetSymbolAddress((void**)&kftlo, g_kftlo);
    cudaGetSymbolAddress((void**)&vthi,  g_vthi);
    cudaGetSymbolAddress((void**)&vtlo,  g_vtlo);
    cudaGetSymbolAddress((void**)&kvtf,  g_kvtf);
    cudaGetSymbolAddress((void**)&kvthi, g_kvthi);
    cudaGetSymbolAddress((void**)&kvtlo, g_kvtlo);
    cudaGetSymbolAddress((void**)&ksum,  g_ksum);
    cudaGetSymbolAddress((void**)&z,     g_z);
    cudaGetSymbolAddress((void**)&y,     g_y);
    cudaGetSymbolAddress((void**)&ahi,   g_ahi);
    cudaGetSymbolAddress((void**)&alo,   g_alo);
    cudaGetSymbolAddress((void**)&bthi,  g_bthi);
    cudaGetSymbolAddress((void**)&btlo,  g_btlo);
    cudaGetSymbolAddress((void**)&qhi,   g_qhi);
    cudaGetSymbolAddress((void**)&qlo,   g_qlo);
    cudaGetSymbolAddress((void**)&khi,   g_khi);
    cudaGetSymbolAddress((void**)&klo,   g_klo);
    cudaGetSymbolAddress((void**)&phi,   g_phi);
    cudaGetSymbolAddress((void**)&plo,   g_plo);

    const float qscale = 0.35355339059327379f;  // 64^-0.25

    cudaFuncSetAttribute(mma_gemm_kernel<0>,
                         cudaFuncAttributeMaxDynamicSharedMemorySize, GEMM_SMEMF);
    cudaFuncSetAttribute(mma_gemm_kernel<1>,
                         cudaFuncAttributeMaxDynamicSharedMemorySize, GEMM_SMEMF);
    cudaFuncSetAttribute(feature_mma_kernel<1>,
                         cudaFuncAttributeMaxDynamicSharedMemorySize, FEAT2_SMEM);
    cudaFuncSetAttribute(feature_mma_kernel<2>,
                         cudaFuncAttributeMaxDynamicSharedMemorySize, FEAT2_SMEM);
    cudaFuncSetAttribute(kv_mma_kernel,
                         cudaFuncAttributeMaxDynamicSharedMemorySize, KV_SMEMF);
    cudaFuncSetAttribute(attn_mma_kernel,
                         cudaFuncAttributeMaxDynamicSharedMemorySize, ATT_SMEMF);

    const int n4 = ROWS * Dc / 4;
    dim3 tgrid(32, 32), tblk(32, 8);

    // splits
    split_kernel<<<n4 / 256, 256>>>(x, ahi, alo, n4);
    split_kernel<<<(Hc * Mc * DHc / 4) / 256, 256>>>(proj, phi, plo, Hc * Mc * DHc / 4);
    tsplit_kernel<<<tgrid, tblk>>>(Wq, bthi,                   btlo);
    tsplit_kernel<<<tgrid, tblk>>>(Wk, bthi + (size_t)Dc*Dc,   btlo + (size_t)Dc*Dc);
    tsplit_kernel<<<tgrid, tblk>>>(Wv, bthi + (size_t)2*Dc*Dc, btlo + (size_t)2*Dc*Dc);

    // zero accumulators (consumed by feature<2> and kv_mma)
    cudaMemsetAsync(ksum, 0, (size_t)BHc * Mc * sizeof(float), 0);
    cudaMemsetAsync(kvtf, 0, (size_t)BHc * DHc * Mc * sizeof(float), 0);

    // fused QKV GEMM
    mma_gemm_kernel<0><<<dim3(24, 64), 256, GEMM_SMEMF>>>(
        ahi, alo, bthi, btlo, v, qhi, qlo, khi, klo, qscale);

    // features: Q -> qf hi/lo [l][m]; K -> kf_t hi/lo [m][l] + ksum
    feature_mma_kernel<1><<<dim3(Lc / 128, BHc), 256, FEAT2_SMEM>>>(
        qhi, qlo, phi, plo, qfhi, qflo, nullptr);
    feature_mma_kernel<2><<<dim3(Lc / 128, BHc), 256, FEAT2_SMEM>>>(
        khi, klo, phi, plo, kfthi, kftlo, ksum);

    // v transpose+split, then kv via tensor cores
    vt_kernel<<<dim3(Lc / 32, BHc), 256>>>(v, vthi, vtlo);
    kv_mma_kernel<<<dim3(8, BHc), 256, KV_SMEMF>>>(vthi, vtlo, kfthi, kftlo, kvtf);
    kvsplit_kernel<<<(BHc * DHc * Mc) / 256, 256>>>(kvtf, kvthi, kvtlo);

    z_kernel<<<dim3(Lc / 8, BHc), 256>>>(qfhi, qflo, ksum, z);

    // attn -> hi/lo directly into O-GEMM A buffers
    attn_mma_kernel<<<dim3(Lc / 256, BHc), 256, ATT_SMEMF>>>(
        qfhi, qflo, kvthi, kvtlo, z, ahi, alo);

    // O projection + exact GELU
    tsplit_kernel<<<tgrid, tblk>>>(Wo, bthi, btlo);
    mma_gemm_kernel<1><<<dim3(8, 64), 256, GEMM_SMEMF>>>(
        ahi, alo, bthi, btlo, y, nullptr, nullptr, nullptr, nullptr, 1.0f);

    ln_dup_kernel<<<ROWS, 256>>>(y, ln_g, ln_b, out);
}